// round 2
// baseline (speedup 1.0000x reference)
#include <cuda_runtime.h>
#include <math.h>

#define NHEADS 8
#define NKVH   2
#define HDIM   64
#define TSEQ   2048
#define BATCH  4
#define NTOK   (BATCH*TSEQ)   /* 8192 */

// ---------------- scratch (device globals; no allocation allowed) ----------------
__device__ float g_cq   [NTOK*256];   // x@W_DQ, then RMS in place
__device__ float g_ckv  [NTOK*128];   // x@W_DKV, then RMS in place
__device__ float g_krope[NTOK*64];    // x@W_KR (pre-rope)
__device__ float g_vres [NTOK*512];   // x@W_VR
__device__ float g_qnope[NTOK*256];   // c_q@W_UQ
__device__ float g_qrope[NTOK*256];   // c_q@W_QR (pre-rope)
__device__ float g_knope[NTOK*64];    // c_kv@W_UK
__device__ float g_vv   [NTOK*128];   // c_kv@W_UV
__device__ float g_q [BATCH*NHEADS*TSEQ*HDIM];  // [B,H,T,64] final q
__device__ float g_k [BATCH*NKVH  *TSEQ*HDIM];  // [B,KVH,T,64] final k
__device__ float g_vt[BATCH*NKVH  *TSEQ*HDIM];  // [B,KVH,T,64] v
__device__ float g_attn[NTOK*512];              // attn_out + v_res, [tok, H*64]

// ---------------- generic tiled SGEMM: C[M,N] = A[M,K] @ B[K,N] ----------------
// BM=BN=64, BK=16, 256 threads, 4x4 microtile. Requires M%64==0, N%64==0, K%16==0.
__global__ __launch_bounds__(256) void sgemm64(const float* __restrict__ A,
                                               const float* __restrict__ B,
                                               float* __restrict__ C,
                                               int M, int N, int K) {
    __shared__ float As[16][65];   // As[k][m] (transposed, padded)
    __shared__ float Bs[16][64];   // Bs[k][n]
    const int m0 = blockIdx.y * 64;
    const int n0 = blockIdx.x * 64;
    const int tid = threadIdx.x;
    const int ty = tid >> 4, tx = tid & 15;
    const int arow = tid >> 2, acol = (tid & 3) * 4;
    const int brow = tid >> 4, bcol = (tid & 15) * 4;

    float acc[4][4];
#pragma unroll
    for (int i = 0; i < 4; i++)
#pragma unroll
        for (int j = 0; j < 4; j++) acc[i][j] = 0.f;

    for (int k0 = 0; k0 < K; k0 += 16) {
        float4 av = *(const float4*)&A[(size_t)(m0 + arow) * K + k0 + acol];
        As[acol + 0][arow] = av.x;
        As[acol + 1][arow] = av.y;
        As[acol + 2][arow] = av.z;
        As[acol + 3][arow] = av.w;
        float4 bv = *(const float4*)&B[(size_t)(k0 + brow) * N + n0 + bcol];
        *(float4*)&Bs[brow][bcol] = bv;
        __syncthreads();
#pragma unroll
        for (int kk = 0; kk < 16; kk++) {
            float a[4], b[4];
#pragma unroll
            for (int i = 0; i < 4; i++) a[i] = As[kk][ty * 4 + i];
#pragma unroll
            for (int j = 0; j < 4; j++) b[j] = Bs[kk][tx * 4 + j];
#pragma unroll
            for (int i = 0; i < 4; i++)
#pragma unroll
                for (int j = 0; j < 4; j++) acc[i][j] += a[i] * b[j];
        }
        __syncthreads();
    }
#pragma unroll
    for (int i = 0; i < 4; i++) {
        float4 o = make_float4(acc[i][0], acc[i][1], acc[i][2], acc[i][3]);
        *(float4*)&C[(size_t)(m0 + ty * 4 + i) * N + n0 + tx * 4] = o;
    }
}

// ---------------- in-place RMSNorm over last dim D (blockDim == D) ----------------
__global__ void rms_inplace(float* __restrict__ X, const float* __restrict__ w, int D) {
    const int n = blockIdx.x;
    float* row = X + (size_t)n * D;
    const int tid = threadIdx.x;
    float v = row[tid];
    float ss = v * v;
#pragma unroll
    for (int o = 16; o > 0; o >>= 1) ss += __shfl_xor_sync(0xffffffffu, ss, o);
    __shared__ float sh[8];
    const int wid = tid >> 5, nw = blockDim.x >> 5;
    if ((tid & 31) == 0) sh[wid] = ss;
    __syncthreads();
    float tot = 0.f;
    for (int i = 0; i < nw; i++) tot += sh[i];
    float scale = rsqrtf(tot / (float)D + 1e-6f);
    row[tid] = v * scale * w[tid];
}

// ---------------- RoPE + concat + per-head RMS + layout to [B,h,T,64] ----------------
// grid = NTOK, 256 threads = 8 warps. Warp w: q head w; warps 0-1 also k heads; 2-3 copy v.
__global__ __launch_bounds__(256) void assemble(const float* __restrict__ qhw,
                                                const float* __restrict__ khw) {
    const int n = blockIdx.x;
    const int b = n / TSEQ, t = n % TSEQ;
    const int tid = threadIdx.x, w = tid >> 5, l = tid & 31;

    const int j = l & 15;
    const float invf = powf(500000.0f, -(float)j / 16.0f);
    const float f = (float)t * invf;
    const float cs = cosf(f), sn = sinf(f);

    // ---- q head h = w ----
    {
        const int h = w;
        float v0 = g_qnope[(size_t)n * 256 + h * 32 + l];
        const float* qr = &g_qrope[(size_t)n * 256 + h * 32];
        float a = qr[l];
        float v1 = (l < 16) ? (a * cs - qr[l + 16] * sn) : (a * cs + qr[l - 16] * sn);
        float ss = v0 * v0 + v1 * v1;
#pragma unroll
        for (int o = 16; o > 0; o >>= 1) ss += __shfl_xor_sync(0xffffffffu, ss, o);
        float scale = rsqrtf(ss / 64.0f + 1e-6f);
        float* qo = &g_q[(((size_t)b * NHEADS + h) * TSEQ + t) * HDIM];
        qo[l]      = v0 * scale * qhw[l];
        qo[32 + l] = v1 * scale * qhw[32 + l];
    }
    // ---- k head (warps 0,1) ----
    if (w < 2) {
        const int kvh = w;
        float v0 = g_knope[(size_t)n * 64 + kvh * 32 + l];
        const float* kr = &g_krope[(size_t)n * 64 + kvh * 32];
        float a = kr[l];
        float v1 = (l < 16) ? (a * cs - kr[l + 16] * sn) : (a * cs + kr[l - 16] * sn);
        float ss = v0 * v0 + v1 * v1;
#pragma unroll
        for (int o = 16; o > 0; o >>= 1) ss += __shfl_xor_sync(0xffffffffu, ss, o);
        float scale = rsqrtf(ss / 64.0f + 1e-6f);
        float* ko = &g_k[(((size_t)b * NKVH + kvh) * TSEQ + t) * HDIM];
        ko[l]      = v0 * scale * khw[l];
        ko[32 + l] = v1 * scale * khw[32 + l];
    } else if (w < 4) {  // ---- v copy (warps 2,3) ----
        const int kvh = w - 2;
        float* vo = &g_vt[(((size_t)b * NKVH + kvh) * TSEQ + t) * HDIM];
        vo[l]      = g_vv[(size_t)n * 128 + kvh * 64 + l];
        vo[32 + l] = g_vv[(size_t)n * 128 + kvh * 64 + 32 + l];
    }
}

// ---------------- causal flash attention, BM=BN=64, d=64 ----------------
// grid = (T/64, B*H). 256 threads, 16x16 layout, 4x4 microtiles. GQA: kvh = h/4.
// Epilogue adds v_res and writes [tok, H*64].
// Shared strides: Qs/Ks/Ps = 65 (scalar access only), Vs = 68 (float4-aligned).
#define VS_STRIDE 68
extern __shared__ float fsm[];
__global__ __launch_bounds__(256) void flash(const float* __restrict__ vres,
                                             float* __restrict__ attn) {
    float* Qs = fsm;                    // [64][65], transposed: Qs[d][m]
    float* Ks = Qs + 64 * 65;           // [64][65], transposed: Ks[d][c]
    float* Vs = Ks + 64 * 65;           // [64][68], row: Vs[c][dd]
    float* Ps = Vs + 64 * VS_STRIDE;    // [64][65], transposed: Ps[c][r]

    const int qt = blockIdx.x;         // query tile
    const int bh = blockIdx.y;         // b*8 + h
    const int b = bh >> 3, h = bh & 7, kvh = h >> 2;
    const int q0 = qt * 64;

    const float* Qg = &g_q [(((size_t)b * NHEADS + h)  * TSEQ + q0) * HDIM];
    const float* Kg = &g_k [(((size_t)b * NKVH + kvh) * TSEQ) * HDIM];
    const float* Vg = &g_vt[(((size_t)b * NKVH + kvh) * TSEQ) * HDIM];

    const int tid = threadIdx.x, ty = tid >> 4, tx = tid & 15;
    const int lr = tid >> 2, lc0 = (tid & 3) * 16;

    // load Q tile (transposed into Qs)
#pragma unroll
    for (int u = 0; u < 4; u++) {
        float4 v = *(const float4*)&Qg[(size_t)lr * HDIM + lc0 + u * 4];
        Qs[(lc0 + u * 4 + 0) * 65 + lr] = v.x;
        Qs[(lc0 + u * 4 + 1) * 65 + lr] = v.y;
        Qs[(lc0 + u * 4 + 2) * 65 + lr] = v.z;
        Qs[(lc0 + u * 4 + 3) * 65 + lr] = v.w;
    }

    float m[4], lsum[4], o[4][4];
#pragma unroll
    for (int i = 0; i < 4; i++) {
        m[i] = -INFINITY; lsum[i] = 0.f;
#pragma unroll
        for (int jj = 0; jj < 4; jj++) o[i][jj] = 0.f;
    }

    for (int kt = 0; kt <= qt; kt++) {
        __syncthreads();
        const float* Kt = Kg + (size_t)kt * 64 * HDIM;
        const float* Vt = Vg + (size_t)kt * 64 * HDIM;
#pragma unroll
        for (int u = 0; u < 4; u++) {
            float4 v = *(const float4*)&Kt[(size_t)lr * HDIM + lc0 + u * 4];
            Ks[(lc0 + u * 4 + 0) * 65 + lr] = v.x;
            Ks[(lc0 + u * 4 + 1) * 65 + lr] = v.y;
            Ks[(lc0 + u * 4 + 2) * 65 + lr] = v.z;
            Ks[(lc0 + u * 4 + 3) * 65 + lr] = v.w;
            float4 w2 = *(const float4*)&Vt[(size_t)lr * HDIM + lc0 + u * 4];
            *(float4*)&Vs[lr * VS_STRIDE + lc0 + u * 4] = w2;
        }
        __syncthreads();

        // S = Q K^T (microtile)
        float s[4][4];
#pragma unroll
        for (int i = 0; i < 4; i++)
#pragma unroll
            for (int jj = 0; jj < 4; jj++) s[i][jj] = 0.f;
#pragma unroll 16
        for (int d = 0; d < 64; d++) {
            float a[4], bb[4];
#pragma unroll
            for (int i = 0; i < 4; i++) a[i] = Qs[d * 65 + ty * 4 + i];
#pragma unroll
            for (int jj = 0; jj < 4; jj++) bb[jj] = Ks[d * 65 + tx * 4 + jj];
#pragma unroll
            for (int i = 0; i < 4; i++)
#pragma unroll
                for (int jj = 0; jj < 4; jj++) s[i][jj] += a[i] * bb[jj];
        }

        const bool diag = (kt == qt);
#pragma unroll
        for (int i = 0; i < 4; i++)
#pragma unroll
            for (int jj = 0; jj < 4; jj++) {
                s[i][jj] *= 0.125f;  // HD^-0.5
                if (diag && (tx * 4 + jj > ty * 4 + i)) s[i][jj] = -INFINITY;
            }

        // online softmax (row groups = 16 lanes sharing ty)
#pragma unroll
        for (int i = 0; i < 4; i++) {
            float mx = fmaxf(fmaxf(s[i][0], s[i][1]), fmaxf(s[i][2], s[i][3]));
#pragma unroll
            for (int od = 8; od > 0; od >>= 1) mx = fmaxf(mx, __shfl_xor_sync(0xffffffffu, mx, od));
            float mnew = fmaxf(m[i], mx);
            float alpha = expf(m[i] - mnew);
            m[i] = mnew;
            float rs = 0.f;
#pragma unroll
            for (int jj = 0; jj < 4; jj++) { s[i][jj] = expf(s[i][jj] - mnew); rs += s[i][jj]; }
#pragma unroll
            for (int od = 8; od > 0; od >>= 1) rs += __shfl_xor_sync(0xffffffffu, rs, od);
            lsum[i] = lsum[i] * alpha + rs;
#pragma unroll
            for (int jj = 0; jj < 4; jj++) o[i][jj] *= alpha;
        }

        // stage P (transposed) and do O += P V
#pragma unroll
        for (int i = 0; i < 4; i++)
#pragma unroll
            for (int jj = 0; jj < 4; jj++) Ps[(tx * 4 + jj) * 65 + ty * 4 + i] = s[i][jj];
        __syncthreads();
#pragma unroll 16
        for (int c = 0; c < 64; c++) {
            float a[4], bb[4];
#pragma unroll
            for (int i = 0; i < 4; i++) a[i] = Ps[c * 65 + ty * 4 + i];
#pragma unroll
            for (int jj = 0; jj < 4; jj++) bb[jj] = Vs[c * VS_STRIDE + tx * 4 + jj];
#pragma unroll
            for (int i = 0; i < 4; i++)
#pragma unroll
                for (int jj = 0; jj < 4; jj++) o[i][jj] += a[i] * bb[jj];
        }
    }

    // epilogue: normalize, add v_res, write [tok, H*64]
#pragma unroll
    for (int i = 0; i < 4; i++) {
        const int r = ty * 4 + i;
        const float inv = 1.0f / lsum[i];
        const size_t tok = (size_t)b * TSEQ + q0 + r;
        float4 vr = *(const float4*)&vres[tok * 512 + h * 64 + tx * 4];
        float4 ov;
        ov.x = o[i][0] * inv + vr.x;
        ov.y = o[i][1] * inv + vr.y;
        ov.z = o[i][2] * inv + vr.z;
        ov.w = o[i][3] * inv + vr.w;
        *(float4*)&attn[tok * 512 + h * 64 + tx * 4] = ov;
    }
}

// ---------------- launch ----------------
extern "C" void kernel_launch(void* const* d_in, const int* in_sizes, int n_in,
                              void* d_out, int out_size) {
    const float* x     = (const float*)d_in[0];
    const float* W_DQ  = (const float*)d_in[1];
    const float* W_UQ  = (const float*)d_in[2];
    const float* W_QR  = (const float*)d_in[3];
    const float* W_DKV = (const float*)d_in[4];
    const float* W_UK  = (const float*)d_in[5];
    const float* W_UV  = (const float*)d_in[6];
    const float* W_KR  = (const float*)d_in[7];
    const float* W_VR  = (const float*)d_in[8];
    const float* W_O   = (const float*)d_in[9];
    const float* q_ln  = (const float*)d_in[10];
    const float* kv_ln = (const float*)d_in[11];
    const float* qhw   = (const float*)d_in[12];
    const float* khw   = (const float*)d_in[13];
    float* out = (float*)d_out;

    float *cq, *ckv, *krope, *vres, *qnope, *qrope, *knope, *vv, *attn;
    cudaGetSymbolAddress((void**)&cq,    g_cq);
    cudaGetSymbolAddress((void**)&ckv,   g_ckv);
    cudaGetSymbolAddress((void**)&krope, g_krope);
    cudaGetSymbolAddress((void**)&vres,  g_vres);
    cudaGetSymbolAddress((void**)&qnope, g_qnope);
    cudaGetSymbolAddress((void**)&qrope, g_qrope);
    cudaGetSymbolAddress((void**)&knope, g_knope);
    cudaGetSymbolAddress((void**)&vv,    g_vv);
    cudaGetSymbolAddress((void**)&attn,  g_attn);

    const int FSM = (3 * 65 + VS_STRIDE) * 64 * (int)sizeof(float);
    cudaFuncSetAttribute(flash, cudaFuncAttributeMaxDynamicSharedMemorySize, FSM);

    // x projections
    sgemm64<<<dim3(256 / 64, NTOK / 64), 256>>>(x, W_DQ,  cq,    NTOK, 256, 512);
    sgemm64<<<dim3(128 / 64, NTOK / 64), 256>>>(x, W_DKV, ckv,   NTOK, 128, 512);
    sgemm64<<<dim3( 64 / 64, NTOK / 64), 256>>>(x, W_KR,  krope, NTOK,  64, 512);
    sgemm64<<<dim3(512 / 64, NTOK / 64), 256>>>(x, W_VR,  vres,  NTOK, 512, 512);

    // latent RMS norms
    rms_inplace<<<NTOK, 256>>>(cq,  q_ln,  256);
    rms_inplace<<<NTOK, 128>>>(ckv, kv_ln, 128);

    // up-projections
    sgemm64<<<dim3(256 / 64, NTOK / 64), 256>>>(cq,  W_UQ, qnope, NTOK, 256, 256);
    sgemm64<<<dim3(256 / 64, NTOK / 64), 256>>>(cq,  W_QR, qrope, NTOK, 256, 256);
    sgemm64<<<dim3( 64 / 64, NTOK / 64), 256>>>(ckv, W_UK, knope, NTOK,  64, 128);
    sgemm64<<<dim3(128 / 64, NTOK / 64), 256>>>(ckv, W_UV, vv,    NTOK, 128, 128);

    // rope + concat + head-RMS + layout
    assemble<<<NTOK, 256>>>(qhw, khw);

    // causal flash attention + v_res
    flash<<<dim3(TSEQ / 64, BATCH * NHEADS), 256, FSM>>>(vres, attn);

    // output projection
    sgemm64<<<dim3(512 / 64, NTOK / 64), 256>>>(attn, W_O, out, NTOK, 512, 512);
}

// round 5
// speedup vs baseline: 1.1550x; 1.1550x over previous
#include <cuda_runtime.h>
#include <cuda_bf16.h>
#include <math.h>
#include <stdint.h>

#define NHEADS 8
#define NKVH   2
#define HDIM   64
#define TSEQ   2048
#define BATCH  4
#define NTOK   (BATCH*TSEQ)   /* 8192 */

// ---------------- scratch (device globals; no allocation allowed) ----------------
__device__ float g_cq   [NTOK*256];
__device__ float g_ckv  [NTOK*128];
__device__ float g_krope[NTOK*64];
__device__ float g_vres [NTOK*512];
__device__ float g_qnope[NTOK*256];
__device__ float g_qrope[NTOK*256];
__device__ float g_knope[NTOK*64];
__device__ float g_vv   [NTOK*128];
__device__ float g_q [BATCH*NHEADS*TSEQ*HDIM];
__device__ float g_k [BATCH*NKVH  *TSEQ*HDIM];
__device__ float g_vt[BATCH*NKVH  *TSEQ*HDIM];
__device__ float g_attn[NTOK*512];

__device__ __forceinline__ uint32_t packbf(__nv_bfloat16 a, __nv_bfloat16 b) {
    return ((uint32_t)__bfloat16_as_ushort(b) << 16) | (uint32_t)__bfloat16_as_ushort(a);
}

__device__ __forceinline__ void mma16816(float* c, uint32_t a0, uint32_t a1,
                                         uint32_t a2, uint32_t a3,
                                         uint32_t b0, uint32_t b1) {
    asm volatile(
        "mma.sync.aligned.m16n8k16.row.col.f32.bf16.bf16.f32 "
        "{%0,%1,%2,%3}, {%4,%5,%6,%7}, {%8,%9}, {%0,%1,%2,%3};"
        : "+f"(c[0]), "+f"(c[1]), "+f"(c[2]), "+f"(c[3])
        : "r"(a0), "r"(a1), "r"(a2), "r"(a3), "r"(b0), "r"(b1));
}

// ---------------- bf16x3 HMMA GEMM: C[M,N] = A[M,K] @ B[K,N] ----------------
// Block 128x64, 8 warps (4m x 2n), warp tile 32x32, K-chunks of 64.
// A,B fp32 in GMEM, split to bf16 hi/lo in the loader. fp32 accumulate.
// C = Ah*Bh + Al*Bh + Ah*Bl  (bf16x3; missing lo*lo term ~2^-16).
#define SA 72   /* element stride of A tiles: 36 words -> conflict-free frag LDS */
#define SB 72
#define HG_AH   0
#define HG_AL   18432
#define HG_BH   36864
#define HG_BL   46080
#define HG_SMEM 55296

extern __shared__ char gsm[];
__global__ __launch_bounds__(256) void hgemm(const float* __restrict__ A,
                                             const float* __restrict__ B,
                                             float* __restrict__ C,
                                             int M, int N, int K) {
    __nv_bfloat16* AsH = (__nv_bfloat16*)(gsm + HG_AH);
    __nv_bfloat16* AsL = (__nv_bfloat16*)(gsm + HG_AL);
    __nv_bfloat16* BsH = (__nv_bfloat16*)(gsm + HG_BH);
    __nv_bfloat16* BsL = (__nv_bfloat16*)(gsm + HG_BL);

    const int tid = threadIdx.x, wid = tid >> 5, lane = tid & 31;
    const int wm = wid & 3, wn = wid >> 2;        // warp grid 4x2
    const int g = lane >> 2, t = lane & 3;
    const int m0 = blockIdx.y * 128, n0 = blockIdx.x * 64;

    float acc[2][4][4];
#pragma unroll
    for (int i = 0; i < 2; i++)
#pragma unroll
        for (int j = 0; j < 4; j++)
#pragma unroll
            for (int r = 0; r < 4; r++) acc[i][j][r] = 0.f;

    const int nch = K >> 6;
    for (int c = 0; c < nch; c++) {
        if (c > 0) __syncthreads();
        const int c64 = c << 6;
        // ---- A chunk: 128 x 64 fp32 -> hi/lo bf16, row-major stride SA ----
#pragma unroll
        for (int i = tid; i < 2048; i += 256) {
            const int row = i >> 4;
            const int col4 = (i & 15) << 2;
            const float4 av = *(const float4*)&A[(size_t)(m0 + row) * K + c64 + col4];
            __nv_bfloat16 h0 = __float2bfloat16(av.x), h1 = __float2bfloat16(av.y);
            __nv_bfloat16 h2 = __float2bfloat16(av.z), h3 = __float2bfloat16(av.w);
            __nv_bfloat16 l0 = __float2bfloat16(av.x - __bfloat162float(h0));
            __nv_bfloat16 l1 = __float2bfloat16(av.y - __bfloat162float(h1));
            __nv_bfloat16 l2 = __float2bfloat16(av.z - __bfloat162float(h2));
            __nv_bfloat16 l3 = __float2bfloat16(av.w - __bfloat162float(h3));
            *(uint2*)&AsH[row * SA + col4] = make_uint2(packbf(h0, h1), packbf(h2, h3));
            *(uint2*)&AsL[row * SA + col4] = make_uint2(packbf(l0, l1), packbf(l2, l3));
        }
        // ---- B chunk: 64 k-rows x 64 n-cols fp32, transposed to [n][k], stride SB ----
#pragma unroll
        for (int i = tid; i < 1024; i += 256) {
            const int k = i >> 4;
            const int n4 = (i & 15) << 2;
            const float4 bv = *(const float4*)&B[(size_t)(c64 + k) * N + n0 + n4];
            const float vals[4] = {bv.x, bv.y, bv.z, bv.w};
#pragma unroll
            for (int j = 0; j < 4; j++) {
                __nv_bfloat16 h = __float2bfloat16(vals[j]);
                __nv_bfloat16 l = __float2bfloat16(vals[j] - __bfloat162float(h));
                BsH[(n4 + j) * SB + k] = h;
                BsL[(n4 + j) * SB + k] = l;
            }
        }
        __syncthreads();

        // ---- compute: 4 k16 steps ----
#pragma unroll
        for (int kk = 0; kk < 64; kk += 16) {
            uint32_t ah[2][4], al[2][4], bh[4][2], bl[4][2];
#pragma unroll
            for (int i = 0; i < 2; i++) {
                const int r0 = wm * 32 + i * 16 + g;
                ah[i][0] = *(const uint32_t*)&AsH[(r0)     * SA + kk + 2 * t];
                ah[i][1] = *(const uint32_t*)&AsH[(r0 + 8) * SA + kk + 2 * t];
                ah[i][2] = *(const uint32_t*)&AsH[(r0)     * SA + kk + 8 + 2 * t];
                ah[i][3] = *(const uint32_t*)&AsH[(r0 + 8) * SA + kk + 8 + 2 * t];
                al[i][0] = *(const uint32_t*)&AsL[(r0)     * SA + kk + 2 * t];
                al[i][1] = *(const uint32_t*)&AsL[(r0 + 8) * SA + kk + 2 * t];
                al[i][2] = *(const uint32_t*)&AsL[(r0)     * SA + kk + 8 + 2 * t];
                al[i][3] = *(const uint32_t*)&AsL[(r0 + 8) * SA + kk + 8 + 2 * t];
            }
#pragma unroll
            for (int j = 0; j < 4; j++) {
                const int n = wn * 32 + j * 8 + g;
                bh[j][0] = *(const uint32_t*)&BsH[n * SB + kk + 2 * t];
                bh[j][1] = *(const uint32_t*)&BsH[n * SB + kk + 8 + 2 * t];
                bl[j][0] = *(const uint32_t*)&BsL[n * SB + kk + 2 * t];
                bl[j][1] = *(const uint32_t*)&BsL[n * SB + kk + 8 + 2 * t];
            }
#pragma unroll
            for (int i = 0; i < 2; i++)
#pragma unroll
                for (int j = 0; j < 4; j++) {
                    mma16816(acc[i][j], ah[i][0], ah[i][1], ah[i][2], ah[i][3], bh[j][0], bh[j][1]);
                    mma16816(acc[i][j], al[i][0], al[i][1], al[i][2], al[i][3], bh[j][0], bh[j][1]);
                    mma16816(acc[i][j], ah[i][0], ah[i][1], ah[i][2], ah[i][3], bl[j][0], bl[j][1]);
                }
        }
    }

    // ---- epilogue ----
#pragma unroll
    for (int i = 0; i < 2; i++)
#pragma unroll
        for (int j = 0; j < 4; j++) {
            const int row = m0 + wm * 32 + i * 16 + g;
            const int col = n0 + wn * 32 + j * 8 + 2 * t;
            *(float2*)&C[(size_t)row * N + col]       = make_float2(acc[i][j][0], acc[i][j][1]);
            *(float2*)&C[(size_t)(row + 8) * N + col] = make_float2(acc[i][j][2], acc[i][j][3]);
        }
}

// ---------------- in-place RMSNorm over last dim D (blockDim == D) ----------------
__global__ void rms_inplace(float* __restrict__ X, const float* __restrict__ w, int D) {
    const int n = blockIdx.x;
    float* row = X + (size_t)n * D;
    const int tid = threadIdx.x;
    float v = row[tid];
    float ss = v * v;
#pragma unroll
    for (int o = 16; o > 0; o >>= 1) ss += __shfl_xor_sync(0xffffffffu, ss, o);
    __shared__ float sh[8];
    const int wid = tid >> 5, nw = blockDim.x >> 5;
    if ((tid & 31) == 0) sh[wid] = ss;
    __syncthreads();
    float tot = 0.f;
    for (int i = 0; i < nw; i++) tot += sh[i];
    float scale = rsqrtf(tot / (float)D + 1e-6f);
    row[tid] = v * scale * w[tid];
}

// ---------------- RoPE + concat + per-head RMS + layout to [B,h,T,64] ----------------
__global__ __launch_bounds__(256) void assemble(const float* __restrict__ qhw,
                                                const float* __restrict__ khw) {
    const int n = blockIdx.x;
    const int b = n / TSEQ, t = n % TSEQ;
    const int tid = threadIdx.x, w = tid >> 5, l = tid & 31;

    const int j = l & 15;
    const float invf = powf(500000.0f, -(float)j / 16.0f);
    const float f = (float)t * invf;
    const float cs = cosf(f), sn = sinf(f);

    {
        const int h = w;
        float v0 = g_qnope[(size_t)n * 256 + h * 32 + l];
        const float* qr = &g_qrope[(size_t)n * 256 + h * 32];
        float a = qr[l];
        float v1 = (l < 16) ? (a * cs - qr[l + 16] * sn) : (a * cs + qr[l - 16] * sn);
        float ss = v0 * v0 + v1 * v1;
#pragma unroll
        for (int o = 16; o > 0; o >>= 1) ss += __shfl_xor_sync(0xffffffffu, ss, o);
        float scale = rsqrtf(ss / 64.0f + 1e-6f);
        float* qo = &g_q[(((size_t)b * NHEADS + h) * TSEQ + t) * HDIM];
        qo[l]      = v0 * scale * qhw[l];
        qo[32 + l] = v1 * scale * qhw[32 + l];
    }
    if (w < 2) {
        const int kvh = w;
        float v0 = g_knope[(size_t)n * 64 + kvh * 32 + l];
        const float* kr = &g_krope[(size_t)n * 64 + kvh * 32];
        float a = kr[l];
        float v1 = (l < 16) ? (a * cs - kr[l + 16] * sn) : (a * cs + kr[l - 16] * sn);
        float ss = v0 * v0 + v1 * v1;
#pragma unroll
        for (int o = 16; o > 0; o >>= 1) ss += __shfl_xor_sync(0xffffffffu, ss, o);
        float scale = rsqrtf(ss / 64.0f + 1e-6f);
        float* ko = &g_k[(((size_t)b * NKVH + kvh) * TSEQ + t) * HDIM];
        ko[l]      = v0 * scale * khw[l];
        ko[32 + l] = v1 * scale * khw[32 + l];
    } else if (w < 4) {
        const int kvh = w - 2;
        float* vo = &g_vt[(((size_t)b * NKVH + kvh) * TSEQ + t) * HDIM];
        vo[l]      = g_vv[(size_t)n * 128 + kvh * 64 + l];
        vo[32 + l] = g_vv[(size_t)n * 128 + kvh * 64 + 32 + l];
    }
}

// ---------------- causal flash attention, BM=BN=64, d=64 ----------------
#define VS_STRIDE 68
extern __shared__ float fsm[];
__global__ __launch_bounds__(256) void flash(const float* __restrict__ vres,
                                             float* __restrict__ attn) {
    float* Qs = fsm;
    float* Ks = Qs + 64 * 65;
    float* Vs = Ks + 64 * 65;
    float* Ps = Vs + 64 * VS_STRIDE;

    const int qt = blockIdx.x;
    const int bh = blockIdx.y;
    const int b = bh >> 3, h = bh & 7, kvh = h >> 2;
    const int q0 = qt * 64;

    const float* Qg = &g_q [(((size_t)b * NHEADS + h)  * TSEQ + q0) * HDIM];
    const float* Kg = &g_k [(((size_t)b * NKVH + kvh) * TSEQ) * HDIM];
    const float* Vg = &g_vt[(((size_t)b * NKVH + kvh) * TSEQ) * HDIM];

    const int tid = threadIdx.x, ty = tid >> 4, tx = tid & 15;
    const int lr = tid >> 2, lc0 = (tid & 3) * 16;

#pragma unroll
    for (int u = 0; u < 4; u++) {
        float4 v = *(const float4*)&Qg[(size_t)lr * HDIM + lc0 + u * 4];
        Qs[(lc0 + u * 4 + 0) * 65 + lr] = v.x;
        Qs[(lc0 + u * 4 + 1) * 65 + lr] = v.y;
        Qs[(lc0 + u * 4 + 2) * 65 + lr] = v.z;
        Qs[(lc0 + u * 4 + 3) * 65 + lr] = v.w;
    }

    float m[4], lsum[4], o[4][4];
#pragma unroll
    for (int i = 0; i < 4; i++) {
        m[i] = -INFINITY; lsum[i] = 0.f;
#pragma unroll
        for (int jj = 0; jj < 4; jj++) o[i][jj] = 0.f;
    }

    for (int kt = 0; kt <= qt; kt++) {
        __syncthreads();
        const float* Kt = Kg + (size_t)kt * 64 * HDIM;
        const float* Vt = Vg + (size_t)kt * 64 * HDIM;
#pragma unroll
        for (int u = 0; u < 4; u++) {
            float4 v = *(const float4*)&Kt[(size_t)lr * HDIM + lc0 + u * 4];
            Ks[(lc0 + u * 4 + 0) * 65 + lr] = v.x;
            Ks[(lc0 + u * 4 + 1) * 65 + lr] = v.y;
            Ks[(lc0 + u * 4 + 2) * 65 + lr] = v.z;
            Ks[(lc0 + u * 4 + 3) * 65 + lr] = v.w;
            float4 w2 = *(const float4*)&Vt[(size_t)lr * HDIM + lc0 + u * 4];
            *(float4*)&Vs[lr * VS_STRIDE + lc0 + u * 4] = w2;
        }
        __syncthreads();

        float s[4][4];
#pragma unroll
        for (int i = 0; i < 4; i++)
#pragma unroll
            for (int jj = 0; jj < 4; jj++) s[i][jj] = 0.f;
#pragma unroll 16
        for (int d = 0; d < 64; d++) {
            float a[4], bb[4];
#pragma unroll
            for (int i = 0; i < 4; i++) a[i] = Qs[d * 65 + ty * 4 + i];
#pragma unroll
            for (int jj = 0; jj < 4; jj++) bb[jj] = Ks[d * 65 + tx * 4 + jj];
#pragma unroll
            for (int i = 0; i < 4; i++)
#pragma unroll
                for (int jj = 0; jj < 4; jj++) s[i][jj] += a[i] * bb[jj];
        }

        const bool diag = (kt == qt);
#pragma unroll
        for (int i = 0; i < 4; i++)
#pragma unroll
            for (int jj = 0; jj < 4; jj++) {
                s[i][jj] *= 0.125f;
                if (diag && (tx * 4 + jj > ty * 4 + i)) s[i][jj] = -INFINITY;
            }

#pragma unroll
        for (int i = 0; i < 4; i++) {
            float mx = fmaxf(fmaxf(s[i][0], s[i][1]), fmaxf(s[i][2], s[i][3]));
#pragma unroll
            for (int od = 8; od > 0; od >>= 1) mx = fmaxf(mx, __shfl_xor_sync(0xffffffffu, mx, od));
            float mnew = fmaxf(m[i], mx);
            float alpha = __expf(m[i] - mnew);
            m[i] = mnew;
            float rs = 0.f;
#pragma unroll
            for (int jj = 0; jj < 4; jj++) { s[i][jj] = __expf(s[i][jj] - mnew); rs += s[i][jj]; }
#pragma unroll
            for (int od = 8; od > 0; od >>= 1) rs += __shfl_xor_sync(0xffffffffu, rs, od);
            lsum[i] = lsum[i] * alpha + rs;
#pragma unroll
            for (int jj = 0; jj < 4; jj++) o[i][jj] *= alpha;
        }

#pragma unroll
        for (int i = 0; i < 4; i++)
#pragma unroll
            for (int jj = 0; jj < 4; jj++) Ps[(tx * 4 + jj) * 65 + ty * 4 + i] = s[i][jj];
        __syncthreads();
#pragma unroll 16
        for (int c = 0; c < 64; c++) {
            float a[4], bb[4];
#pragma unroll
            for (int i = 0; i < 4; i++) a[i] = Ps[c * 65 + ty * 4 + i];
#pragma unroll
            for (int jj = 0; jj < 4; jj++) bb[jj] = Vs[c * VS_STRIDE + tx * 4 + jj];
#pragma unroll
            for (int i = 0; i < 4; i++)
#pragma unroll
                for (int jj = 0; jj < 4; jj++) o[i][jj] += a[i] * bb[jj];
        }
    }

#pragma unroll
    for (int i = 0; i < 4; i++) {
        const int r = ty * 4 + i;
        const float inv = 1.0f / lsum[i];
        const size_t tok = (size_t)b * TSEQ + q0 + r;
        float4 vr = *(const float4*)&vres[tok * 512 + h * 64 + tx * 4];
        float4 ov;
        ov.x = o[i][0] * inv + vr.x;
        ov.y = o[i][1] * inv + vr.y;
        ov.z = o[i][2] * inv + vr.z;
        ov.w = o[i][3] * inv + vr.w;
        *(float4*)&attn[tok * 512 + h * 64 + tx * 4] = ov;
    }
}

// ---------------- launch ----------------
extern "C" void kernel_launch(void* const* d_in, const int* in_sizes, int n_in,
                              void* d_out, int out_size) {
    const float* x     = (const float*)d_in[0];
    const float* W_DQ  = (const float*)d_in[1];
    const float* W_UQ  = (const float*)d_in[2];
    const float* W_QR  = (const float*)d_in[3];
    const float* W_DKV = (const float*)d_in[4];
    const float* W_UK  = (const float*)d_in[5];
    const float* W_UV  = (const float*)d_in[6];
    const float* W_KR  = (const float*)d_in[7];
    const float* W_VR  = (const float*)d_in[8];
    const float* W_O   = (const float*)d_in[9];
    const float* q_ln  = (const float*)d_in[10];
    const float* kv_ln = (const float*)d_in[11];
    const float* qhw   = (const float*)d_in[12];
    const float* khw   = (const float*)d_in[13];
    float* out = (float*)d_out;

    float *cq, *ckv, *krope, *vres, *qnope, *qrope, *knope, *vv, *attn;
    cudaGetSymbolAddress((void**)&cq,    g_cq);
    cudaGetSymbolAddress((void**)&ckv,   g_ckv);
    cudaGetSymbolAddress((void**)&krope, g_krope);
    cudaGetSymbolAddress((void**)&vres,  g_vres);
    cudaGetSymbolAddress((void**)&qnope, g_qnope);
    cudaGetSymbolAddress((void**)&qrope, g_qrope);
    cudaGetSymbolAddress((void**)&knope, g_knope);
    cudaGetSymbolAddress((void**)&vv,    g_vv);
    cudaGetSymbolAddress((void**)&attn,  g_attn);

    const int FSM = (3 * 65 + VS_STRIDE) * 64 * (int)sizeof(float);
    cudaFuncSetAttribute(flash, cudaFuncAttributeMaxDynamicSharedMemorySize, FSM);
    cudaFuncSetAttribute(hgemm, cudaFuncAttributeMaxDynamicSharedMemorySize, HG_SMEM);

#define GEMM(A, Bm, Cm, Mv, Nv, Kv) \
    hgemm<<<dim3((Nv) / 64, (Mv) / 128), 256, HG_SMEM>>>(A, Bm, Cm, Mv, Nv, Kv)

    // x projections
    GEMM(x, W_DQ,  cq,    NTOK, 256, 512);
    GEMM(x, W_DKV, ckv,   NTOK, 128, 512);
    GEMM(x, W_KR,  krope, NTOK,  64, 512);
    GEMM(x, W_VR,  vres,  NTOK, 512, 512);

    // latent RMS norms
    rms_inplace<<<NTOK, 256>>>(cq,  q_ln,  256);
    rms_inplace<<<NTOK, 128>>>(ckv, kv_ln, 128);

    // up-projections
    GEMM(cq,  W_UQ, qnope, NTOK, 256, 256);
    GEMM(cq,  W_QR, qrope, NTOK, 256, 256);
    GEMM(ckv, W_UK, knope, NTOK,  64, 128);
    GEMM(ckv, W_UV, vv,    NTOK, 128, 128);

    // rope + concat + head-RMS + layout
    assemble<<<NTOK, 256>>>(qhw, khw);

    // causal flash attention + v_res
    flash<<<dim3(TSEQ / 64, BATCH * NHEADS), 256, FSM>>>(vres, attn);

    // output projection
    GEMM(attn, W_O, out, NTOK, 512, 512);
}

// round 6
// speedup vs baseline: 1.9109x; 1.6545x over previous
#include <cuda_runtime.h>
#include <cuda_bf16.h>
#include <math.h>
#include <stdint.h>

#define NHEADS 8
#define NKVH   2
#define HDIM   64
#define TSEQ   2048
#define BATCH  4
#define NTOK   (BATCH*TSEQ)   /* 8192 */

// ---------------- scratch (device globals; no allocation allowed) ----------------
__device__ float g_cq   [NTOK*256];
__device__ float g_ckv  [NTOK*128];
__device__ float g_krope[NTOK*64];
__device__ float g_vres [NTOK*512];
__device__ float g_qnope[NTOK*256];
__device__ float g_qrope[NTOK*256];
__device__ float g_knope[NTOK*64];
__device__ float g_vv   [NTOK*128];
__device__ float g_q [BATCH*NHEADS*TSEQ*HDIM];
__device__ float g_k [BATCH*NKVH  *TSEQ*HDIM];
__device__ float g_vt[BATCH*NKVH  *TSEQ*HDIM];
__device__ float g_attn[NTOK*512];

__device__ __forceinline__ uint32_t packbf(__nv_bfloat16 a, __nv_bfloat16 b) {
    return ((uint32_t)__bfloat16_as_ushort(b) << 16) | (uint32_t)__bfloat16_as_ushort(a);
}

__device__ __forceinline__ void mma16816(float* c, uint32_t a0, uint32_t a1,
                                         uint32_t a2, uint32_t a3,
                                         uint32_t b0, uint32_t b1) {
    asm volatile(
        "mma.sync.aligned.m16n8k16.row.col.f32.bf16.bf16.f32 "
        "{%0,%1,%2,%3}, {%4,%5,%6,%7}, {%8,%9}, {%0,%1,%2,%3};"
        : "+f"(c[0]), "+f"(c[1]), "+f"(c[2]), "+f"(c[3])
        : "r"(a0), "r"(a1), "r"(a2), "r"(a3), "r"(b0), "r"(b1));
}

// split fp32 -> bf16 hi + lo
__device__ __forceinline__ void bfsplit(float v, __nv_bfloat16& h, __nv_bfloat16& l) {
    h = __float2bfloat16(v);
    l = __float2bfloat16(v - __bfloat162float(h));
}

// ---------------- bf16x3 HMMA GEMM: C[M,N] = A[M,K] @ B[K,N] ----------------
#define SA 72
#define SB 72
#define HG_AH   0
#define HG_AL   18432
#define HG_BH   36864
#define HG_BL   46080
#define HG_SMEM 55296

extern __shared__ char gsm[];
__global__ __launch_bounds__(256) void hgemm(const float* __restrict__ A,
                                             const float* __restrict__ B,
                                             float* __restrict__ C,
                                             int M, int N, int K) {
    __nv_bfloat16* AsH = (__nv_bfloat16*)(gsm + HG_AH);
    __nv_bfloat16* AsL = (__nv_bfloat16*)(gsm + HG_AL);
    __nv_bfloat16* BsH = (__nv_bfloat16*)(gsm + HG_BH);
    __nv_bfloat16* BsL = (__nv_bfloat16*)(gsm + HG_BL);

    const int tid = threadIdx.x, wid = tid >> 5, lane = tid & 31;
    const int wm = wid & 3, wn = wid >> 2;
    const int g = lane >> 2, t = lane & 3;
    const int m0 = blockIdx.y * 128, n0 = blockIdx.x * 64;

    float acc[2][4][4];
#pragma unroll
    for (int i = 0; i < 2; i++)
#pragma unroll
        for (int j = 0; j < 4; j++)
#pragma unroll
            for (int r = 0; r < 4; r++) acc[i][j][r] = 0.f;

    const int nch = K >> 6;
    for (int c = 0; c < nch; c++) {
        if (c > 0) __syncthreads();
        const int c64 = c << 6;
#pragma unroll
        for (int i = tid; i < 2048; i += 256) {
            const int row = i >> 4;
            const int col4 = (i & 15) << 2;
            const float4 av = *(const float4*)&A[(size_t)(m0 + row) * K + c64 + col4];
            __nv_bfloat16 h0, h1, h2, h3, l0, l1, l2, l3;
            bfsplit(av.x, h0, l0); bfsplit(av.y, h1, l1);
            bfsplit(av.z, h2, l2); bfsplit(av.w, h3, l3);
            *(uint2*)&AsH[row * SA + col4] = make_uint2(packbf(h0, h1), packbf(h2, h3));
            *(uint2*)&AsL[row * SA + col4] = make_uint2(packbf(l0, l1), packbf(l2, l3));
        }
#pragma unroll
        for (int i = tid; i < 1024; i += 256) {
            const int k = i >> 4;
            const int n4 = (i & 15) << 2;
            const float4 bv = *(const float4*)&B[(size_t)(c64 + k) * N + n0 + n4];
            const float vals[4] = {bv.x, bv.y, bv.z, bv.w};
#pragma unroll
            for (int j = 0; j < 4; j++) {
                __nv_bfloat16 h, l;
                bfsplit(vals[j], h, l);
                BsH[(n4 + j) * SB + k] = h;
                BsL[(n4 + j) * SB + k] = l;
            }
        }
        __syncthreads();

#pragma unroll
        for (int kk = 0; kk < 64; kk += 16) {
            uint32_t ah[2][4], al[2][4], bh[4][2], bl[4][2];
#pragma unroll
            for (int i = 0; i < 2; i++) {
                const int r0 = wm * 32 + i * 16 + g;
                ah[i][0] = *(const uint32_t*)&AsH[(r0)     * SA + kk + 2 * t];
                ah[i][1] = *(const uint32_t*)&AsH[(r0 + 8) * SA + kk + 2 * t];
                ah[i][2] = *(const uint32_t*)&AsH[(r0)     * SA + kk + 8 + 2 * t];
                ah[i][3] = *(const uint32_t*)&AsH[(r0 + 8) * SA + kk + 8 + 2 * t];
                al[i][0] = *(const uint32_t*)&AsL[(r0)     * SA + kk + 2 * t];
                al[i][1] = *(const uint32_t*)&AsL[(r0 + 8) * SA + kk + 2 * t];
                al[i][2] = *(const uint32_t*)&AsL[(r0)     * SA + kk + 8 + 2 * t];
                al[i][3] = *(const uint32_t*)&AsL[(r0 + 8) * SA + kk + 8 + 2 * t];
            }
#pragma unroll
            for (int j = 0; j < 4; j++) {
                const int n = wn * 32 + j * 8 + g;
                bh[j][0] = *(const uint32_t*)&BsH[n * SB + kk + 2 * t];
                bh[j][1] = *(const uint32_t*)&BsH[n * SB + kk + 8 + 2 * t];
                bl[j][0] = *(const uint32_t*)&BsL[n * SB + kk + 2 * t];
                bl[j][1] = *(const uint32_t*)&BsL[n * SB + kk + 8 + 2 * t];
            }
#pragma unroll
            for (int i = 0; i < 2; i++)
#pragma unroll
                for (int j = 0; j < 4; j++) {
                    mma16816(acc[i][j], ah[i][0], ah[i][1], ah[i][2], ah[i][3], bh[j][0], bh[j][1]);
                    mma16816(acc[i][j], al[i][0], al[i][1], al[i][2], al[i][3], bh[j][0], bh[j][1]);
                    mma16816(acc[i][j], ah[i][0], ah[i][1], ah[i][2], ah[i][3], bl[j][0], bl[j][1]);
                }
        }
    }

#pragma unroll
    for (int i = 0; i < 2; i++)
#pragma unroll
        for (int j = 0; j < 4; j++) {
            const int row = m0 + wm * 32 + i * 16 + g;
            const int col = n0 + wn * 32 + j * 8 + 2 * t;
            *(float2*)&C[(size_t)row * N + col]       = make_float2(acc[i][j][0], acc[i][j][1]);
            *(float2*)&C[(size_t)(row + 8) * N + col] = make_float2(acc[i][j][2], acc[i][j][3]);
        }
}

// ---------------- in-place RMSNorm over last dim D (blockDim == D) ----------------
__global__ void rms_inplace(float* __restrict__ X, const float* __restrict__ w, int D) {
    const int n = blockIdx.x;
    float* row = X + (size_t)n * D;
    const int tid = threadIdx.x;
    float v = row[tid];
    float ss = v * v;
#pragma unroll
    for (int o = 16; o > 0; o >>= 1) ss += __shfl_xor_sync(0xffffffffu, ss, o);
    __shared__ float sh[8];
    const int wid = tid >> 5, nw = blockDim.x >> 5;
    if ((tid & 31) == 0) sh[wid] = ss;
    __syncthreads();
    float tot = 0.f;
    for (int i = 0; i < nw; i++) tot += sh[i];
    float scale = rsqrtf(tot / (float)D + 1e-6f);
    row[tid] = v * scale * w[tid];
}

// ---------------- RoPE + concat + per-head RMS + layout to [B,h,T,64] ----------------
__global__ __launch_bounds__(256) void assemble(const float* __restrict__ qhw,
                                                const float* __restrict__ khw) {
    const int n = blockIdx.x;
    const int b = n / TSEQ, t = n % TSEQ;
    const int tid = threadIdx.x, w = tid >> 5, l = tid & 31;

    const int j = l & 15;
    const float invf = powf(500000.0f, -(float)j / 16.0f);
    const float f = (float)t * invf;
    const float cs = cosf(f), sn = sinf(f);

    {
        const int h = w;
        float v0 = g_qnope[(size_t)n * 256 + h * 32 + l];
        const float* qr = &g_qrope[(size_t)n * 256 + h * 32];
        float a = qr[l];
        float v1 = (l < 16) ? (a * cs - qr[l + 16] * sn) : (a * cs + qr[l - 16] * sn);
        float ss = v0 * v0 + v1 * v1;
#pragma unroll
        for (int o = 16; o > 0; o >>= 1) ss += __shfl_xor_sync(0xffffffffu, ss, o);
        float scale = rsqrtf(ss / 64.0f + 1e-6f);
        float* qo = &g_q[(((size_t)b * NHEADS + h) * TSEQ + t) * HDIM];
        qo[l]      = v0 * scale * qhw[l];
        qo[32 + l] = v1 * scale * qhw[32 + l];
    }
    if (w < 2) {
        const int kvh = w;
        float v0 = g_knope[(size_t)n * 64 + kvh * 32 + l];
        const float* kr = &g_krope[(size_t)n * 64 + kvh * 32];
        float a = kr[l];
        float v1 = (l < 16) ? (a * cs - kr[l + 16] * sn) : (a * cs + kr[l - 16] * sn);
        float ss = v0 * v0 + v1 * v1;
#pragma unroll
        for (int o = 16; o > 0; o >>= 1) ss += __shfl_xor_sync(0xffffffffu, ss, o);
        float scale = rsqrtf(ss / 64.0f + 1e-6f);
        float* ko = &g_k[(((size_t)b * NKVH + kvh) * TSEQ + t) * HDIM];
        ko[l]      = v0 * scale * khw[l];
        ko[32 + l] = v1 * scale * khw[32 + l];
    } else if (w < 4) {
        const int kvh = w - 2;
        float* vo = &g_vt[(((size_t)b * NKVH + kvh) * TSEQ + t) * HDIM];
        vo[l]      = g_vv[(size_t)n * 128 + kvh * 64 + l];
        vo[32 + l] = g_vv[(size_t)n * 128 + kvh * 64 + 32 + l];
    }
}

// ---------------- HMMA causal flash attention, BM=128, BN=64, d=64 ----------------
// 8 warps, each owns 16 query rows and the full N=64 width.
// bf16x3 for S = QK^T and O += PV; P fragments taken directly from S accumulators.
#define FS 72
#define FL_QH 0
#define FL_QL 9216
#define FL_KH 18432
#define FL_KL 23040
#define FL_VH 27648
#define FL_VL 32256
#define FL_SMEM (36864 * 2)   /* 73728 bytes */

__global__ __launch_bounds__(256) void flash(const float* __restrict__ vres,
                                             float* __restrict__ attn) {
    __nv_bfloat16* QH = (__nv_bfloat16*)gsm + FL_QH;
    __nv_bfloat16* QL = (__nv_bfloat16*)gsm + FL_QL;
    __nv_bfloat16* KH = (__nv_bfloat16*)gsm + FL_KH;
    __nv_bfloat16* KL = (__nv_bfloat16*)gsm + FL_KL;
    __nv_bfloat16* VH = (__nv_bfloat16*)gsm + FL_VH;
    __nv_bfloat16* VL = (__nv_bfloat16*)gsm + FL_VL;

    const int qt = gridDim.x - 1 - blockIdx.x;   // heavy tiles first
    const int bh = blockIdx.y;
    const int b = bh >> 3, h = bh & 7, kvh = h >> 2;
    const int q0 = qt * 128;

    const int tid = threadIdx.x, wid = tid >> 5, lane = tid & 31;
    const int g = lane >> 2, t = lane & 3;
    const int r0 = wid * 16;

    const float* Qg = &g_q [(((size_t)b * NHEADS + h)  * TSEQ + q0) * HDIM];
    const float* Kg = &g_k [(((size_t)b * NKVH + kvh) * TSEQ) * HDIM];
    const float* Vg = &g_vt[(((size_t)b * NKVH + kvh) * TSEQ) * HDIM];

    // load Q tile 128x64 (hi/lo)
#pragma unroll
    for (int i = tid; i < 2048; i += 256) {
        const int row = i >> 4;
        const int col4 = (i & 15) << 2;
        const float4 av = *(const float4*)&Qg[(size_t)row * HDIM + col4];
        __nv_bfloat16 h0, h1, h2, h3, l0, l1, l2, l3;
        bfsplit(av.x, h0, l0); bfsplit(av.y, h1, l1);
        bfsplit(av.z, h2, l2); bfsplit(av.w, h3, l3);
        *(uint2*)&QH[row * FS + col4] = make_uint2(packbf(h0, h1), packbf(h2, h3));
        *(uint2*)&QL[row * FS + col4] = make_uint2(packbf(l0, l1), packbf(l2, l3));
    }

    float m0 = -INFINITY, m1 = -INFINITY, l0 = 0.f, l1 = 0.f;
    float o[8][4];
#pragma unroll
    for (int j = 0; j < 8; j++)
#pragma unroll
        for (int r = 0; r < 4; r++) o[j][r] = 0.f;

    const int ktmax = 2 * qt + 1;
    for (int kt = 0; kt <= ktmax; kt++) {
        __syncthreads();
        const float* Kt = Kg + (size_t)kt * 64 * HDIM;
        const float* Vt = Vg + (size_t)kt * 64 * HDIM;
#pragma unroll
        for (int i = tid; i < 1024; i += 256) {
            const int kv = i >> 4;
            const int d4 = (i & 15) << 2;
            // K: row-major [kv][d]
            const float4 kvv = *(const float4*)&Kt[(size_t)kv * HDIM + d4];
            __nv_bfloat16 h0, h1, h2, h3, l0_, l1_, l2_, l3_;
            bfsplit(kvv.x, h0, l0_); bfsplit(kvv.y, h1, l1_);
            bfsplit(kvv.z, h2, l2_); bfsplit(kvv.w, h3, l3_);
            *(uint2*)&KH[kv * FS + d4] = make_uint2(packbf(h0, h1), packbf(h2, h3));
            *(uint2*)&KL[kv * FS + d4] = make_uint2(packbf(l0_, l1_), packbf(l2_, l3_));
            // V: transposed [d][kv]
            const float4 vv = *(const float4*)&Vt[(size_t)kv * HDIM + d4];
            const float vals[4] = {vv.x, vv.y, vv.z, vv.w};
#pragma unroll
            for (int u = 0; u < 4; u++) {
                __nv_bfloat16 hh, ll;
                bfsplit(vals[u], hh, ll);
                VH[(d4 + u) * FS + kv] = hh;
                VL[(d4 + u) * FS + kv] = ll;
            }
        }
        __syncthreads();

        // ---- S = Q K^T ----
        float s[8][4];
#pragma unroll
        for (int j = 0; j < 8; j++)
#pragma unroll
            for (int r = 0; r < 4; r++) s[j][r] = 0.f;

#pragma unroll
        for (int kk = 0; kk < 64; kk += 16) {
            uint32_t aH[4], aL[4];
            aH[0] = *(const uint32_t*)&QH[(r0 + g)     * FS + kk + 2 * t];
            aH[1] = *(const uint32_t*)&QH[(r0 + g + 8) * FS + kk + 2 * t];
            aH[2] = *(const uint32_t*)&QH[(r0 + g)     * FS + kk + 8 + 2 * t];
            aH[3] = *(const uint32_t*)&QH[(r0 + g + 8) * FS + kk + 8 + 2 * t];
            aL[0] = *(const uint32_t*)&QL[(r0 + g)     * FS + kk + 2 * t];
            aL[1] = *(const uint32_t*)&QL[(r0 + g + 8) * FS + kk + 2 * t];
            aL[2] = *(const uint32_t*)&QL[(r0 + g)     * FS + kk + 8 + 2 * t];
            aL[3] = *(const uint32_t*)&QL[(r0 + g + 8) * FS + kk + 8 + 2 * t];
#pragma unroll
            for (int j = 0; j < 8; j++) {
                const int n = j * 8 + g;
                uint32_t bH0 = *(const uint32_t*)&KH[n * FS + kk + 2 * t];
                uint32_t bH1 = *(const uint32_t*)&KH[n * FS + kk + 8 + 2 * t];
                uint32_t bL0 = *(const uint32_t*)&KL[n * FS + kk + 2 * t];
                uint32_t bL1 = *(const uint32_t*)&KL[n * FS + kk + 8 + 2 * t];
                mma16816(s[j], aH[0], aH[1], aH[2], aH[3], bH0, bH1);
                mma16816(s[j], aL[0], aL[1], aL[2], aL[3], bH0, bH1);
                mma16816(s[j], aH[0], aH[1], aH[2], aH[3], bL0, bL1);
            }
        }

        // ---- scale + causal mask ----
        const bool diag = (kt >= 2 * qt);
#pragma unroll
        for (int j = 0; j < 8; j++) {
#pragma unroll
            for (int r = 0; r < 4; r++) {
                s[j][r] *= 0.125f;
                if (diag) {
                    const int col = kt * 64 + j * 8 + 2 * t + (r & 1);
                    const int row = q0 + r0 + g + ((r >> 1) << 3);
                    if (col > row) s[j][r] = -INFINITY;
                }
            }
        }

        // ---- online softmax (rows g and g+8; 4-lane t-group shuffles) ----
        float mx0 = -INFINITY, mx1 = -INFINITY;
#pragma unroll
        for (int j = 0; j < 8; j++) {
            mx0 = fmaxf(mx0, fmaxf(s[j][0], s[j][1]));
            mx1 = fmaxf(mx1, fmaxf(s[j][2], s[j][3]));
        }
        mx0 = fmaxf(mx0, __shfl_xor_sync(0xffffffffu, mx0, 1));
        mx0 = fmaxf(mx0, __shfl_xor_sync(0xffffffffu, mx0, 2));
        mx1 = fmaxf(mx1, __shfl_xor_sync(0xffffffffu, mx1, 1));
        mx1 = fmaxf(mx1, __shfl_xor_sync(0xffffffffu, mx1, 2));
        const float mn0 = fmaxf(m0, mx0), mn1 = fmaxf(m1, mx1);
        const float al0 = __expf(m0 - mn0), al1 = __expf(m1 - mn1);
        m0 = mn0; m1 = mn1;
        float rs0 = 0.f, rs1 = 0.f;
#pragma unroll
        for (int j = 0; j < 8; j++) {
            s[j][0] = __expf(s[j][0] - m0);
            s[j][1] = __expf(s[j][1] - m0);
            s[j][2] = __expf(s[j][2] - m1);
            s[j][3] = __expf(s[j][3] - m1);
            rs0 += s[j][0] + s[j][1];
            rs1 += s[j][2] + s[j][3];
        }
        rs0 += __shfl_xor_sync(0xffffffffu, rs0, 1);
        rs0 += __shfl_xor_sync(0xffffffffu, rs0, 2);
        rs1 += __shfl_xor_sync(0xffffffffu, rs1, 1);
        rs1 += __shfl_xor_sync(0xffffffffu, rs1, 2);
        l0 = l0 * al0 + rs0;
        l1 = l1 * al1 + rs1;
#pragma unroll
        for (int j = 0; j < 8; j++) {
            o[j][0] *= al0; o[j][1] *= al0;
            o[j][2] *= al1; o[j][3] *= al1;
        }

        // ---- O += P V  (P fragments directly from s registers) ----
#pragma unroll
        for (int u = 0; u < 4; u++) {
            uint32_t aPh[4], aPl[4];
            {
                __nv_bfloat16 h0, h1, h2, h3, lo0, lo1, lo2, lo3;
                bfsplit(s[2*u][0], h0, lo0);   bfsplit(s[2*u][1], h1, lo1);
                bfsplit(s[2*u][2], h2, lo2);   bfsplit(s[2*u][3], h3, lo3);
                aPh[0] = packbf(h0, h1);  aPl[0] = packbf(lo0, lo1);
                aPh[1] = packbf(h2, h3);  aPl[1] = packbf(lo2, lo3);
                bfsplit(s[2*u+1][0], h0, lo0); bfsplit(s[2*u+1][1], h1, lo1);
                bfsplit(s[2*u+1][2], h2, lo2); bfsplit(s[2*u+1][3], h3, lo3);
                aPh[2] = packbf(h0, h1);  aPl[2] = packbf(lo0, lo1);
                aPh[3] = packbf(h2, h3);  aPl[3] = packbf(lo2, lo3);
            }
#pragma unroll
            for (int j = 0; j < 8; j++) {
                const int n = j * 8 + g;
                uint32_t bH0 = *(const uint32_t*)&VH[n * FS + 16 * u + 2 * t];
                uint32_t bH1 = *(const uint32_t*)&VH[n * FS + 16 * u + 8 + 2 * t];
                uint32_t bL0 = *(const uint32_t*)&VL[n * FS + 16 * u + 2 * t];
                uint32_t bL1 = *(const uint32_t*)&VL[n * FS + 16 * u + 8 + 2 * t];
                mma16816(o[j], aPh[0], aPh[1], aPh[2], aPh[3], bH0, bH1);
                mma16816(o[j], aPl[0], aPl[1], aPl[2], aPl[3], bH0, bH1);
                mma16816(o[j], aPh[0], aPh[1], aPh[2], aPh[3], bL0, bL1);
            }
        }
    }

    // ---- epilogue: normalize, add v_res, write [tok, H*64] ----
    const float inv0 = 1.0f / l0, inv1 = 1.0f / l1;
#pragma unroll
    for (int j = 0; j < 8; j++) {
        const int col = h * 64 + j * 8 + 2 * t;
        {
            const int row = q0 + r0 + g;
            const size_t tok = (size_t)b * TSEQ + row;
            const float2 vr = *(const float2*)&vres[tok * 512 + col];
            *(float2*)&attn[tok * 512 + col] =
                make_float2(o[j][0] * inv0 + vr.x, o[j][1] * inv0 + vr.y);
        }
        {
            const int row = q0 + r0 + g + 8;
            const size_t tok = (size_t)b * TSEQ + row;
            const float2 vr = *(const float2*)&vres[tok * 512 + col];
            *(float2*)&attn[tok * 512 + col] =
                make_float2(o[j][2] * inv1 + vr.x, o[j][3] * inv1 + vr.y);
        }
    }
}

// ---------------- launch ----------------
extern "C" void kernel_launch(void* const* d_in, const int* in_sizes, int n_in,
                              void* d_out, int out_size) {
    const float* x     = (const float*)d_in[0];
    const float* W_DQ  = (const float*)d_in[1];
    const float* W_UQ  = (const float*)d_in[2];
    const float* W_QR  = (const float*)d_in[3];
    const float* W_DKV = (const float*)d_in[4];
    const float* W_UK  = (const float*)d_in[5];
    const float* W_UV  = (const float*)d_in[6];
    const float* W_KR  = (const float*)d_in[7];
    const float* W_VR  = (const float*)d_in[8];
    const float* W_O   = (const float*)d_in[9];
    const float* q_ln  = (const float*)d_in[10];
    const float* kv_ln = (const float*)d_in[11];
    const float* qhw   = (const float*)d_in[12];
    const float* khw   = (const float*)d_in[13];
    float* out = (float*)d_out;

    float *cq, *ckv, *krope, *vres, *qnope, *qrope, *knope, *vv, *attn;
    cudaGetSymbolAddress((void**)&cq,    g_cq);
    cudaGetSymbolAddress((void**)&ckv,   g_ckv);
    cudaGetSymbolAddress((void**)&krope, g_krope);
    cudaGetSymbolAddress((void**)&vres,  g_vres);
    cudaGetSymbolAddress((void**)&qnope, g_qnope);
    cudaGetSymbolAddress((void**)&qrope, g_qrope);
    cudaGetSymbolAddress((void**)&knope, g_knope);
    cudaGetSymbolAddress((void**)&vv,    g_vv);
    cudaGetSymbolAddress((void**)&attn,  g_attn);

    cudaFuncSetAttribute(flash, cudaFuncAttributeMaxDynamicSharedMemorySize, FL_SMEM);
    cudaFuncSetAttribute(hgemm, cudaFuncAttributeMaxDynamicSharedMemorySize, HG_SMEM);

#define GEMM(A, Bm, Cm, Mv, Nv, Kv) \
    hgemm<<<dim3((Nv) / 64, (Mv) / 128), 256, HG_SMEM>>>(A, Bm, Cm, Mv, Nv, Kv)

    // x projections
    GEMM(x, W_DQ,  cq,    NTOK, 256, 512);
    GEMM(x, W_DKV, ckv,   NTOK, 128, 512);
    GEMM(x, W_KR,  krope, NTOK,  64, 512);
    GEMM(x, W_VR,  vres,  NTOK, 512, 512);

    // latent RMS norms
    rms_inplace<<<NTOK, 256>>>(cq,  q_ln,  256);
    rms_inplace<<<NTOK, 128>>>(ckv, kv_ln, 128);

    // up-projections
    GEMM(cq,  W_UQ, qnope, NTOK, 256, 256);
    GEMM(cq,  W_QR, qrope, NTOK, 256, 256);
    GEMM(ckv, W_UK, knope, NTOK,  64, 128);
    GEMM(ckv, W_UV, vv,    NTOK, 128, 128);

    // rope + concat + head-RMS + layout
    assemble<<<NTOK, 256>>>(qhw, khw);

    // causal flash attention + v_res (BM=128)
    flash<<<dim3(TSEQ / 128, BATCH * NHEADS), 256, FL_SMEM>>>(vres, attn);

    // output projection
    GEMM(attn, W_O, out, NTOK, 512, 512);
}

// round 8
// speedup vs baseline: 2.0776x; 1.0872x over previous
#include <cuda_runtime.h>
#include <cuda_bf16.h>
#include <math.h>
#include <stdint.h>

#define NHEADS 8
#define NKVH   2
#define HDIM   64
#define TSEQ   2048
#define BATCH  4
#define NTOK   (BATCH*TSEQ)   /* 8192 */

// ---------------- scratch (device globals; no allocation allowed) ----------------
__device__ float g_cq   [NTOK*256];
__device__ float g_ckv  [NTOK*128];
__device__ float g_krope[NTOK*64];
__device__ float g_vres [NTOK*512];
__device__ float g_qnope[NTOK*256];
__device__ float g_qrope[NTOK*256];
__device__ float g_knope[NTOK*64];
__device__ float g_vv   [NTOK*128];
__device__ float g_attn[NTOK*512];
// bf16 hi/lo pre-split operands for flash
__device__ __nv_bfloat16 g_qh [BATCH*NHEADS*TSEQ*HDIM];
__device__ __nv_bfloat16 g_ql [BATCH*NHEADS*TSEQ*HDIM];
__device__ __nv_bfloat16 g_kh [BATCH*NKVH*TSEQ*HDIM];
__device__ __nv_bfloat16 g_kl [BATCH*NKVH*TSEQ*HDIM];
__device__ __nv_bfloat16 g_vth[BATCH*NKVH*HDIM*TSEQ];   // [b,kvh,d,T] transposed
__device__ __nv_bfloat16 g_vtl[BATCH*NKVH*HDIM*TSEQ];

__device__ __forceinline__ uint32_t packbf(__nv_bfloat16 a, __nv_bfloat16 b) {
    return ((uint32_t)__bfloat16_as_ushort(b) << 16) | (uint32_t)__bfloat16_as_ushort(a);
}
__device__ __forceinline__ void mma16816(float* c, uint32_t a0, uint32_t a1,
                                         uint32_t a2, uint32_t a3,
                                         uint32_t b0, uint32_t b1) {
    asm volatile(
        "mma.sync.aligned.m16n8k16.row.col.f32.bf16.bf16.f32 "
        "{%0,%1,%2,%3}, {%4,%5,%6,%7}, {%8,%9}, {%0,%1,%2,%3};"
        : "+f"(c[0]), "+f"(c[1]), "+f"(c[2]), "+f"(c[3])
        : "r"(a0), "r"(a1), "r"(a2), "r"(a3), "r"(b0), "r"(b1));
}
__device__ __forceinline__ void bfsplit(float v, __nv_bfloat16& h, __nv_bfloat16& l) {
    h = __float2bfloat16(v);
    l = __float2bfloat16(v - __bfloat162float(h));
}
__device__ __forceinline__ uint32_t smem_u32(const void* p) {
    uint32_t a;
    asm("{ .reg .u64 t; cvta.to.shared.u64 t, %1; cvt.u32.u64 %0, t; }" : "=r"(a) : "l"(p));
    return a;
}
__device__ __forceinline__ void cpa16(uint32_t dst, const void* src) {
    asm volatile("cp.async.ca.shared.global [%0], [%1], 16;" :: "r"(dst), "l"(src) : "memory");
}
#define CP_COMMIT() asm volatile("cp.async.commit_group;" ::: "memory")
#define CP_WAIT0()  asm volatile("cp.async.wait_group 0;" ::: "memory")
#define CP_WAIT1()  asm volatile("cp.async.wait_group 1;" ::: "memory")

// ---------------- bf16x3 HMMA GEMM: C[M,N] = A[M,K] @ B[K,N] ----------------
#define SA 72
#define SB 72
#define HG_AH   0
#define HG_AL   18432
#define HG_BH   36864
#define HG_BL   46080
#define HG_SMEM 55296

extern __shared__ char gsm[];
__global__ __launch_bounds__(256) void hgemm(const float* __restrict__ A,
                                             const float* __restrict__ B,
                                             float* __restrict__ C,
                                             int M, int N, int K) {
    __nv_bfloat16* AsH = (__nv_bfloat16*)(gsm + HG_AH);
    __nv_bfloat16* AsL = (__nv_bfloat16*)(gsm + HG_AL);
    __nv_bfloat16* BsH = (__nv_bfloat16*)(gsm + HG_BH);
    __nv_bfloat16* BsL = (__nv_bfloat16*)(gsm + HG_BL);

    const int tid = threadIdx.x, wid = tid >> 5, lane = tid & 31;
    const int wm = wid & 3, wn = wid >> 2;
    const int g = lane >> 2, t = lane & 3;
    const int m0 = blockIdx.y * 128, n0 = blockIdx.x * 64;

    float acc[2][4][4];
#pragma unroll
    for (int i = 0; i < 2; i++)
#pragma unroll
        for (int j = 0; j < 4; j++)
#pragma unroll
            for (int r = 0; r < 4; r++) acc[i][j][r] = 0.f;

    const int nch = K >> 6;
    for (int c = 0; c < nch; c++) {
        if (c > 0) __syncthreads();
        const int c64 = c << 6;
#pragma unroll
        for (int i = tid; i < 2048; i += 256) {
            const int row = i >> 4;
            const int col4 = (i & 15) << 2;
            const float4 av = *(const float4*)&A[(size_t)(m0 + row) * K + c64 + col4];
            __nv_bfloat16 h0, h1, h2, h3, l0, l1, l2, l3;
            bfsplit(av.x, h0, l0); bfsplit(av.y, h1, l1);
            bfsplit(av.z, h2, l2); bfsplit(av.w, h3, l3);
            *(uint2*)&AsH[row * SA + col4] = make_uint2(packbf(h0, h1), packbf(h2, h3));
            *(uint2*)&AsL[row * SA + col4] = make_uint2(packbf(l0, l1), packbf(l2, l3));
        }
#pragma unroll
        for (int i = tid; i < 1024; i += 256) {
            const int k = i >> 4;
            const int n4 = (i & 15) << 2;
            const float4 bv = *(const float4*)&B[(size_t)(c64 + k) * N + n0 + n4];
            const float vals[4] = {bv.x, bv.y, bv.z, bv.w};
#pragma unroll
            for (int j = 0; j < 4; j++) {
                __nv_bfloat16 h, l;
                bfsplit(vals[j], h, l);
                BsH[(n4 + j) * SB + k] = h;
                BsL[(n4 + j) * SB + k] = l;
            }
        }
        __syncthreads();

#pragma unroll
        for (int kk = 0; kk < 64; kk += 16) {
            uint32_t ah[2][4], al[2][4], bh[4][2], bl[4][2];
#pragma unroll
            for (int i = 0; i < 2; i++) {
                const int r0 = wm * 32 + i * 16 + g;
                ah[i][0] = *(const uint32_t*)&AsH[(r0)     * SA + kk + 2 * t];
                ah[i][1] = *(const uint32_t*)&AsH[(r0 + 8) * SA + kk + 2 * t];
                ah[i][2] = *(const uint32_t*)&AsH[(r0)     * SA + kk + 8 + 2 * t];
                ah[i][3] = *(const uint32_t*)&AsH[(r0 + 8) * SA + kk + 8 + 2 * t];
                al[i][0] = *(const uint32_t*)&AsL[(r0)     * SA + kk + 2 * t];
                al[i][1] = *(const uint32_t*)&AsL[(r0 + 8) * SA + kk + 2 * t];
                al[i][2] = *(const uint32_t*)&AsL[(r0)     * SA + kk + 8 + 2 * t];
                al[i][3] = *(const uint32_t*)&AsL[(r0 + 8) * SA + kk + 8 + 2 * t];
            }
#pragma unroll
            for (int j = 0; j < 4; j++) {
                const int n = wn * 32 + j * 8 + g;
                bh[j][0] = *(const uint32_t*)&BsH[n * SB + kk + 2 * t];
                bh[j][1] = *(const uint32_t*)&BsH[n * SB + kk + 8 + 2 * t];
                bl[j][0] = *(const uint32_t*)&BsL[n * SB + kk + 2 * t];
                bl[j][1] = *(const uint32_t*)&BsL[n * SB + kk + 8 + 2 * t];
            }
#pragma unroll
            for (int i = 0; i < 2; i++)
#pragma unroll
                for (int j = 0; j < 4; j++) {
                    mma16816(acc[i][j], ah[i][0], ah[i][1], ah[i][2], ah[i][3], bh[j][0], bh[j][1]);
                    mma16816(acc[i][j], al[i][0], al[i][1], al[i][2], al[i][3], bh[j][0], bh[j][1]);
                    mma16816(acc[i][j], ah[i][0], ah[i][1], ah[i][2], ah[i][3], bl[j][0], bl[j][1]);
                }
        }
    }

#pragma unroll
    for (int i = 0; i < 2; i++)
#pragma unroll
        for (int j = 0; j < 4; j++) {
            const int row = m0 + wm * 32 + i * 16 + g;
            const int col = n0 + wn * 32 + j * 8 + 2 * t;
            *(float2*)&C[(size_t)row * N + col]       = make_float2(acc[i][j][0], acc[i][j][1]);
            *(float2*)&C[(size_t)(row + 8) * N + col] = make_float2(acc[i][j][2], acc[i][j][3]);
        }
}

// ---------------- in-place RMSNorm over last dim D (blockDim == D) ----------------
__global__ void rms_inplace(float* __restrict__ X, const float* __restrict__ w, int D) {
    const int n = blockIdx.x;
    float* row = X + (size_t)n * D;
    const int tid = threadIdx.x;
    float v = row[tid];
    float ss = v * v;
#pragma unroll
    for (int o = 16; o > 0; o >>= 1) ss += __shfl_xor_sync(0xffffffffu, ss, o);
    __shared__ float sh[8];
    const int wid = tid >> 5, nw = blockDim.x >> 5;
    if ((tid & 31) == 0) sh[wid] = ss;
    __syncthreads();
    float tot = 0.f;
    for (int i = 0; i < nw; i++) tot += sh[i];
    float scale = rsqrtf(tot / (float)D + 1e-6f);
    row[tid] = v * scale * w[tid];
}

// ---------------- RoPE + concat + per-head RMS -> bf16 hi/lo [B,h,T,64] ----------------
__global__ __launch_bounds__(256) void assemble(const float* __restrict__ qhw,
                                                const float* __restrict__ khw) {
    const int n = blockIdx.x;
    const int b = n / TSEQ, t = n % TSEQ;
    const int tid = threadIdx.x, w = tid >> 5, l = tid & 31;

    const int j = l & 15;
    const float invf = powf(500000.0f, -(float)j / 16.0f);
    const float f = (float)t * invf;
    const float cs = cosf(f), sn = sinf(f);

    {
        const int h = w;
        float v0 = g_qnope[(size_t)n * 256 + h * 32 + l];
        const float* qr = &g_qrope[(size_t)n * 256 + h * 32];
        float a = qr[l];
        float v1 = (l < 16) ? (a * cs - qr[l + 16] * sn) : (a * cs + qr[l - 16] * sn);
        float ss = v0 * v0 + v1 * v1;
#pragma unroll
        for (int o = 16; o > 0; o >>= 1) ss += __shfl_xor_sync(0xffffffffu, ss, o);
        float scale = rsqrtf(ss / 64.0f + 1e-6f);
        const size_t base = (((size_t)b * NHEADS + h) * TSEQ + t) * HDIM;
        __nv_bfloat16 hh, ll;
        bfsplit(v0 * scale * qhw[l], hh, ll);
        g_qh[base + l] = hh; g_ql[base + l] = ll;
        bfsplit(v1 * scale * qhw[32 + l], hh, ll);
        g_qh[base + 32 + l] = hh; g_ql[base + 32 + l] = ll;
    }
    if (w < 2) {
        const int kvh = w;
        float v0 = g_knope[(size_t)n * 64 + kvh * 32 + l];
        const float* kr = &g_krope[(size_t)n * 64 + kvh * 32];
        float a = kr[l];
        float v1 = (l < 16) ? (a * cs - kr[l + 16] * sn) : (a * cs + kr[l - 16] * sn);
        float ss = v0 * v0 + v1 * v1;
#pragma unroll
        for (int o = 16; o > 0; o >>= 1) ss += __shfl_xor_sync(0xffffffffu, ss, o);
        float scale = rsqrtf(ss / 64.0f + 1e-6f);
        const size_t base = (((size_t)b * NKVH + kvh) * TSEQ + t) * HDIM;
        __nv_bfloat16 hh, ll;
        bfsplit(v0 * scale * khw[l], hh, ll);
        g_kh[base + l] = hh; g_kl[base + l] = ll;
        bfsplit(v1 * scale * khw[32 + l], hh, ll);
        g_kh[base + 32 + l] = hh; g_kl[base + 32 + l] = ll;
    }
}

// ---------------- V: fp32 [tok, kvh*64+d] -> bf16 hi/lo transposed [b,kvh,d,T] ----------------
__global__ __launch_bounds__(256) void vtrans() {
    __shared__ __nv_bfloat16 sh[64][65], sl[64][65];
    const int bk = blockIdx.x;            // b*NKVH + kvh
    const int b = bk >> 1, kvh = bk & 1;
    const int t0 = blockIdx.y * 64;
    const int tid = threadIdx.x;
    for (int i = tid; i < 4096; i += 256) {
        const int tt = i >> 6, d = i & 63;
        float v = g_vv[(size_t)(b * TSEQ + t0 + tt) * 128 + kvh * 64 + d];
        __nv_bfloat16 hh, ll;
        bfsplit(v, hh, ll);
        sh[tt][d] = hh; sl[tt][d] = ll;
    }
    __syncthreads();
    for (int i = tid; i < 4096; i += 256) {
        const int d = i >> 6, tt = i & 63;
        g_vth[((size_t)bk * 64 + d) * TSEQ + t0 + tt] = sh[tt][d];
        g_vtl[((size_t)bk * 64 + d) * TSEQ + t0 + tt] = sl[tt][d];
    }
}

// ---------------- HMMA causal flash attention, BM=128, BN=64, d=64 ----------------
// bf16 hi/lo operands pre-split in GMEM; cp.async double-buffered K/V tiles.
#define FS 72
#define FQH 0
#define FQL 9216
#define FSTG 18432      /* first stage base, elems */
#define FSTGSZ 18432    /* per-stage elems: KH,KL,VH,VL x 4608 */
#define FL_SMEM ((FSTG + 2 * FSTGSZ) * 2)   /* 110592 bytes */

__device__ __forceinline__ void flash_prefetch(uint32_t sb, int stage, int kt, int tid,
        const __nv_bfloat16* Khb, const __nv_bfloat16* Klb,
        const __nv_bfloat16* Vthb, const __nv_bfloat16* Vtlb) {
    const int base = FSTG + stage * FSTGSZ;
#pragma unroll
    for (int i = tid; i < 2048; i += 256) {
        const int arr = i >> 9;          // 0 KH, 1 KL, 2 VH, 3 VL
        const int r = (i >> 3) & 63;
        const int c = i & 7;
        const uint32_t dst = sb + (uint32_t)(base + arr * 4608 + r * FS + c * 8) * 2;
        const __nv_bfloat16* src;
        if (arr == 0)      src = Khb + ((size_t)(kt * 64 + r)) * 64 + c * 8;
        else if (arr == 1) src = Klb + ((size_t)(kt * 64 + r)) * 64 + c * 8;
        else if (arr == 2) src = Vthb + (size_t)r * TSEQ + kt * 64 + c * 8;
        else               src = Vtlb + (size_t)r * TSEQ + kt * 64 + c * 8;
        cpa16(dst, src);
    }
}

__global__ __launch_bounds__(256) void flash(const float* __restrict__ vres,
                                             float* __restrict__ attn) {
    __nv_bfloat16* sm = (__nv_bfloat16*)gsm;
    const uint32_t sb = smem_u32(gsm);

    const int qt = gridDim.x - 1 - blockIdx.x;   // heavy tiles first
    const int bh = blockIdx.y;
    const int b = bh >> 3, h = bh & 7, kvh = h >> 2;
    const int q0 = qt * 128;

    const int tid = threadIdx.x, wid = tid >> 5, lane = tid & 31;
    const int g = lane >> 2, t = lane & 3;
    const int r0 = wid * 16;

    const __nv_bfloat16* Qhb = &g_qh[(((size_t)b * NHEADS + h) * TSEQ + q0) * HDIM];
    const __nv_bfloat16* Qlb = &g_ql[(((size_t)b * NHEADS + h) * TSEQ + q0) * HDIM];
    const __nv_bfloat16* Khb = &g_kh[(((size_t)b * NKVH + kvh) * TSEQ) * HDIM];
    const __nv_bfloat16* Klb = &g_kl[(((size_t)b * NKVH + kvh) * TSEQ) * HDIM];
    const __nv_bfloat16* Vthb = &g_vth[(((size_t)b * NKVH + kvh) * HDIM) * TSEQ];
    const __nv_bfloat16* Vtlb = &g_vtl[(((size_t)b * NKVH + kvh) * HDIM) * TSEQ];

    // prefetch Q (hi+lo) and tile 0 in one group
#pragma unroll
    for (int i = tid; i < 2048; i += 256) {
        const int half = i >> 10;
        const int r = (i >> 3) & 127;
        const int c = i & 7;
        const uint32_t dst = sb + (uint32_t)((half ? FQL : FQH) + r * FS + c * 8) * 2;
        const __nv_bfloat16* src = (half ? Qlb : Qhb) + (size_t)r * 64 + c * 8;
        cpa16(dst, src);
    }
    flash_prefetch(sb, 0, 0, tid, Khb, Klb, Vthb, Vtlb);
    CP_COMMIT();

    float m0 = -INFINITY, m1 = -INFINITY, l0 = 0.f, l1 = 0.f;
    float o[8][4];
#pragma unroll
    for (int j = 0; j < 8; j++)
#pragma unroll
        for (int r = 0; r < 4; r++) o[j][r] = 0.f;

    const int ktmax = 2 * qt + 1;
    for (int kt = 0; kt <= ktmax; kt++) {
        const int st = kt & 1;
        if (kt < ktmax) {
            flash_prefetch(sb, st ^ 1, kt + 1, tid, Khb, Klb, Vthb, Vtlb);
            CP_COMMIT();
            CP_WAIT1();
        } else {
            CP_WAIT0();
        }
        __syncthreads();

        __nv_bfloat16* KH = sm + FSTG + st * FSTGSZ;
        __nv_bfloat16* KL = KH + 4608;
        __nv_bfloat16* VH = KH + 9216;
        __nv_bfloat16* VL = KH + 13824;
        __nv_bfloat16* QH = sm + FQH;
        __nv_bfloat16* QL = sm + FQL;

        // ---- S = Q K^T ----
        float s[8][4];
#pragma unroll
        for (int j = 0; j < 8; j++)
#pragma unroll
            for (int r = 0; r < 4; r++) s[j][r] = 0.f;

#pragma unroll
        for (int kk = 0; kk < 64; kk += 16) {
            uint32_t aH[4], aL[4];
            aH[0] = *(const uint32_t*)&QH[(r0 + g)     * FS + kk + 2 * t];
            aH[1] = *(const uint32_t*)&QH[(r0 + g + 8) * FS + kk + 2 * t];
            aH[2] = *(const uint32_t*)&QH[(r0 + g)     * FS + kk + 8 + 2 * t];
            aH[3] = *(const uint32_t*)&QH[(r0 + g + 8) * FS + kk + 8 + 2 * t];
            aL[0] = *(const uint32_t*)&QL[(r0 + g)     * FS + kk + 2 * t];
            aL[1] = *(const uint32_t*)&QL[(r0 + g + 8) * FS + kk + 2 * t];
            aL[2] = *(const uint32_t*)&QL[(r0 + g)     * FS + kk + 8 + 2 * t];
            aL[3] = *(const uint32_t*)&QL[(r0 + g + 8) * FS + kk + 8 + 2 * t];
#pragma unroll
            for (int j = 0; j < 8; j++) {
                const int n = j * 8 + g;
                uint32_t bH0 = *(const uint32_t*)&KH[n * FS + kk + 2 * t];
                uint32_t bH1 = *(const uint32_t*)&KH[n * FS + kk + 8 + 2 * t];
                uint32_t bL0 = *(const uint32_t*)&KL[n * FS + kk + 2 * t];
                uint32_t bL1 = *(const uint32_t*)&KL[n * FS + kk + 8 + 2 * t];
                mma16816(s[j], aH[0], aH[1], aH[2], aH[3], bH0, bH1);
                mma16816(s[j], aL[0], aL[1], aL[2], aL[3], bH0, bH1);
                mma16816(s[j], aH[0], aH[1], aH[2], aH[3], bL0, bL1);
            }
        }

        // ---- scale + causal mask ----
        const bool diag = (kt >= 2 * qt);
#pragma unroll
        for (int j = 0; j < 8; j++) {
#pragma unroll
            for (int r = 0; r < 4; r++) {
                s[j][r] *= 0.125f;
                if (diag) {
                    const int col = kt * 64 + j * 8 + 2 * t + (r & 1);
                    const int row = q0 + r0 + g + ((r >> 1) << 3);
                    if (col > row) s[j][r] = -INFINITY;
                }
            }
        }

        // ---- online softmax (rows g and g+8; 4-lane t-group shuffles) ----
        float mx0 = -INFINITY, mx1 = -INFINITY;
#pragma unroll
        for (int j = 0; j < 8; j++) {
            mx0 = fmaxf(mx0, fmaxf(s[j][0], s[j][1]));
            mx1 = fmaxf(mx1, fmaxf(s[j][2], s[j][3]));
        }
        mx0 = fmaxf(mx0, __shfl_xor_sync(0xffffffffu, mx0, 1));
        mx0 = fmaxf(mx0, __shfl_xor_sync(0xffffffffu, mx0, 2));
        mx1 = fmaxf(mx1, __shfl_xor_sync(0xffffffffu, mx1, 1));
        mx1 = fmaxf(mx1, __shfl_xor_sync(0xffffffffu, mx1, 2));
        const float mn0 = fmaxf(m0, mx0), mn1 = fmaxf(m1, mx1);
        const float al0 = __expf(m0 - mn0), al1 = __expf(m1 - mn1);
        m0 = mn0; m1 = mn1;
        float rs0 = 0.f, rs1 = 0.f;
#pragma unroll
        for (int j = 0; j < 8; j++) {
            s[j][0] = __expf(s[j][0] - m0);
            s[j][1] = __expf(s[j][1] - m0);
            s[j][2] = __expf(s[j][2] - m1);
            s[j][3] = __expf(s[j][3] - m1);
            rs0 += s[j][0] + s[j][1];
            rs1 += s[j][2] + s[j][3];
        }
        rs0 += __shfl_xor_sync(0xffffffffu, rs0, 1);
        rs0 += __shfl_xor_sync(0xffffffffu, rs0, 2);
        rs1 += __shfl_xor_sync(0xffffffffu, rs1, 1);
        rs1 += __shfl_xor_sync(0xffffffffu, rs1, 2);
        l0 = l0 * al0 + rs0;
        l1 = l1 * al1 + rs1;
#pragma unroll
        for (int j = 0; j < 8; j++) {
            o[j][0] *= al0; o[j][1] *= al0;
            o[j][2] *= al1; o[j][3] *= al1;
        }

        // ---- O += P V  (P fragments directly from s registers) ----
#pragma unroll
        for (int u = 0; u < 4; u++) {
            uint32_t aPh[4], aPl[4];
            {
                __nv_bfloat16 h0, h1, h2, h3, lo0, lo1, lo2, lo3;
                bfsplit(s[2*u][0], h0, lo0);   bfsplit(s[2*u][1], h1, lo1);
                bfsplit(s[2*u][2], h2, lo2);   bfsplit(s[2*u][3], h3, lo3);
                aPh[0] = packbf(h0, h1);  aPl[0] = packbf(lo0, lo1);
                aPh[1] = packbf(h2, h3);  aPl[1] = packbf(lo2, lo3);
                bfsplit(s[2*u+1][0], h0, lo0); bfsplit(s[2*u+1][1], h1, lo1);
                bfsplit(s[2*u+1][2], h2, lo2); bfsplit(s[2*u+1][3], h3, lo3);
                aPh[2] = packbf(h0, h1);  aPl[2] = packbf(lo0, lo1);
                aPh[3] = packbf(h2, h3);  aPl[3] = packbf(lo2, lo3);
            }
#pragma unroll
            for (int j = 0; j < 8; j++) {
                const int n = j * 8 + g;
                uint32_t bH0 = *(const uint32_t*)&VH[n * FS + 16 * u + 2 * t];
                uint32_t bH1 = *(const uint32_t*)&VH[n * FS + 16 * u + 8 + 2 * t];
                uint32_t bL0 = *(const uint32_t*)&VL[n * FS + 16 * u + 2 * t];
                uint32_t bL1 = *(const uint32_t*)&VL[n * FS + 16 * u + 8 + 2 * t];
                mma16816(o[j], aPh[0], aPh[1], aPh[2], aPh[3], bH0, bH1);
                mma16816(o[j], aPl[0], aPl[1], aPl[2], aPl[3], bH0, bH1);
                mma16816(o[j], aPh[0], aPh[1], aPh[2], aPh[3], bL0, bL1);
            }
        }
        __syncthreads();
    }

    // ---- epilogue: normalize, add v_res, write [tok, H*64] ----
    const float inv0 = 1.0f / l0, inv1 = 1.0f / l1;
#pragma unroll
    for (int j = 0; j < 8; j++) {
        const int col = h * 64 + j * 8 + 2 * t;
        {
            const int row = q0 + r0 + g;
            const size_t tok = (size_t)b * TSEQ + row;
            const float2 vr = *(const float2*)&vres[tok * 512 + col];
            *(float2*)&attn[tok * 512 + col] =
                make_float2(o[j][0] * inv0 + vr.x, o[j][1] * inv0 + vr.y);
        }
        {
            const int row = q0 + r0 + g + 8;
            const size_t tok = (size_t)b * TSEQ + row;
            const float2 vr = *(const float2*)&vres[tok * 512 + col];
            *(float2*)&attn[tok * 512 + col] =
                make_float2(o[j][2] * inv1 + vr.x, o[j][3] * inv1 + vr.y);
        }
    }
}

// ---------------- launch ----------------
extern "C" void kernel_launch(void* const* d_in, const int* in_sizes, int n_in,
                              void* d_out, int out_size) {
    const float* x     = (const float*)d_in[0];
    const float* W_DQ  = (const float*)d_in[1];
    const float* W_UQ  = (const float*)d_in[2];
    const float* W_QR  = (const float*)d_in[3];
    const float* W_DKV = (const float*)d_in[4];
    const float* W_UK  = (const float*)d_in[5];
    const float* W_UV  = (const float*)d_in[6];
    const float* W_KR  = (const float*)d_in[7];
    const float* W_VR  = (const float*)d_in[8];
    const float* W_O   = (const float*)d_in[9];
    const float* q_ln  = (const float*)d_in[10];
    const float* kv_ln = (const float*)d_in[11];
    const float* qhw   = (const float*)d_in[12];
    const float* khw   = (const float*)d_in[13];
    float* out = (float*)d_out;

    float *cq, *ckv, *krope, *vres, *qnope, *qrope, *knope, *vv, *attn;
    cudaGetSymbolAddress((void**)&cq,    g_cq);
    cudaGetSymbolAddress((void**)&ckv,   g_ckv);
    cudaGetSymbolAddress((void**)&krope, g_krope);
    cudaGetSymbolAddress((void**)&vres,  g_vres);
    cudaGetSymbolAddress((void**)&qnope, g_qnope);
    cudaGetSymbolAddress((void**)&qrope, g_qrope);
    cudaGetSymbolAddress((void**)&knope, g_knope);
    cudaGetSymbolAddress((void**)&vv,    g_vv);
    cudaGetSymbolAddress((void**)&attn,  g_attn);

    cudaFuncSetAttribute(flash, cudaFuncAttributeMaxDynamicSharedMemorySize, FL_SMEM);
    cudaFuncSetAttribute(hgemm, cudaFuncAttributeMaxDynamicSharedMemorySize, HG_SMEM);

#define GEMM(A, Bm, Cm, Mv, Nv, Kv) \
    hgemm<<<dim3((Nv) / 64, (Mv) / 128), 256, HG_SMEM>>>(A, Bm, Cm, Mv, Nv, Kv)

    // x projections
    GEMM(x, W_DQ,  cq,    NTOK, 256, 512);
    GEMM(x, W_DKV, ckv,   NTOK, 128, 512);
    GEMM(x, W_KR,  krope, NTOK,  64, 512);
    GEMM(x, W_VR,  vres,  NTOK, 512, 512);

    // latent RMS norms
    rms_inplace<<<NTOK, 256>>>(cq,  q_ln,  256);
    rms_inplace<<<NTOK, 128>>>(ckv, kv_ln, 128);

    // up-projections
    GEMM(cq,  W_UQ, qnope, NTOK, 256, 256);
    GEMM(cq,  W_QR, qrope, NTOK, 256, 256);
    GEMM(ckv, W_UK, knope, NTOK,  64, 128);
    GEMM(ckv, W_UV, vv,    NTOK, 128, 128);

    // rope + concat + head-RMS + bf16 split; V transpose+split
    assemble<<<NTOK, 256>>>(qhw, khw);
    vtrans<<<dim3(BATCH * NKVH, TSEQ / 64), 256>>>();

    // causal flash attention + v_res (BM=128, cp.async double-buffered)
    flash<<<dim3(TSEQ / 128, BATCH * NHEADS), 256, FL_SMEM>>>(vres, attn);

    // output projection
    GEMM(attn, W_O, out, NTOK, 512, 512);
}

// round 10
// speedup vs baseline: 2.4051x; 1.1576x over previous
#include <cuda_runtime.h>
#include <cuda_bf16.h>
#include <math.h>
#include <stdint.h>

#define NHEADS 8
#define NKVH   2
#define HDIM   64
#define TSEQ   2048
#define BATCH  4
#define NTOK   (BATCH*TSEQ)   /* 8192 */

// ---------------- scratch (device globals; no allocation allowed) ----------------
__device__ float g_cq   [NTOK*256];
__device__ float g_ckv  [NTOK*128];
__device__ float g_krope[NTOK*64];
__device__ float g_vres [NTOK*512];
__device__ float g_qnope[NTOK*256];
__device__ float g_qrope[NTOK*256];
__device__ float g_knope[NTOK*64];
__device__ float g_vv   [NTOK*128];
// pre-split bf16 hi/lo activations
__device__ __nv_bfloat16 g_xh  [NTOK*512], g_xl  [NTOK*512];
__device__ __nv_bfloat16 g_cqh [NTOK*256], g_cql [NTOK*256];
__device__ __nv_bfloat16 g_ckvh[NTOK*128], g_ckvl[NTOK*128];
__device__ __nv_bfloat16 g_ath [NTOK*512], g_atl [NTOK*512];
// pre-split, pre-transposed [N,K] weights
__device__ __nv_bfloat16 g_wdqh [256*512], g_wdql [256*512];
__device__ __nv_bfloat16 g_wuqh [256*256], g_wuql [256*256];
__device__ __nv_bfloat16 g_wqrh [256*256], g_wqrl [256*256];
__device__ __nv_bfloat16 g_wdkvh[128*512], g_wdkvl[128*512];
__device__ __nv_bfloat16 g_wukh [64*128],  g_wukl [64*128];
__device__ __nv_bfloat16 g_wuvh [128*128], g_wuvl [128*128];
__device__ __nv_bfloat16 g_wkrh [64*512],  g_wkrl [64*512];
__device__ __nv_bfloat16 g_wvrh [512*512], g_wvrl [512*512];
__device__ __nv_bfloat16 g_woh  [512*512], g_wol  [512*512];
// flash operands
__device__ __nv_bfloat16 g_qh [BATCH*NHEADS*TSEQ*HDIM];
__device__ __nv_bfloat16 g_ql [BATCH*NHEADS*TSEQ*HDIM];
__device__ __nv_bfloat16 g_kh [BATCH*NKVH*TSEQ*HDIM];
__device__ __nv_bfloat16 g_kl [BATCH*NKVH*TSEQ*HDIM];
__device__ __nv_bfloat16 g_vth[BATCH*NKVH*HDIM*TSEQ];
__device__ __nv_bfloat16 g_vtl[BATCH*NKVH*HDIM*TSEQ];

__device__ __forceinline__ uint32_t packbf(__nv_bfloat16 a, __nv_bfloat16 b) {
    return ((uint32_t)__bfloat16_as_ushort(b) << 16) | (uint32_t)__bfloat16_as_ushort(a);
}
__device__ __forceinline__ void mma16816(float* c, uint32_t a0, uint32_t a1,
                                         uint32_t a2, uint32_t a3,
                                         uint32_t b0, uint32_t b1) {
    asm volatile(
        "mma.sync.aligned.m16n8k16.row.col.f32.bf16.bf16.f32 "
        "{%0,%1,%2,%3}, {%4,%5,%6,%7}, {%8,%9}, {%0,%1,%2,%3};"
        : "+f"(c[0]), "+f"(c[1]), "+f"(c[2]), "+f"(c[3])
        : "r"(a0), "r"(a1), "r"(a2), "r"(a3), "r"(b0), "r"(b1));
}
__device__ __forceinline__ void bfsplit(float v, __nv_bfloat16& h, __nv_bfloat16& l) {
    h = __float2bfloat16(v);
    l = __float2bfloat16(v - __bfloat162float(h));
}
__device__ __forceinline__ uint32_t smem_u32(const void* p) {
    uint32_t a;
    asm("{ .reg .u64 t; cvta.to.shared.u64 t, %1; cvt.u32.u64 %0, t; }" : "=r"(a) : "l"(p));
    return a;
}
__device__ __forceinline__ void cpa16(uint32_t dst, const void* src) {
    asm volatile("cp.async.ca.shared.global [%0], [%1], 16;" :: "r"(dst), "l"(src) : "memory");
}
#define CP_COMMIT() asm volatile("cp.async.commit_group;" ::: "memory")
#define CP_WAIT0()  asm volatile("cp.async.wait_group 0;" ::: "memory")
#define CP_WAIT1()  asm volatile("cp.async.wait_group 1;" ::: "memory")

// ---------------- split helpers ----------------
// row-major fp32 -> bf16 hi/lo (no transpose); n4 = nelem/4
__global__ void asplit(const float* __restrict__ X, __nv_bfloat16* __restrict__ Xh,
                       __nv_bfloat16* __restrict__ Xl, int n4) {
    const int i = blockIdx.x * blockDim.x + threadIdx.x;
    if (i >= n4) return;
    const float4 v = ((const float4*)X)[i];
    __nv_bfloat16 h0, h1, h2, h3, l0, l1, l2, l3;
    bfsplit(v.x, h0, l0); bfsplit(v.y, h1, l1);
    bfsplit(v.z, h2, l2); bfsplit(v.w, h3, l3);
    ((uint2*)Xh)[i] = make_uint2(packbf(h0, h1), packbf(h2, h3));
    ((uint2*)Xl)[i] = make_uint2(packbf(l0, l1), packbf(l2, l3));
}

// W [K,N] fp32 -> Wh/Wl [N,K] bf16 (transpose + split). K,N multiples of 32.
__global__ void wsplit_t(const float* __restrict__ W, __nv_bfloat16* __restrict__ Wh,
                         __nv_bfloat16* __restrict__ Wl, int K, int N) {
    __shared__ float tile[32][33];
    const int k0 = blockIdx.y * 32, n0 = blockIdx.x * 32;
    const int tid = threadIdx.x;
    for (int i = tid; i < 1024; i += 256) {
        const int r = i >> 5, c = i & 31;
        tile[r][c] = W[(size_t)(k0 + r) * N + n0 + c];
    }
    __syncthreads();
    for (int i = tid; i < 1024; i += 256) {
        const int n = i >> 5, k = i & 31;
        __nv_bfloat16 h, l;
        bfsplit(tile[k][n], h, l);
        Wh[(size_t)(n0 + n) * K + k0 + k] = h;
        Wl[(size_t)(n0 + n) * K + k0 + k] = l;
    }
}

// RMSNorm (blockDim == D) -> bf16 hi/lo split output
__global__ void rms_split(const float* __restrict__ X, const float* __restrict__ w,
                          __nv_bfloat16* __restrict__ Xh, __nv_bfloat16* __restrict__ Xl,
                          int D) {
    const int n = blockIdx.x;
    const float* row = X + (size_t)n * D;
    const int tid = threadIdx.x;
    const float v = row[tid];
    float ss = v * v;
#pragma unroll
    for (int o = 16; o > 0; o >>= 1) ss += __shfl_xor_sync(0xffffffffu, ss, o);
    __shared__ float sh[8];
    const int wid = tid >> 5, nw = blockDim.x >> 5;
    if ((tid & 31) == 0) sh[wid] = ss;
    __syncthreads();
    float tot = 0.f;
    for (int i = 0; i < nw; i++) tot += sh[i];
    const float scale = rsqrtf(tot / (float)D + 1e-6f);
    __nv_bfloat16 h, l;
    bfsplit(v * scale * w[tid], h, l);
    Xh[(size_t)n * D + tid] = h;
    Xl[(size_t)n * D + tid] = l;
}

// ---------------- bf16x3 HMMA GEMM, pre-split operands, cp.async double-buffered ----
// A: [M,K] bf16 h/l; B: [N,K] bf16 h/l (pre-transposed); C: fp32 [M,N].
// Block 128x64, 8 warps (4m x 2n), K-chunks of 64.
#define GS 72
#define GB_AH 0
#define GB_AL 9216
#define GB_BH 18432
#define GB_BL 23040
#define GB_STG 27648                    /* elems per stage */
#define GB_SMEM (2 * GB_STG * 2)        /* 110592 bytes */

extern __shared__ char gsm[];

__device__ __forceinline__ void gemm_prefetch(uint32_t sb, int stage, int c64, int tid,
        const __nv_bfloat16* Ah, const __nv_bfloat16* Al,
        const __nv_bfloat16* Bh, const __nv_bfloat16* Bl,
        int m0, int n0, int K) {
    const int base = stage * GB_STG;
#pragma unroll
    for (int i = tid; i < 2048; i += 256) {
        const int half = i >> 10;            // 0: AH, 1: AL
        const int r = (i >> 3) & 127;
        const int cc = i & 7;
        const uint32_t dst = sb + (uint32_t)(base + (half ? GB_AL : GB_AH) + r * GS + cc * 8) * 2;
        const __nv_bfloat16* src = (half ? Al : Ah) + (size_t)(m0 + r) * K + c64 + cc * 8;
        cpa16(dst, src);
    }
#pragma unroll
    for (int i = tid; i < 1024; i += 256) {
        const int half = i >> 9;             // 0: BH, 1: BL
        const int r = (i >> 3) & 63;
        const int cc = i & 7;
        const uint32_t dst = sb + (uint32_t)(base + (half ? GB_BL : GB_BH) + r * GS + cc * 8) * 2;
        const __nv_bfloat16* src = (half ? Bl : Bh) + (size_t)(n0 + r) * K + c64 + cc * 8;
        cpa16(dst, src);
    }
}

__global__ __launch_bounds__(256) void hgemm_bs(
        const __nv_bfloat16* __restrict__ Ah, const __nv_bfloat16* __restrict__ Al,
        const __nv_bfloat16* __restrict__ Bh, const __nv_bfloat16* __restrict__ Bl,
        float* __restrict__ C, int M, int N, int K) {
    __nv_bfloat16* sm = (__nv_bfloat16*)gsm;
    const uint32_t sb = smem_u32(gsm);

    const int tid = threadIdx.x, wid = tid >> 5, lane = tid & 31;
    const int wm = wid & 3, wn = wid >> 2;
    const int g = lane >> 2, t = lane & 3;
    const int m0 = blockIdx.y * 128, n0 = blockIdx.x * 64;

    float acc[2][4][4];
#pragma unroll
    for (int i = 0; i < 2; i++)
#pragma unroll
        for (int j = 0; j < 4; j++)
#pragma unroll
            for (int r = 0; r < 4; r++) acc[i][j][r] = 0.f;

    const int nch = K >> 6;
    gemm_prefetch(sb, 0, 0, tid, Ah, Al, Bh, Bl, m0, n0, K);
    CP_COMMIT();

    for (int c = 0; c < nch; c++) {
        const int st = c & 1;
        if (c + 1 < nch) {
            gemm_prefetch(sb, st ^ 1, (c + 1) << 6, tid, Ah, Al, Bh, Bl, m0, n0, K);
            CP_COMMIT();
            CP_WAIT1();
        } else {
            CP_WAIT0();
        }
        __syncthreads();

        __nv_bfloat16* AsH = sm + st * GB_STG + GB_AH;
        __nv_bfloat16* AsL = sm + st * GB_STG + GB_AL;
        __nv_bfloat16* BsH = sm + st * GB_STG + GB_BH;
        __nv_bfloat16* BsL = sm + st * GB_STG + GB_BL;

#pragma unroll
        for (int kk = 0; kk < 64; kk += 16) {
            uint32_t ah[2][4], al[2][4], bh[4][2], bl[4][2];
#pragma unroll
            for (int i = 0; i < 2; i++) {
                const int r0 = wm * 32 + i * 16 + g;
                ah[i][0] = *(const uint32_t*)&AsH[(r0)     * GS + kk + 2 * t];
                ah[i][1] = *(const uint32_t*)&AsH[(r0 + 8) * GS + kk + 2 * t];
                ah[i][2] = *(const uint32_t*)&AsH[(r0)     * GS + kk + 8 + 2 * t];
                ah[i][3] = *(const uint32_t*)&AsH[(r0 + 8) * GS + kk + 8 + 2 * t];
                al[i][0] = *(const uint32_t*)&AsL[(r0)     * GS + kk + 2 * t];
                al[i][1] = *(const uint32_t*)&AsL[(r0 + 8) * GS + kk + 2 * t];
                al[i][2] = *(const uint32_t*)&AsL[(r0)     * GS + kk + 8 + 2 * t];
                al[i][3] = *(const uint32_t*)&AsL[(r0 + 8) * GS + kk + 8 + 2 * t];
            }
#pragma unroll
            for (int j = 0; j < 4; j++) {
                const int n = wn * 32 + j * 8 + g;
                bh[j][0] = *(const uint32_t*)&BsH[n * GS + kk + 2 * t];
                bh[j][1] = *(const uint32_t*)&BsH[n * GS + kk + 8 + 2 * t];
                bl[j][0] = *(const uint32_t*)&BsL[n * GS + kk + 2 * t];
                bl[j][1] = *(const uint32_t*)&BsL[n * GS + kk + 8 + 2 * t];
            }
#pragma unroll
            for (int i = 0; i < 2; i++)
#pragma unroll
                for (int j = 0; j < 4; j++) {
                    mma16816(acc[i][j], ah[i][0], ah[i][1], ah[i][2], ah[i][3], bh[j][0], bh[j][1]);
                    mma16816(acc[i][j], al[i][0], al[i][1], al[i][2], al[i][3], bh[j][0], bh[j][1]);
                    mma16816(acc[i][j], ah[i][0], ah[i][1], ah[i][2], ah[i][3], bl[j][0], bl[j][1]);
                }
        }
        __syncthreads();
    }

#pragma unroll
    for (int i = 0; i < 2; i++)
#pragma unroll
        for (int j = 0; j < 4; j++) {
            const int row = m0 + wm * 32 + i * 16 + g;
            const int col = n0 + wn * 32 + j * 8 + 2 * t;
            *(float2*)&C[(size_t)row * N + col]       = make_float2(acc[i][j][0], acc[i][j][1]);
            *(float2*)&C[(size_t)(row + 8) * N + col] = make_float2(acc[i][j][2], acc[i][j][3]);
        }
}

// ---------------- RoPE + concat + per-head RMS -> bf16 hi/lo [B,h,T,64] ----------------
__global__ __launch_bounds__(256) void assemble(const float* __restrict__ qhw,
                                                const float* __restrict__ khw) {
    const int n = blockIdx.x;
    const int b = n / TSEQ, t = n % TSEQ;
    const int tid = threadIdx.x, w = tid >> 5, l = tid & 31;

    const int j = l & 15;
    const float invf = powf(500000.0f, -(float)j / 16.0f);
    const float f = (float)t * invf;
    const float cs = cosf(f), sn = sinf(f);

    {
        const int h = w;
        float v0 = g_qnope[(size_t)n * 256 + h * 32 + l];
        const float* qr = &g_qrope[(size_t)n * 256 + h * 32];
        float a = qr[l];
        float v1 = (l < 16) ? (a * cs - qr[l + 16] * sn) : (a * cs + qr[l - 16] * sn);
        float ss = v0 * v0 + v1 * v1;
#pragma unroll
        for (int o = 16; o > 0; o >>= 1) ss += __shfl_xor_sync(0xffffffffu, ss, o);
        float scale = rsqrtf(ss / 64.0f + 1e-6f);
        const size_t base = (((size_t)b * NHEADS + h) * TSEQ + t) * HDIM;
        __nv_bfloat16 hh, ll;
        bfsplit(v0 * scale * qhw[l], hh, ll);
        g_qh[base + l] = hh; g_ql[base + l] = ll;
        bfsplit(v1 * scale * qhw[32 + l], hh, ll);
        g_qh[base + 32 + l] = hh; g_ql[base + 32 + l] = ll;
    }
    if (w < 2) {
        const int kvh = w;
        float v0 = g_knope[(size_t)n * 64 + kvh * 32 + l];
        const float* kr = &g_krope[(size_t)n * 64 + kvh * 32];
        float a = kr[l];
        float v1 = (l < 16) ? (a * cs - kr[l + 16] * sn) : (a * cs + kr[l - 16] * sn);
        float ss = v0 * v0 + v1 * v1;
#pragma unroll
        for (int o = 16; o > 0; o >>= 1) ss += __shfl_xor_sync(0xffffffffu, ss, o);
        float scale = rsqrtf(ss / 64.0f + 1e-6f);
        const size_t base = (((size_t)b * NKVH + kvh) * TSEQ + t) * HDIM;
        __nv_bfloat16 hh, ll;
        bfsplit(v0 * scale * khw[l], hh, ll);
        g_kh[base + l] = hh; g_kl[base + l] = ll;
        bfsplit(v1 * scale * khw[32 + l], hh, ll);
        g_kh[base + 32 + l] = hh; g_kl[base + 32 + l] = ll;
    }
}

// ---------------- V: fp32 [tok, kvh*64+d] -> bf16 hi/lo transposed [b,kvh,d,T] ----------------
__global__ __launch_bounds__(256) void vtrans() {
    __shared__ __nv_bfloat16 sh[64][65], sl[64][65];
    const int bk = blockIdx.x;
    const int b = bk >> 1, kvh = bk & 1;
    const int t0 = blockIdx.y * 64;
    const int tid = threadIdx.x;
    for (int i = tid; i < 4096; i += 256) {
        const int tt = i >> 6, d = i & 63;
        float v = g_vv[(size_t)(b * TSEQ + t0 + tt) * 128 + kvh * 64 + d];
        __nv_bfloat16 hh, ll;
        bfsplit(v, hh, ll);
        sh[tt][d] = hh; sl[tt][d] = ll;
    }
    __syncthreads();
    for (int i = tid; i < 4096; i += 256) {
        const int d = i >> 6, tt = i & 63;
        g_vth[((size_t)bk * 64 + d) * TSEQ + t0 + tt] = sh[tt][d];
        g_vtl[((size_t)bk * 64 + d) * TSEQ + t0 + tt] = sl[tt][d];
    }
}

// ---------------- HMMA causal flash attention, BM=128, BN=64, d=64 ----------------
#define FS 72
#define FQH 0
#define FQL 9216
#define FSTG 18432
#define FSTGSZ 18432
#define FL_SMEM ((FSTG + 2 * FSTGSZ) * 2)   /* 110592 bytes */

__device__ __forceinline__ void flash_prefetch(uint32_t sb, int stage, int kt, int tid,
        const __nv_bfloat16* Khb, const __nv_bfloat16* Klb,
        const __nv_bfloat16* Vthb, const __nv_bfloat16* Vtlb) {
    const int base = FSTG + stage * FSTGSZ;
#pragma unroll
    for (int i = tid; i < 2048; i += 256) {
        const int arr = i >> 9;
        const int r = (i >> 3) & 63;
        const int c = i & 7;
        const uint32_t dst = sb + (uint32_t)(base + arr * 4608 + r * FS + c * 8) * 2;
        const __nv_bfloat16* src;
        if (arr == 0)      src = Khb + ((size_t)(kt * 64 + r)) * 64 + c * 8;
        else if (arr == 1) src = Klb + ((size_t)(kt * 64 + r)) * 64 + c * 8;
        else if (arr == 2) src = Vthb + (size_t)r * TSEQ + kt * 64 + c * 8;
        else               src = Vtlb + (size_t)r * TSEQ + kt * 64 + c * 8;
        cpa16(dst, src);
    }
}

__global__ __launch_bounds__(256) void flash(const float* __restrict__ vres) {
    __nv_bfloat16* sm = (__nv_bfloat16*)gsm;
    const uint32_t sb = smem_u32(gsm);

    const int qt = gridDim.x - 1 - blockIdx.x;
    const int bh = blockIdx.y;
    const int b = bh >> 3, h = bh & 7, kvh = h >> 2;
    const int q0 = qt * 128;

    const int tid = threadIdx.x, wid = tid >> 5, lane = tid & 31;
    const int g = lane >> 2, t = lane & 3;
    const int r0 = wid * 16;

    const __nv_bfloat16* Qhb = &g_qh[(((size_t)b * NHEADS + h) * TSEQ + q0) * HDIM];
    const __nv_bfloat16* Qlb = &g_ql[(((size_t)b * NHEADS + h) * TSEQ + q0) * HDIM];
    const __nv_bfloat16* Khb = &g_kh[(((size_t)b * NKVH + kvh) * TSEQ) * HDIM];
    const __nv_bfloat16* Klb = &g_kl[(((size_t)b * NKVH + kvh) * TSEQ) * HDIM];
    const __nv_bfloat16* Vthb = &g_vth[(((size_t)b * NKVH + kvh) * HDIM) * TSEQ];
    const __nv_bfloat16* Vtlb = &g_vtl[(((size_t)b * NKVH + kvh) * HDIM) * TSEQ];

#pragma unroll
    for (int i = tid; i < 2048; i += 256) {
        const int half = i >> 10;
        const int r = (i >> 3) & 127;
        const int c = i & 7;
        const uint32_t dst = sb + (uint32_t)((half ? FQL : FQH) + r * FS + c * 8) * 2;
        const __nv_bfloat16* src = (half ? Qlb : Qhb) + (size_t)r * 64 + c * 8;
        cpa16(dst, src);
    }
    flash_prefetch(sb, 0, 0, tid, Khb, Klb, Vthb, Vtlb);
    CP_COMMIT();

    float m0 = -INFINITY, m1 = -INFINITY, l0 = 0.f, l1 = 0.f;
    float o[8][4];
#pragma unroll
    for (int j = 0; j < 8; j++)
#pragma unroll
        for (int r = 0; r < 4; r++) o[j][r] = 0.f;

    const int ktmax = 2 * qt + 1;
    for (int kt = 0; kt <= ktmax; kt++) {
        const int st = kt & 1;
        if (kt < ktmax) {
            flash_prefetch(sb, st ^ 1, kt + 1, tid, Khb, Klb, Vthb, Vtlb);
            CP_COMMIT();
            CP_WAIT1();
        } else {
            CP_WAIT0();
        }
        __syncthreads();

        __nv_bfloat16* KH = sm + FSTG + st * FSTGSZ;
        __nv_bfloat16* KL = KH + 4608;
        __nv_bfloat16* VH = KH + 9216;
        __nv_bfloat16* VL = KH + 13824;
        __nv_bfloat16* QH = sm + FQH;
        __nv_bfloat16* QL = sm + FQL;

        float s[8][4];
#pragma unroll
        for (int j = 0; j < 8; j++)
#pragma unroll
            for (int r = 0; r < 4; r++) s[j][r] = 0.f;

#pragma unroll
        for (int kk = 0; kk < 64; kk += 16) {
            uint32_t aH[4], aL[4];
            aH[0] = *(const uint32_t*)&QH[(r0 + g)     * FS + kk + 2 * t];
            aH[1] = *(const uint32_t*)&QH[(r0 + g + 8) * FS + kk + 2 * t];
            aH[2] = *(const uint32_t*)&QH[(r0 + g)     * FS + kk + 8 + 2 * t];
            aH[3] = *(const uint32_t*)&QH[(r0 + g + 8) * FS + kk + 8 + 2 * t];
            aL[0] = *(const uint32_t*)&QL[(r0 + g)     * FS + kk + 2 * t];
            aL[1] = *(const uint32_t*)&QL[(r0 + g + 8) * FS + kk + 2 * t];
            aL[2] = *(const uint32_t*)&QL[(r0 + g)     * FS + kk + 8 + 2 * t];
            aL[3] = *(const uint32_t*)&QL[(r0 + g + 8) * FS + kk + 8 + 2 * t];
#pragma unroll
            for (int j = 0; j < 8; j++) {
                const int n = j * 8 + g;
                uint32_t bH0 = *(const uint32_t*)&KH[n * FS + kk + 2 * t];
                uint32_t bH1 = *(const uint32_t*)&KH[n * FS + kk + 8 + 2 * t];
                uint32_t bL0 = *(const uint32_t*)&KL[n * FS + kk + 2 * t];
                uint32_t bL1 = *(const uint32_t*)&KL[n * FS + kk + 8 + 2 * t];
                mma16816(s[j], aH[0], aH[1], aH[2], aH[3], bH0, bH1);
                mma16816(s[j], aL[0], aL[1], aL[2], aL[3], bH0, bH1);
                mma16816(s[j], aH[0], aH[1], aH[2], aH[3], bL0, bL1);
            }
        }

        const bool diag = (kt >= 2 * qt);
#pragma unroll
        for (int j = 0; j < 8; j++) {
#pragma unroll
            for (int r = 0; r < 4; r++) {
                s[j][r] *= 0.125f;
                if (diag) {
                    const int col = kt * 64 + j * 8 + 2 * t + (r & 1);
                    const int row = q0 + r0 + g + ((r >> 1) << 3);
                    if (col > row) s[j][r] = -INFINITY;
                }
            }
        }

        float mx0 = -INFINITY, mx1 = -INFINITY;
#pragma unroll
        for (int j = 0; j < 8; j++) {
            mx0 = fmaxf(mx0, fmaxf(s[j][0], s[j][1]));
            mx1 = fmaxf(mx1, fmaxf(s[j][2], s[j][3]));
        }
        mx0 = fmaxf(mx0, __shfl_xor_sync(0xffffffffu, mx0, 1));
        mx0 = fmaxf(mx0, __shfl_xor_sync(0xffffffffu, mx0, 2));
        mx1 = fmaxf(mx1, __shfl_xor_sync(0xffffffffu, mx1, 1));
        mx1 = fmaxf(mx1, __shfl_xor_sync(0xffffffffu, mx1, 2));
        const float mn0 = fmaxf(m0, mx0), mn1 = fmaxf(m1, mx1);
        const float al0 = __expf(m0 - mn0), al1 = __expf(m1 - mn1);
        m0 = mn0; m1 = mn1;
        float rs0 = 0.f, rs1 = 0.f;
#pragma unroll
        for (int j = 0; j < 8; j++) {
            s[j][0] = __expf(s[j][0] - m0);
            s[j][1] = __expf(s[j][1] - m0);
            s[j][2] = __expf(s[j][2] - m1);
            s[j][3] = __expf(s[j][3] - m1);
            rs0 += s[j][0] + s[j][1];
            rs1 += s[j][2] + s[j][3];
        }
        rs0 += __shfl_xor_sync(0xffffffffu, rs0, 1);
        rs0 += __shfl_xor_sync(0xffffffffu, rs0, 2);
        rs1 += __shfl_xor_sync(0xffffffffu, rs1, 1);
        rs1 += __shfl_xor_sync(0xffffffffu, rs1, 2);
        l0 = l0 * al0 + rs0;
        l1 = l1 * al1 + rs1;
#pragma unroll
        for (int j = 0; j < 8; j++) {
            o[j][0] *= al0; o[j][1] *= al0;
            o[j][2] *= al1; o[j][3] *= al1;
        }

#pragma unroll
        for (int u = 0; u < 4; u++) {
            uint32_t aPh[4], aPl[4];
            {
                __nv_bfloat16 h0, h1, h2, h3, lo0, lo1, lo2, lo3;
                bfsplit(s[2*u][0], h0, lo0);   bfsplit(s[2*u][1], h1, lo1);
                bfsplit(s[2*u][2], h2, lo2);   bfsplit(s[2*u][3], h3, lo3);
                aPh[0] = packbf(h0, h1);  aPl[0] = packbf(lo0, lo1);
                aPh[1] = packbf(h2, h3);  aPl[1] = packbf(lo2, lo3);
                bfsplit(s[2*u+1][0], h0, lo0); bfsplit(s[2*u+1][1], h1, lo1);
                bfsplit(s[2*u+1][2], h2, lo2); bfsplit(s[2*u+1][3], h3, lo3);
                aPh[2] = packbf(h0, h1);  aPl[2] = packbf(lo0, lo1);
                aPh[3] = packbf(h2, h3);  aPl[3] = packbf(lo2, lo3);
            }
#pragma unroll
            for (int j = 0; j < 8; j++) {
                const int n = j * 8 + g;
                uint32_t bH0 = *(const uint32_t*)&VH[n * FS + 16 * u + 2 * t];
                uint32_t bH1 = *(const uint32_t*)&VH[n * FS + 16 * u + 8 + 2 * t];
                uint32_t bL0 = *(const uint32_t*)&VL[n * FS + 16 * u + 2 * t];
                uint32_t bL1 = *(const uint32_t*)&VL[n * FS + 16 * u + 8 + 2 * t];
                mma16816(o[j], aPh[0], aPh[1], aPh[2], aPh[3], bH0, bH1);
                mma16816(o[j], aPl[0], aPl[1], aPl[2], aPl[3], bH0, bH1);
                mma16816(o[j], aPh[0], aPh[1], aPh[2], aPh[3], bL0, bL1);
            }
        }
        __syncthreads();
    }

    // ---- epilogue: normalize, add v_res, write attn as bf16 hi/lo pairs ----
    const float inv0 = 1.0f / l0, inv1 = 1.0f / l1;
#pragma unroll
    for (int j = 0; j < 8; j++) {
        const int col = h * 64 + j * 8 + 2 * t;
        {
            const int row = q0 + r0 + g;
            const size_t tok = (size_t)b * TSEQ + row;
            const float2 vr = *(const float2*)&vres[tok * 512 + col];
            __nv_bfloat16 h0, lo0, h1, lo1;
            bfsplit(o[j][0] * inv0 + vr.x, h0, lo0);
            bfsplit(o[j][1] * inv0 + vr.y, h1, lo1);
            *(uint32_t*)&g_ath[tok * 512 + col] = packbf(h0, h1);
            *(uint32_t*)&g_atl[tok * 512 + col] = packbf(lo0, lo1);
        }
        {
            const int row = q0 + r0 + g + 8;
            const size_t tok = (size_t)b * TSEQ + row;
            const float2 vr = *(const float2*)&vres[tok * 512 + col];
            __nv_bfloat16 h0, lo0, h1, lo1;
            bfsplit(o[j][2] * inv1 + vr.x, h0, lo0);
            bfsplit(o[j][3] * inv1 + vr.y, h1, lo1);
            *(uint32_t*)&g_ath[tok * 512 + col] = packbf(h0, h1);
            *(uint32_t*)&g_atl[tok * 512 + col] = packbf(lo0, lo1);
        }
    }
}

// ---------------- launch ----------------
extern "C" void kernel_launch(void* const* d_in, const int* in_sizes, int n_in,
                              void* d_out, int out_size) {
    const float* x     = (const float*)d_in[0];
    const float* W_DQ  = (const float*)d_in[1];
    const float* W_UQ  = (const float*)d_in[2];
    const float* W_QR  = (const float*)d_in[3];
    const float* W_DKV = (const float*)d_in[4];
    const float* W_UK  = (const float*)d_in[5];
    const float* W_UV  = (const float*)d_in[6];
    const float* W_KR  = (const float*)d_in[7];
    const float* W_VR  = (const float*)d_in[8];
    const float* W_O   = (const float*)d_in[9];
    const float* q_ln  = (const float*)d_in[10];
    const float* kv_ln = (const float*)d_in[11];
    const float* qhw   = (const float*)d_in[12];
    const float* khw   = (const float*)d_in[13];
    float* out = (float*)d_out;

    float *cq, *ckv, *krope, *vres, *qnope, *qrope, *knope;
    cudaGetSymbolAddress((void**)&cq,    g_cq);
    cudaGetSymbolAddress((void**)&ckv,   g_ckv);
    cudaGetSymbolAddress((void**)&krope, g_krope);
    cudaGetSymbolAddress((void**)&vres,  g_vres);
    cudaGetSymbolAddress((void**)&qnope, g_qnope);
    cudaGetSymbolAddress((void**)&qrope, g_qrope);
    cudaGetSymbolAddress((void**)&knope, g_knope);

    __nv_bfloat16 *xh, *xl, *cqh, *cql, *ckvh, *ckvl, *ath, *atl;
    __nv_bfloat16 *wdqh, *wdql, *wuqh, *wuql, *wqrh, *wqrl, *wdkvh, *wdkvl;
    __nv_bfloat16 *wukh, *wukl, *wuvh, *wuvl, *wkrh, *wkrl, *wvrh, *wvrl, *woh, *wol;
    float* vvp;
    cudaGetSymbolAddress((void**)&vvp, g_vv);
    cudaGetSymbolAddress((void**)&xh, g_xh);     cudaGetSymbolAddress((void**)&xl, g_xl);
    cudaGetSymbolAddress((void**)&cqh, g_cqh);   cudaGetSymbolAddress((void**)&cql, g_cql);
    cudaGetSymbolAddress((void**)&ckvh, g_ckvh); cudaGetSymbolAddress((void**)&ckvl, g_ckvl);
    cudaGetSymbolAddress((void**)&ath, g_ath);   cudaGetSymbolAddress((void**)&atl, g_atl);
    cudaGetSymbolAddress((void**)&wdqh, g_wdqh);   cudaGetSymbolAddress((void**)&wdql, g_wdql);
    cudaGetSymbolAddress((void**)&wuqh, g_wuqh);   cudaGetSymbolAddress((void**)&wuql, g_wuql);
    cudaGetSymbolAddress((void**)&wqrh, g_wqrh);   cudaGetSymbolAddress((void**)&wqrl, g_wqrl);
    cudaGetSymbolAddress((void**)&wdkvh, g_wdkvh); cudaGetSymbolAddress((void**)&wdkvl, g_wdkvl);
    cudaGetSymbolAddress((void**)&wukh, g_wukh);   cudaGetSymbolAddress((void**)&wukl, g_wukl);
    cudaGetSymbolAddress((void**)&wuvh, g_wuvh);   cudaGetSymbolAddress((void**)&wuvl, g_wuvl);
    cudaGetSymbolAddress((void**)&wkrh, g_wkrh);   cudaGetSymbolAddress((void**)&wkrl, g_wkrl);
    cudaGetSymbolAddress((void**)&wvrh, g_wvrh);   cudaGetSymbolAddress((void**)&wvrl, g_wvrl);
    cudaGetSymbolAddress((void**)&woh, g_woh);     cudaGetSymbolAddress((void**)&wol, g_wol);

    cudaFuncSetAttribute(flash, cudaFuncAttributeMaxDynamicSharedMemorySize, FL_SMEM);
    cudaFuncSetAttribute(hgemm_bs, cudaFuncAttributeMaxDynamicSharedMemorySize, GB_SMEM);

    // ---- pre-split inputs & weights ----
    asplit<<<(NTOK * 512 / 4 + 255) / 256, 256>>>(x, xh, xl, NTOK * 512 / 4);
    wsplit_t<<<dim3(256 / 32, 512 / 32), 256>>>(W_DQ,  wdqh,  wdql,  512, 256);
    wsplit_t<<<dim3(256 / 32, 256 / 32), 256>>>(W_UQ,  wuqh,  wuql,  256, 256);
    wsplit_t<<<dim3(256 / 32, 256 / 32), 256>>>(W_QR,  wqrh,  wqrl,  256, 256);
    wsplit_t<<<dim3(128 / 32, 512 / 32), 256>>>(W_DKV, wdkvh, wdkvl, 512, 128);
    wsplit_t<<<dim3( 64 / 32, 128 / 32), 256>>>(W_UK,  wukh,  wukl,  128,  64);
    wsplit_t<<<dim3(128 / 32, 128 / 32), 256>>>(W_UV,  wuvh,  wuvl,  128, 128);
    wsplit_t<<<dim3( 64 / 32, 512 / 32), 256>>>(W_KR,  wkrh,  wkrl,  512,  64);
    wsplit_t<<<dim3(512 / 32, 512 / 32), 256>>>(W_VR,  wvrh,  wvrl,  512, 512);
    wsplit_t<<<dim3(512 / 32, 512 / 32), 256>>>(W_O,   woh,   wol,   512, 512);

#define GEMMB(Ah, Al, Bh, Bl, Cm, Mv, Nv, Kv) \
    hgemm_bs<<<dim3((Nv) / 64, (Mv) / 128), 256, GB_SMEM>>>(Ah, Al, Bh, Bl, Cm, Mv, Nv, Kv)

    // x projections
    GEMMB(xh, xl, wdqh,  wdql,  cq,    NTOK, 256, 512);
    GEMMB(xh, xl, wdkvh, wdkvl, ckv,   NTOK, 128, 512);
    GEMMB(xh, xl, wkrh,  wkrl,  krope, NTOK,  64, 512);
    GEMMB(xh, xl, wvrh,  wvrl,  vres,  NTOK, 512, 512);

    // latent RMS norms (+ split)
    rms_split<<<NTOK, 256>>>(cq,  q_ln,  cqh,  cql,  256);
    rms_split<<<NTOK, 128>>>(ckv, kv_ln, ckvh, ckvl, 128);

    // up-projections
    GEMMB(cqh,  cql,  wuqh, wuql, qnope, NTOK, 256, 256);
    GEMMB(cqh,  cql,  wqrh, wqrl, qrope, NTOK, 256, 256);
    GEMMB(ckvh, ckvl, wukh, wukl, knope, NTOK,  64, 128);
    GEMMB(ckvh, ckvl, wuvh, wuvl, vvp,   NTOK, 128, 128);

    // rope + concat + head-RMS + split; V transpose+split
    assemble<<<NTOK, 256>>>(qhw, khw);
    vtrans<<<dim3(BATCH * NKVH, TSEQ / 64), 256>>>();

    // causal flash attention + v_res (writes pre-split attn)
    flash<<<dim3(TSEQ / 128, BATCH * NHEADS), 256, FL_SMEM>>>(vres);

    // output projection
    GEMMB(ath, atl, woh, wol, out, NTOK, 512, 512);
}

// round 11
// speedup vs baseline: 2.5818x; 1.0734x over previous
#include <cuda_runtime.h>
#include <cuda_bf16.h>
#include <math.h>
#include <stdint.h>

#define NHEADS 8
#define NKVH   2
#define HDIM   64
#define TSEQ   2048
#define BATCH  4
#define NTOK   (BATCH*TSEQ)   /* 8192 */

// ---------------- scratch (device globals; no allocation allowed) ----------------
__device__ float g_cq   [NTOK*256];
__device__ float g_ckv  [NTOK*128];
__device__ float g_krope[NTOK*64];
__device__ float g_vres [NTOK*512];
__device__ float g_qnope[NTOK*256];
__device__ float g_qrope[NTOK*256];
__device__ float g_knope[NTOK*64];
__device__ float g_vv   [NTOK*128];
// pre-split bf16 hi/lo activations
__device__ __nv_bfloat16 g_xh  [NTOK*512], g_xl  [NTOK*512];
__device__ __nv_bfloat16 g_cqh [NTOK*256], g_cql [NTOK*256];
__device__ __nv_bfloat16 g_ckvh[NTOK*128], g_ckvl[NTOK*128];
__device__ __nv_bfloat16 g_ath [NTOK*512], g_atl [NTOK*512];
// pre-split, pre-transposed [N,K] weights
__device__ __nv_bfloat16 g_wdqh [256*512], g_wdql [256*512];
__device__ __nv_bfloat16 g_wuqh [256*256], g_wuql [256*256];
__device__ __nv_bfloat16 g_wqrh [256*256], g_wqrl [256*256];
__device__ __nv_bfloat16 g_wdkvh[128*512], g_wdkvl[128*512];
__device__ __nv_bfloat16 g_wukh [64*128],  g_wukl [64*128];
__device__ __nv_bfloat16 g_wuvh [128*128], g_wuvl [128*128];
__device__ __nv_bfloat16 g_wkrh [64*512],  g_wkrl [64*512];
__device__ __nv_bfloat16 g_wvrh [512*512], g_wvrl [512*512];
__device__ __nv_bfloat16 g_woh  [512*512], g_wol  [512*512];
// flash operands
__device__ __nv_bfloat16 g_qh [BATCH*NHEADS*TSEQ*HDIM];
__device__ __nv_bfloat16 g_ql [BATCH*NHEADS*TSEQ*HDIM];
__device__ __nv_bfloat16 g_kh [BATCH*NKVH*TSEQ*HDIM];
__device__ __nv_bfloat16 g_kl [BATCH*NKVH*TSEQ*HDIM];
__device__ __nv_bfloat16 g_vth[BATCH*NKVH*HDIM*TSEQ];
__device__ __nv_bfloat16 g_vtl[BATCH*NKVH*HDIM*TSEQ];

__device__ __forceinline__ uint32_t packbf(__nv_bfloat16 a, __nv_bfloat16 b) {
    return ((uint32_t)__bfloat16_as_ushort(b) << 16) | (uint32_t)__bfloat16_as_ushort(a);
}
__device__ __forceinline__ void mma16816(float* c, uint32_t a0, uint32_t a1,
                                         uint32_t a2, uint32_t a3,
                                         uint32_t b0, uint32_t b1) {
    asm volatile(
        "mma.sync.aligned.m16n8k16.row.col.f32.bf16.bf16.f32 "
        "{%0,%1,%2,%3}, {%4,%5,%6,%7}, {%8,%9}, {%0,%1,%2,%3};"
        : "+f"(c[0]), "+f"(c[1]), "+f"(c[2]), "+f"(c[3])
        : "r"(a0), "r"(a1), "r"(a2), "r"(a3), "r"(b0), "r"(b1));
}
__device__ __forceinline__ void ldsm4(uint32_t& r0, uint32_t& r1, uint32_t& r2,
                                      uint32_t& r3, uint32_t addr) {
    asm volatile("ldmatrix.sync.aligned.m8n8.x4.shared.b16 {%0,%1,%2,%3}, [%4];"
                 : "=r"(r0), "=r"(r1), "=r"(r2), "=r"(r3) : "r"(addr));
}
__device__ __forceinline__ void bfsplit(float v, __nv_bfloat16& h, __nv_bfloat16& l) {
    h = __float2bfloat16(v);
    l = __float2bfloat16(v - __bfloat162float(h));
}
__device__ __forceinline__ uint32_t smem_u32(const void* p) {
    uint32_t a;
    asm("{ .reg .u64 t; cvta.to.shared.u64 t, %1; cvt.u32.u64 %0, t; }" : "=r"(a) : "l"(p));
    return a;
}
__device__ __forceinline__ void cpa16(uint32_t dst, const void* src) {
    asm volatile("cp.async.ca.shared.global [%0], [%1], 16;" :: "r"(dst), "l"(src) : "memory");
}
#define CP_COMMIT() asm volatile("cp.async.commit_group;" ::: "memory")
#define CP_WAIT0()  asm volatile("cp.async.wait_group 0;" ::: "memory")
#define CP_WAIT1()  asm volatile("cp.async.wait_group 1;" ::: "memory")

// ---------------- split helpers ----------------
__global__ void asplit(const float* __restrict__ X, __nv_bfloat16* __restrict__ Xh,
                       __nv_bfloat16* __restrict__ Xl, int n4) {
    const int i = blockIdx.x * blockDim.x + threadIdx.x;
    if (i >= n4) return;
    const float4 v = ((const float4*)X)[i];
    __nv_bfloat16 h0, h1, h2, h3, l0, l1, l2, l3;
    bfsplit(v.x, h0, l0); bfsplit(v.y, h1, l1);
    bfsplit(v.z, h2, l2); bfsplit(v.w, h3, l3);
    ((uint2*)Xh)[i] = make_uint2(packbf(h0, h1), packbf(h2, h3));
    ((uint2*)Xl)[i] = make_uint2(packbf(l0, l1), packbf(l2, l3));
}

__global__ void wsplit_t(const float* __restrict__ W, __nv_bfloat16* __restrict__ Wh,
                         __nv_bfloat16* __restrict__ Wl, int K, int N) {
    __shared__ float tile[32][33];
    const int k0 = blockIdx.y * 32, n0 = blockIdx.x * 32;
    const int tid = threadIdx.x;
    for (int i = tid; i < 1024; i += 256) {
        const int r = i >> 5, c = i & 31;
        tile[r][c] = W[(size_t)(k0 + r) * N + n0 + c];
    }
    __syncthreads();
    for (int i = tid; i < 1024; i += 256) {
        const int n = i >> 5, k = i & 31;
        __nv_bfloat16 h, l;
        bfsplit(tile[k][n], h, l);
        Wh[(size_t)(n0 + n) * K + k0 + k] = h;
        Wl[(size_t)(n0 + n) * K + k0 + k] = l;
    }
}

__global__ void rms_split(const float* __restrict__ X, const float* __restrict__ w,
                          __nv_bfloat16* __restrict__ Xh, __nv_bfloat16* __restrict__ Xl,
                          int D) {
    const int n = blockIdx.x;
    const float* row = X + (size_t)n * D;
    const int tid = threadIdx.x;
    const float v = row[tid];
    float ss = v * v;
#pragma unroll
    for (int o = 16; o > 0; o >>= 1) ss += __shfl_xor_sync(0xffffffffu, ss, o);
    __shared__ float sh[8];
    const int wid = tid >> 5, nw = blockDim.x >> 5;
    if ((tid & 31) == 0) sh[wid] = ss;
    __syncthreads();
    float tot = 0.f;
    for (int i = 0; i < nw; i++) tot += sh[i];
    const float scale = rsqrtf(tot / (float)D + 1e-6f);
    __nv_bfloat16 h, l;
    bfsplit(v * scale * w[tid], h, l);
    Xh[(size_t)n * D + tid] = h;
    Xl[(size_t)n * D + tid] = l;
}

// ---------------- bf16x3 HMMA GEMM, pre-split, cp.async + ldmatrix ----------------
#define GS 72
#define GB_AH 0
#define GB_AL 9216
#define GB_BH 18432
#define GB_BL 23040
#define GB_STG 27648
#define GB_SMEM (2 * GB_STG * 2)        /* 110592 bytes */

extern __shared__ char gsm[];

__device__ __forceinline__ void gemm_prefetch(uint32_t sb, int stage, int c64, int tid,
        const __nv_bfloat16* Ah, const __nv_bfloat16* Al,
        const __nv_bfloat16* Bh, const __nv_bfloat16* Bl,
        int m0, int n0, int K) {
    const int base = stage * GB_STG;
#pragma unroll
    for (int i = tid; i < 2048; i += 256) {
        const int half = i >> 10;
        const int r = (i >> 3) & 127;
        const int cc = i & 7;
        const uint32_t dst = sb + (uint32_t)(base + (half ? GB_AL : GB_AH) + r * GS + cc * 8) * 2;
        const __nv_bfloat16* src = (half ? Al : Ah) + (size_t)(m0 + r) * K + c64 + cc * 8;
        cpa16(dst, src);
    }
#pragma unroll
    for (int i = tid; i < 1024; i += 256) {
        const int half = i >> 9;
        const int r = (i >> 3) & 63;
        const int cc = i & 7;
        const uint32_t dst = sb + (uint32_t)(base + (half ? GB_BL : GB_BH) + r * GS + cc * 8) * 2;
        const __nv_bfloat16* src = (half ? Bl : Bh) + (size_t)(n0 + r) * K + c64 + cc * 8;
        cpa16(dst, src);
    }
}

__global__ __launch_bounds__(256) void hgemm_bs(
        const __nv_bfloat16* __restrict__ Ah, const __nv_bfloat16* __restrict__ Al,
        const __nv_bfloat16* __restrict__ Bh, const __nv_bfloat16* __restrict__ Bl,
        float* __restrict__ C, int M, int N, int K) {
    const uint32_t sb = smem_u32(gsm);

    const int tid = threadIdx.x, wid = tid >> 5, lane = tid & 31;
    const int wm = wid & 3, wn = wid >> 2;
    const int g = lane >> 2, t = lane & 3;
    const int m0 = blockIdx.y * 128, n0 = blockIdx.x * 64;

    // ldmatrix lane mappings
    const int arow = ((lane >> 3) & 1) * 8 + (lane & 7);   // A-type
    const int acol = (lane >> 4) << 3;
    const int brow = ((lane >> 4) << 3) + (lane & 7);      // B-type
    const int bcol = ((lane >> 3) & 1) * 8;

    float acc[2][4][4];
#pragma unroll
    for (int i = 0; i < 2; i++)
#pragma unroll
        for (int j = 0; j < 4; j++)
#pragma unroll
            for (int r = 0; r < 4; r++) acc[i][j][r] = 0.f;

    const int nch = K >> 6;
    gemm_prefetch(sb, 0, 0, tid, Ah, Al, Bh, Bl, m0, n0, K);
    CP_COMMIT();

    for (int c = 0; c < nch; c++) {
        const int st = c & 1;
        if (c + 1 < nch) {
            gemm_prefetch(sb, st ^ 1, (c + 1) << 6, tid, Ah, Al, Bh, Bl, m0, n0, K);
            CP_COMMIT();
            CP_WAIT1();
        } else {
            CP_WAIT0();
        }
        __syncthreads();

        const uint32_t stg = sb + (uint32_t)(st * GB_STG) * 2;
        const uint32_t aH_b = stg + (uint32_t)(GB_AH + (wm * 32 + arow) * GS + acol) * 2;
        const uint32_t aL_b = stg + (uint32_t)(GB_AL + (wm * 32 + arow) * GS + acol) * 2;
        const uint32_t bH_b = stg + (uint32_t)(GB_BH + (wn * 32 + brow) * GS + bcol) * 2;
        const uint32_t bL_b = stg + (uint32_t)(GB_BL + (wn * 32 + brow) * GS + bcol) * 2;

#pragma unroll
        for (int kk = 0; kk < 64; kk += 16) {
            uint32_t ah[2][4], al[2][4];
#pragma unroll
            for (int i = 0; i < 2; i++) {
                ldsm4(ah[i][0], ah[i][1], ah[i][2], ah[i][3],
                      aH_b + (uint32_t)(i * 16 * GS + kk) * 2);
                ldsm4(al[i][0], al[i][1], al[i][2], al[i][3],
                      aL_b + (uint32_t)(i * 16 * GS + kk) * 2);
            }
#pragma unroll
            for (int jp = 0; jp < 2; jp++) {
                uint32_t h0, h1, h2, h3, l0, l1, l2, l3;
                ldsm4(h0, h1, h2, h3, bH_b + (uint32_t)(jp * 16 * GS + kk) * 2);
                ldsm4(l0, l1, l2, l3, bL_b + (uint32_t)(jp * 16 * GS + kk) * 2);
#pragma unroll
                for (int i = 0; i < 2; i++) {
                    mma16816(acc[i][2*jp],   ah[i][0], ah[i][1], ah[i][2], ah[i][3], h0, h1);
                    mma16816(acc[i][2*jp],   al[i][0], al[i][1], al[i][2], al[i][3], h0, h1);
                    mma16816(acc[i][2*jp],   ah[i][0], ah[i][1], ah[i][2], ah[i][3], l0, l1);
                    mma16816(acc[i][2*jp+1], ah[i][0], ah[i][1], ah[i][2], ah[i][3], h2, h3);
                    mma16816(acc[i][2*jp+1], al[i][0], al[i][1], al[i][2], al[i][3], h2, h3);
                    mma16816(acc[i][2*jp+1], ah[i][0], ah[i][1], ah[i][2], ah[i][3], l2, l3);
                }
            }
        }
        __syncthreads();
    }

#pragma unroll
    for (int i = 0; i < 2; i++)
#pragma unroll
        for (int j = 0; j < 4; j++) {
            const int row = m0 + wm * 32 + i * 16 + g;
            const int col = n0 + wn * 32 + j * 8 + 2 * t;
            *(float2*)&C[(size_t)row * N + col]       = make_float2(acc[i][j][0], acc[i][j][1]);
            *(float2*)&C[(size_t)(row + 8) * N + col] = make_float2(acc[i][j][2], acc[i][j][3]);
        }
}

// ---------------- RoPE + concat + per-head RMS -> bf16 hi/lo [B,h,T,64] ----------------
__global__ __launch_bounds__(256) void assemble(const float* __restrict__ qhw,
                                                const float* __restrict__ khw) {
    const int n = blockIdx.x;
    const int b = n / TSEQ, t = n % TSEQ;
    const int tid = threadIdx.x, w = tid >> 5, l = tid & 31;

    const int j = l & 15;
    const float invf = powf(500000.0f, -(float)j / 16.0f);
    const float f = (float)t * invf;
    const float cs = cosf(f), sn = sinf(f);

    {
        const int h = w;
        float v0 = g_qnope[(size_t)n * 256 + h * 32 + l];
        const float* qr = &g_qrope[(size_t)n * 256 + h * 32];
        float a = qr[l];
        float v1 = (l < 16) ? (a * cs - qr[l + 16] * sn) : (a * cs + qr[l - 16] * sn);
        float ss = v0 * v0 + v1 * v1;
#pragma unroll
        for (int o = 16; o > 0; o >>= 1) ss += __shfl_xor_sync(0xffffffffu, ss, o);
        float scale = rsqrtf(ss / 64.0f + 1e-6f);
        const size_t base = (((size_t)b * NHEADS + h) * TSEQ + t) * HDIM;
        __nv_bfloat16 hh, ll;
        bfsplit(v0 * scale * qhw[l], hh, ll);
        g_qh[base + l] = hh; g_ql[base + l] = ll;
        bfsplit(v1 * scale * qhw[32 + l], hh, ll);
        g_qh[base + 32 + l] = hh; g_ql[base + 32 + l] = ll;
    }
    if (w < 2) {
        const int kvh = w;
        float v0 = g_knope[(size_t)n * 64 + kvh * 32 + l];
        const float* kr = &g_krope[(size_t)n * 64 + kvh * 32];
        float a = kr[l];
        float v1 = (l < 16) ? (a * cs - kr[l + 16] * sn) : (a * cs + kr[l - 16] * sn);
        float ss = v0 * v0 + v1 * v1;
#pragma unroll
        for (int o = 16; o > 0; o >>= 1) ss += __shfl_xor_sync(0xffffffffu, ss, o);
        float scale = rsqrtf(ss / 64.0f + 1e-6f);
        const size_t base = (((size_t)b * NKVH + kvh) * TSEQ + t) * HDIM;
        __nv_bfloat16 hh, ll;
        bfsplit(v0 * scale * khw[l], hh, ll);
        g_kh[base + l] = hh; g_kl[base + l] = ll;
        bfsplit(v1 * scale * khw[32 + l], hh, ll);
        g_kh[base + 32 + l] = hh; g_kl[base + 32 + l] = ll;
    }
}

// ---------------- V transpose + split ----------------
__global__ __launch_bounds__(256) void vtrans() {
    __shared__ __nv_bfloat16 sh[64][65], sl[64][65];
    const int bk = blockIdx.x;
    const int b = bk >> 1, kvh = bk & 1;
    const int t0 = blockIdx.y * 64;
    const int tid = threadIdx.x;
    for (int i = tid; i < 4096; i += 256) {
        const int tt = i >> 6, d = i & 63;
        float v = g_vv[(size_t)(b * TSEQ + t0 + tt) * 128 + kvh * 64 + d];
        __nv_bfloat16 hh, ll;
        bfsplit(v, hh, ll);
        sh[tt][d] = hh; sl[tt][d] = ll;
    }
    __syncthreads();
    for (int i = tid; i < 4096; i += 256) {
        const int d = i >> 6, tt = i & 63;
        g_vth[((size_t)bk * 64 + d) * TSEQ + t0 + tt] = sh[tt][d];
        g_vtl[((size_t)bk * 64 + d) * TSEQ + t0 + tt] = sl[tt][d];
    }
}

// ---------------- HMMA causal flash attention, BM=128, BN=64, d=64, ldmatrix ----------------
#define FS 72
#define FQH 0
#define FQL 9216
#define FSTG 18432
#define FSTGSZ 18432
#define FL_SMEM ((FSTG + 2 * FSTGSZ) * 2)   /* 110592 bytes */

__device__ __forceinline__ void flash_prefetch(uint32_t sb, int stage, int kt, int tid,
        const __nv_bfloat16* Khb, const __nv_bfloat16* Klb,
        const __nv_bfloat16* Vthb, const __nv_bfloat16* Vtlb) {
    const int base = FSTG + stage * FSTGSZ;
#pragma unroll
    for (int i = tid; i < 2048; i += 256) {
        const int arr = i >> 9;
        const int r = (i >> 3) & 63;
        const int c = i & 7;
        const uint32_t dst = sb + (uint32_t)(base + arr * 4608 + r * FS + c * 8) * 2;
        const __nv_bfloat16* src;
        if (arr == 0)      src = Khb + ((size_t)(kt * 64 + r)) * 64 + c * 8;
        else if (arr == 1) src = Klb + ((size_t)(kt * 64 + r)) * 64 + c * 8;
        else if (arr == 2) src = Vthb + (size_t)r * TSEQ + kt * 64 + c * 8;
        else               src = Vtlb + (size_t)r * TSEQ + kt * 64 + c * 8;
        cpa16(dst, src);
    }
}

__global__ __launch_bounds__(256) void flash(const float* __restrict__ vres) {
    const uint32_t sb = smem_u32(gsm);

    const int qt = gridDim.x - 1 - blockIdx.x;
    const int bh = blockIdx.y;
    const int b = bh >> 3, h = bh & 7, kvh = h >> 2;
    const int q0 = qt * 128;

    const int tid = threadIdx.x, wid = tid >> 5, lane = tid & 31;
    const int g = lane >> 2, t = lane & 3;
    const int r0 = wid * 16;

    // ldmatrix lane mappings
    const int arow = ((lane >> 3) & 1) * 8 + (lane & 7);
    const int acol = (lane >> 4) << 3;
    const int brow = ((lane >> 4) << 3) + (lane & 7);
    const int bcol = ((lane >> 3) & 1) * 8;
    const uint32_t qh_a = sb + (uint32_t)(FQH + (r0 + arow) * FS + acol) * 2;
    const uint32_t ql_a = sb + (uint32_t)(FQL + (r0 + arow) * FS + acol) * 2;

    const __nv_bfloat16* Qhb = &g_qh[(((size_t)b * NHEADS + h) * TSEQ + q0) * HDIM];
    const __nv_bfloat16* Qlb = &g_ql[(((size_t)b * NHEADS + h) * TSEQ + q0) * HDIM];
    const __nv_bfloat16* Khb = &g_kh[(((size_t)b * NKVH + kvh) * TSEQ) * HDIM];
    const __nv_bfloat16* Klb = &g_kl[(((size_t)b * NKVH + kvh) * TSEQ) * HDIM];
    const __nv_bfloat16* Vthb = &g_vth[(((size_t)b * NKVH + kvh) * HDIM) * TSEQ];
    const __nv_bfloat16* Vtlb = &g_vtl[(((size_t)b * NKVH + kvh) * HDIM) * TSEQ];

#pragma unroll
    for (int i = tid; i < 2048; i += 256) {
        const int half = i >> 10;
        const int r = (i >> 3) & 127;
        const int c = i & 7;
        const uint32_t dst = sb + (uint32_t)((half ? FQL : FQH) + r * FS + c * 8) * 2;
        const __nv_bfloat16* src = (half ? Qlb : Qhb) + (size_t)r * 64 + c * 8;
        cpa16(dst, src);
    }
    flash_prefetch(sb, 0, 0, tid, Khb, Klb, Vthb, Vtlb);
    CP_COMMIT();

    float m0 = -INFINITY, m1 = -INFINITY, l0 = 0.f, l1 = 0.f;
    float o[8][4];
#pragma unroll
    for (int j = 0; j < 8; j++)
#pragma unroll
        for (int r = 0; r < 4; r++) o[j][r] = 0.f;

    const int ktmax = 2 * qt + 1;
    for (int kt = 0; kt <= ktmax; kt++) {
        const int st = kt & 1;
        if (kt < ktmax) {
            flash_prefetch(sb, st ^ 1, kt + 1, tid, Khb, Klb, Vthb, Vtlb);
            CP_COMMIT();
            CP_WAIT1();
        } else {
            CP_WAIT0();
        }
        __syncthreads();

        const uint32_t stg = sb + (uint32_t)(FSTG + st * FSTGSZ) * 2;
        const uint32_t kh_b = stg + (uint32_t)(brow * FS + bcol) * 2;
        const uint32_t kl_b = kh_b + 4608 * 2;
        const uint32_t vh_b = kh_b + 9216 * 2;
        const uint32_t vl_b = kh_b + 13824 * 2;

        // ---- S = Q K^T ----
        float s[8][4];
#pragma unroll
        for (int j = 0; j < 8; j++)
#pragma unroll
            for (int r = 0; r < 4; r++) s[j][r] = 0.f;

#pragma unroll
        for (int kk = 0; kk < 64; kk += 16) {
            uint32_t aH[4], aL[4];
            ldsm4(aH[0], aH[1], aH[2], aH[3], qh_a + (uint32_t)kk * 2);
            ldsm4(aL[0], aL[1], aL[2], aL[3], ql_a + (uint32_t)kk * 2);
#pragma unroll
            for (int jp = 0; jp < 4; jp++) {
                uint32_t h0, h1, h2, h3, lo0, lo1, lo2, lo3;
                ldsm4(h0, h1, h2, h3, kh_b + (uint32_t)(jp * 16 * FS + kk) * 2);
                ldsm4(lo0, lo1, lo2, lo3, kl_b + (uint32_t)(jp * 16 * FS + kk) * 2);
                mma16816(s[2*jp],   aH[0], aH[1], aH[2], aH[3], h0, h1);
                mma16816(s[2*jp],   aL[0], aL[1], aL[2], aL[3], h0, h1);
                mma16816(s[2*jp],   aH[0], aH[1], aH[2], aH[3], lo0, lo1);
                mma16816(s[2*jp+1], aH[0], aH[1], aH[2], aH[3], h2, h3);
                mma16816(s[2*jp+1], aL[0], aL[1], aL[2], aL[3], h2, h3);
                mma16816(s[2*jp+1], aH[0], aH[1], aH[2], aH[3], lo2, lo3);
            }
        }

        // ---- scale + causal mask ----
        const bool diag = (kt >= 2 * qt);
#pragma unroll
        for (int j = 0; j < 8; j++) {
#pragma unroll
            for (int r = 0; r < 4; r++) {
                s[j][r] *= 0.125f;
                if (diag) {
                    const int col = kt * 64 + j * 8 + 2 * t + (r & 1);
                    const int row = q0 + r0 + g + ((r >> 1) << 3);
                    if (col > row) s[j][r] = -INFINITY;
                }
            }
        }

        // ---- online softmax ----
        float mx0 = -INFINITY, mx1 = -INFINITY;
#pragma unroll
        for (int j = 0; j < 8; j++) {
            mx0 = fmaxf(mx0, fmaxf(s[j][0], s[j][1]));
            mx1 = fmaxf(mx1, fmaxf(s[j][2], s[j][3]));
        }
        mx0 = fmaxf(mx0, __shfl_xor_sync(0xffffffffu, mx0, 1));
        mx0 = fmaxf(mx0, __shfl_xor_sync(0xffffffffu, mx0, 2));
        mx1 = fmaxf(mx1, __shfl_xor_sync(0xffffffffu, mx1, 1));
        mx1 = fmaxf(mx1, __shfl_xor_sync(0xffffffffu, mx1, 2));
        const float mn0 = fmaxf(m0, mx0), mn1 = fmaxf(m1, mx1);
        const float al0 = __expf(m0 - mn0), al1 = __expf(m1 - mn1);
        m0 = mn0; m1 = mn1;
        float rs0 = 0.f, rs1 = 0.f;
#pragma unroll
        for (int j = 0; j < 8; j++) {
            s[j][0] = __expf(s[j][0] - m0);
            s[j][1] = __expf(s[j][1] - m0);
            s[j][2] = __expf(s[j][2] - m1);
            s[j][3] = __expf(s[j][3] - m1);
            rs0 += s[j][0] + s[j][1];
            rs1 += s[j][2] + s[j][3];
        }
        rs0 += __shfl_xor_sync(0xffffffffu, rs0, 1);
        rs0 += __shfl_xor_sync(0xffffffffu, rs0, 2);
        rs1 += __shfl_xor_sync(0xffffffffu, rs1, 1);
        rs1 += __shfl_xor_sync(0xffffffffu, rs1, 2);
        l0 = l0 * al0 + rs0;
        l1 = l1 * al1 + rs1;
#pragma unroll
        for (int j = 0; j < 8; j++) {
            o[j][0] *= al0; o[j][1] *= al0;
            o[j][2] *= al1; o[j][3] *= al1;
        }

        // ---- O += P V ----
#pragma unroll
        for (int u = 0; u < 4; u++) {
            uint32_t aPh[4], aPl[4];
            {
                __nv_bfloat16 h0, h1, h2, h3, lo0, lo1, lo2, lo3;
                bfsplit(s[2*u][0], h0, lo0);   bfsplit(s[2*u][1], h1, lo1);
                bfsplit(s[2*u][2], h2, lo2);   bfsplit(s[2*u][3], h3, lo3);
                aPh[0] = packbf(h0, h1);  aPl[0] = packbf(lo0, lo1);
                aPh[1] = packbf(h2, h3);  aPl[1] = packbf(lo2, lo3);
                bfsplit(s[2*u+1][0], h0, lo0); bfsplit(s[2*u+1][1], h1, lo1);
                bfsplit(s[2*u+1][2], h2, lo2); bfsplit(s[2*u+1][3], h3, lo3);
                aPh[2] = packbf(h0, h1);  aPl[2] = packbf(lo0, lo1);
                aPh[3] = packbf(h2, h3);  aPl[3] = packbf(lo2, lo3);
            }
#pragma unroll
            for (int jp = 0; jp < 4; jp++) {
                uint32_t h0, h1, h2, h3, lo0, lo1, lo2, lo3;
                ldsm4(h0, h1, h2, h3, vh_b + (uint32_t)(jp * 16 * FS + 16 * u) * 2);
                ldsm4(lo0, lo1, lo2, lo3, vl_b + (uint32_t)(jp * 16 * FS + 16 * u) * 2);
                mma16816(o[2*jp],   aPh[0], aPh[1], aPh[2], aPh[3], h0, h1);
                mma16816(o[2*jp],   aPl[0], aPl[1], aPl[2], aPl[3], h0, h1);
                mma16816(o[2*jp],   aPh[0], aPh[1], aPh[2], aPh[3], lo0, lo1);
                mma16816(o[2*jp+1], aPh[0], aPh[1], aPh[2], aPh[3], h2, h3);
                mma16816(o[2*jp+1], aPl[0], aPl[1], aPl[2], aPl[3], h2, h3);
                mma16816(o[2*jp+1], aPh[0], aPh[1], aPh[2], aPh[3], lo2, lo3);
            }
        }
        __syncthreads();
    }

    // ---- epilogue: normalize, add v_res, write attn as bf16 hi/lo pairs ----
    const float inv0 = 1.0f / l0, inv1 = 1.0f / l1;
#pragma unroll
    for (int j = 0; j < 8; j++) {
        const int col = h * 64 + j * 8 + 2 * t;
        {
            const int row = q0 + r0 + g;
            const size_t tok = (size_t)b * TSEQ + row;
            const float2 vr = *(const float2*)&vres[tok * 512 + col];
            __nv_bfloat16 h0, lo0, h1, lo1;
            bfsplit(o[j][0] * inv0 + vr.x, h0, lo0);
            bfsplit(o[j][1] * inv0 + vr.y, h1, lo1);
            *(uint32_t*)&g_ath[tok * 512 + col] = packbf(h0, h1);
            *(uint32_t*)&g_atl[tok * 512 + col] = packbf(lo0, lo1);
        }
        {
            const int row = q0 + r0 + g + 8;
            const size_t tok = (size_t)b * TSEQ + row;
            const float2 vr = *(const float2*)&vres[tok * 512 + col];
            __nv_bfloat16 h0, lo0, h1, lo1;
            bfsplit(o[j][2] * inv1 + vr.x, h0, lo0);
            bfsplit(o[j][3] * inv1 + vr.y, h1, lo1);
            *(uint32_t*)&g_ath[tok * 512 + col] = packbf(h0, h1);
            *(uint32_t*)&g_atl[tok * 512 + col] = packbf(lo0, lo1);
        }
    }
}

// ---------------- launch ----------------
extern "C" void kernel_launch(void* const* d_in, const int* in_sizes, int n_in,
                              void* d_out, int out_size) {
    const float* x     = (const float*)d_in[0];
    const float* W_DQ  = (const float*)d_in[1];
    const float* W_UQ  = (const float*)d_in[2];
    const float* W_QR  = (const float*)d_in[3];
    const float* W_DKV = (const float*)d_in[4];
    const float* W_UK  = (const float*)d_in[5];
    const float* W_UV  = (const float*)d_in[6];
    const float* W_KR  = (const float*)d_in[7];
    const float* W_VR  = (const float*)d_in[8];
    const float* W_O   = (const float*)d_in[9];
    const float* q_ln  = (const float*)d_in[10];
    const float* kv_ln = (const float*)d_in[11];
    const float* qhw   = (const float*)d_in[12];
    const float* khw   = (const float*)d_in[13];
    float* out = (float*)d_out;

    float *cq, *ckv, *krope, *vres, *qnope, *qrope, *knope;
    cudaGetSymbolAddress((void**)&cq,    g_cq);
    cudaGetSymbolAddress((void**)&ckv,   g_ckv);
    cudaGetSymbolAddress((void**)&krope, g_krope);
    cudaGetSymbolAddress((void**)&vres,  g_vres);
    cudaGetSymbolAddress((void**)&qnope, g_qnope);
    cudaGetSymbolAddress((void**)&qrope, g_qrope);
    cudaGetSymbolAddress((void**)&knope, g_knope);

    __nv_bfloat16 *xh, *xl, *cqh, *cql, *ckvh, *ckvl, *ath, *atl;
    __nv_bfloat16 *wdqh, *wdql, *wuqh, *wuql, *wqrh, *wqrl, *wdkvh, *wdkvl;
    __nv_bfloat16 *wukh, *wukl, *wuvh, *wuvl, *wkrh, *wkrl, *wvrh, *wvrl, *woh, *wol;
    float* vvp;
    cudaGetSymbolAddress((void**)&vvp, g_vv);
    cudaGetSymbolAddress((void**)&xh, g_xh);     cudaGetSymbolAddress((void**)&xl, g_xl);
    cudaGetSymbolAddress((void**)&cqh, g_cqh);   cudaGetSymbolAddress((void**)&cql, g_cql);
    cudaGetSymbolAddress((void**)&ckvh, g_ckvh); cudaGetSymbolAddress((void**)&ckvl, g_ckvl);
    cudaGetSymbolAddress((void**)&ath, g_ath);   cudaGetSymbolAddress((void**)&atl, g_atl);
    cudaGetSymbolAddress((void**)&wdqh, g_wdqh);   cudaGetSymbolAddress((void**)&wdql, g_wdql);
    cudaGetSymbolAddress((void**)&wuqh, g_wuqh);   cudaGetSymbolAddress((void**)&wuql, g_wuql);
    cudaGetSymbolAddress((void**)&wqrh, g_wqrh);   cudaGetSymbolAddress((void**)&wqrl, g_wqrl);
    cudaGetSymbolAddress((void**)&wdkvh, g_wdkvh); cudaGetSymbolAddress((void**)&wdkvl, g_wdkvl);
    cudaGetSymbolAddress((void**)&wukh, g_wukh);   cudaGetSymbolAddress((void**)&wukl, g_wukl);
    cudaGetSymbolAddress((void**)&wuvh, g_wuvh);   cudaGetSymbolAddress((void**)&wuvl, g_wuvl);
    cudaGetSymbolAddress((void**)&wkrh, g_wkrh);   cudaGetSymbolAddress((void**)&wkrl, g_wkrl);
    cudaGetSymbolAddress((void**)&wvrh, g_wvrh);   cudaGetSymbolAddress((void**)&wvrl, g_wvrl);
    cudaGetSymbolAddress((void**)&woh, g_woh);     cudaGetSymbolAddress((void**)&wol, g_wol);

    cudaFuncSetAttribute(flash, cudaFuncAttributeMaxDynamicSharedMemorySize, FL_SMEM);
    cudaFuncSetAttribute(hgemm_bs, cudaFuncAttributeMaxDynamicSharedMemorySize, GB_SMEM);

    // ---- pre-split inputs & weights ----
    asplit<<<(NTOK * 512 / 4 + 255) / 256, 256>>>(x, xh, xl, NTOK * 512 / 4);
    wsplit_t<<<dim3(256 / 32, 512 / 32), 256>>>(W_DQ,  wdqh,  wdql,  512, 256);
    wsplit_t<<<dim3(256 / 32, 256 / 32), 256>>>(W_UQ,  wuqh,  wuql,  256, 256);
    wsplit_t<<<dim3(256 / 32, 256 / 32), 256>>>(W_QR,  wqrh,  wqrl,  256, 256);
    wsplit_t<<<dim3(128 / 32, 512 / 32), 256>>>(W_DKV, wdkvh, wdkvl, 512, 128);
    wsplit_t<<<dim3( 64 / 32, 128 / 32), 256>>>(W_UK,  wukh,  wukl,  128,  64);
    wsplit_t<<<dim3(128 / 32, 128 / 32), 256>>>(W_UV,  wuvh,  wuvl,  128, 128);
    wsplit_t<<<dim3( 64 / 32, 512 / 32), 256>>>(W_KR,  wkrh,  wkrl,  512,  64);
    wsplit_t<<<dim3(512 / 32, 512 / 32), 256>>>(W_VR,  wvrh,  wvrl,  512, 512);
    wsplit_t<<<dim3(512 / 32, 512 / 32), 256>>>(W_O,   woh,   wol,   512, 512);

#define GEMMB(Ah, Al, Bh, Bl, Cm, Mv, Nv, Kv) \
    hgemm_bs<<<dim3((Nv) / 64, (Mv) / 128), 256, GB_SMEM>>>(Ah, Al, Bh, Bl, Cm, Mv, Nv, Kv)

    // x projections
    GEMMB(xh, xl, wdqh,  wdql,  cq,    NTOK, 256, 512);
    GEMMB(xh, xl, wdkvh, wdkvl, ckv,   NTOK, 128, 512);
    GEMMB(xh, xl, wkrh,  wkrl,  krope, NTOK,  64, 512);
    GEMMB(xh, xl, wvrh,  wvrl,  vres,  NTOK, 512, 512);

    // latent RMS norms (+ split)
    rms_split<<<NTOK, 256>>>(cq,  q_ln,  cqh,  cql,  256);
    rms_split<<<NTOK, 128>>>(ckv, kv_ln, ckvh, ckvl, 128);

    // up-projections
    GEMMB(cqh,  cql,  wuqh, wuql, qnope, NTOK, 256, 256);
    GEMMB(cqh,  cql,  wqrh, wqrl, qrope, NTOK, 256, 256);
    GEMMB(ckvh, ckvl, wukh, wukl, knope, NTOK,  64, 128);
    GEMMB(ckvh, ckvl, wuvh, wuvl, vvp,   NTOK, 128, 128);

    // rope + concat + head-RMS + split; V transpose+split
    assemble<<<NTOK, 256>>>(qhw, khw);
    vtrans<<<dim3(BATCH * NKVH, TSEQ / 64), 256>>>();

    // causal flash attention + v_res (ldmatrix fragment loads)
    flash<<<dim3(TSEQ / 128, BATCH * NHEADS), 256, FL_SMEM>>>(vres);

    // output projection
    GEMMB(ath, atl, woh, wol, out, NTOK, 512, 512);
}

// round 12
// speedup vs baseline: 2.7531x; 1.0664x over previous
#include <cuda_runtime.h>
#include <cuda_bf16.h>
#include <math.h>
#include <stdint.h>

#define NHEADS 8
#define NKVH   2
#define HDIM   64
#define TSEQ   2048
#define BATCH  4
#define NTOK   (BATCH*TSEQ)   /* 8192 */

// ---------------- scratch (device globals; no allocation allowed) ----------------
// fused fp32 GEMM outputs
__device__ float g_xo[NTOK*960];   // [cq 0:256 | ckv 256:384 | krope 384:448 | vres 448:960]
__device__ float g_qo[NTOK*512];   // [qnope 0:256 | qrope 256:512]
__device__ float g_ko[NTOK*192];   // [knope 0:64 | vv 64:192]
// pre-split bf16 hi/lo activations
__device__ __nv_bfloat16 g_xh  [NTOK*512], g_xl  [NTOK*512];
__device__ __nv_bfloat16 g_cqh [NTOK*256], g_cql [NTOK*256];
__device__ __nv_bfloat16 g_ckvh[NTOK*128], g_ckvl[NTOK*128];
__device__ __nv_bfloat16 g_ath [NTOK*512], g_atl [NTOK*512];
// pre-split, pre-transposed [N,K] fused weights
__device__ __nv_bfloat16 g_wxh [960*512], g_wxl [960*512];
__device__ __nv_bfloat16 g_wqh [512*256], g_wql [512*256];
__device__ __nv_bfloat16 g_wkvh[192*128], g_wkvl[192*128];
__device__ __nv_bfloat16 g_woh [512*512], g_wol [512*512];
// flash operands
__device__ __nv_bfloat16 g_qh [BATCH*NHEADS*TSEQ*HDIM];
__device__ __nv_bfloat16 g_ql [BATCH*NHEADS*TSEQ*HDIM];
__device__ __nv_bfloat16 g_kh [BATCH*NKVH*TSEQ*HDIM];
__device__ __nv_bfloat16 g_kl [BATCH*NKVH*TSEQ*HDIM];
__device__ __nv_bfloat16 g_vth[BATCH*NKVH*HDIM*TSEQ];
__device__ __nv_bfloat16 g_vtl[BATCH*NKVH*HDIM*TSEQ];

__device__ __forceinline__ uint32_t packbf(__nv_bfloat16 a, __nv_bfloat16 b) {
    return ((uint32_t)__bfloat16_as_ushort(b) << 16) | (uint32_t)__bfloat16_as_ushort(a);
}
__device__ __forceinline__ void mma16816(float* c, uint32_t a0, uint32_t a1,
                                         uint32_t a2, uint32_t a3,
                                         uint32_t b0, uint32_t b1) {
    asm volatile(
        "mma.sync.aligned.m16n8k16.row.col.f32.bf16.bf16.f32 "
        "{%0,%1,%2,%3}, {%4,%5,%6,%7}, {%8,%9}, {%0,%1,%2,%3};"
        : "+f"(c[0]), "+f"(c[1]), "+f"(c[2]), "+f"(c[3])
        : "r"(a0), "r"(a1), "r"(a2), "r"(a3), "r"(b0), "r"(b1));
}
__device__ __forceinline__ void ldsm4(uint32_t& r0, uint32_t& r1, uint32_t& r2,
                                      uint32_t& r3, uint32_t addr) {
    asm volatile("ldmatrix.sync.aligned.m8n8.x4.shared.b16 {%0,%1,%2,%3}, [%4];"
                 : "=r"(r0), "=r"(r1), "=r"(r2), "=r"(r3) : "r"(addr));
}
__device__ __forceinline__ void bfsplit(float v, __nv_bfloat16& h, __nv_bfloat16& l) {
    h = __float2bfloat16(v);
    l = __float2bfloat16(v - __bfloat162float(h));
}
__device__ __forceinline__ float fexp2(float x) {
    float y;
    asm("ex2.approx.f32 %0, %1;" : "=f"(y) : "f"(x));
    return y;
}
__device__ __forceinline__ uint32_t smem_u32(const void* p) {
    uint32_t a;
    asm("{ .reg .u64 t; cvta.to.shared.u64 t, %1; cvt.u32.u64 %0, t; }" : "=r"(a) : "l"(p));
    return a;
}
__device__ __forceinline__ void cpa16(uint32_t dst, const void* src) {
    asm volatile("cp.async.ca.shared.global [%0], [%1], 16;" :: "r"(dst), "l"(src) : "memory");
}
#define CP_COMMIT() asm volatile("cp.async.commit_group;" ::: "memory")
#define CP_WAIT0()  asm volatile("cp.async.wait_group 0;" ::: "memory")

// ---------------- split helpers ----------------
__global__ void asplit(const float* __restrict__ X, __nv_bfloat16* __restrict__ Xh,
                       __nv_bfloat16* __restrict__ Xl, int n4) {
    const int i = blockIdx.x * blockDim.x + threadIdx.x;
    if (i >= n4) return;
    const float4 v = ((const float4*)X)[i];
    __nv_bfloat16 h0, h1, h2, h3, l0, l1, l2, l3;
    bfsplit(v.x, h0, l0); bfsplit(v.y, h1, l1);
    bfsplit(v.z, h2, l2); bfsplit(v.w, h3, l3);
    ((uint2*)Xh)[i] = make_uint2(packbf(h0, h1), packbf(h2, h3));
    ((uint2*)Xl)[i] = make_uint2(packbf(l0, l1), packbf(l2, l3));
}

// W [K,N] fp32 -> Wh/Wl [N,K] bf16 (transpose + split); caller pre-offsets Wh/Wl rows.
__global__ void wsplit_t(const float* __restrict__ W, __nv_bfloat16* __restrict__ Wh,
                         __nv_bfloat16* __restrict__ Wl, int K, int N) {
    __shared__ float tile[32][33];
    const int k0 = blockIdx.y * 32, n0 = blockIdx.x * 32;
    const int tid = threadIdx.x;
    for (int i = tid; i < 1024; i += 256) {
        const int r = i >> 5, c = i & 31;
        tile[r][c] = W[(size_t)(k0 + r) * N + n0 + c];
    }
    __syncthreads();
    for (int i = tid; i < 1024; i += 256) {
        const int n = i >> 5, k = i & 31;
        __nv_bfloat16 h, l;
        bfsplit(tile[k][n], h, l);
        Wh[(size_t)(n0 + n) * K + k0 + k] = h;
        Wl[(size_t)(n0 + n) * K + k0 + k] = l;
    }
}

// RMSNorm over D elems at row stride ldx, column offset off -> bf16 hi/lo
__global__ void rms_split(const float* __restrict__ X, const float* __restrict__ w,
                          __nv_bfloat16* __restrict__ Xh, __nv_bfloat16* __restrict__ Xl,
                          int D, int ldx, int off) {
    const int n = blockIdx.x;
    const float* row = X + (size_t)n * ldx + off;
    const int tid = threadIdx.x;
    const float v = row[tid];
    float ss = v * v;
#pragma unroll
    for (int o = 16; o > 0; o >>= 1) ss += __shfl_xor_sync(0xffffffffu, ss, o);
    __shared__ float sh[8];
    const int wid = tid >> 5, nw = blockDim.x >> 5;
    if ((tid & 31) == 0) sh[wid] = ss;
    __syncthreads();
    float tot = 0.f;
    for (int i = 0; i < nw; i++) tot += sh[i];
    const float scale = rsqrtf(tot / (float)D + 1e-6f);
    __nv_bfloat16 h, l;
    bfsplit(v * scale * w[tid], h, l);
    Xh[(size_t)n * D + tid] = h;
    Xl[(size_t)n * D + tid] = l;
}

// ---------------- bf16x3 HMMA GEMM, pre-split, cp.async + ldmatrix, 1 sync/chunk ----
#define GS 72
#define GB_AH 0
#define GB_AL 9216
#define GB_BH 18432
#define GB_BL 23040
#define GB_STG 27648
#define GB_SMEM (2 * GB_STG * 2)        /* 110592 bytes */

extern __shared__ char gsm[];

__device__ __forceinline__ void gemm_prefetch(uint32_t sb, int stage, int c64, int tid,
        const __nv_bfloat16* Ah, const __nv_bfloat16* Al,
        const __nv_bfloat16* Bh, const __nv_bfloat16* Bl,
        int m0, int n0, int K) {
    const int base = stage * GB_STG;
#pragma unroll
    for (int i = tid; i < 2048; i += 256) {
        const int half = i >> 10;
        const int r = (i >> 3) & 127;
        const int cc = i & 7;
        const uint32_t dst = sb + (uint32_t)(base + (half ? GB_AL : GB_AH) + r * GS + cc * 8) * 2;
        const __nv_bfloat16* src = (half ? Al : Ah) + (size_t)(m0 + r) * K + c64 + cc * 8;
        cpa16(dst, src);
    }
#pragma unroll
    for (int i = tid; i < 1024; i += 256) {
        const int half = i >> 9;
        const int r = (i >> 3) & 63;
        const int cc = i & 7;
        const uint32_t dst = sb + (uint32_t)(base + (half ? GB_BL : GB_BH) + r * GS + cc * 8) * 2;
        const __nv_bfloat16* src = (half ? Bl : Bh) + (size_t)(n0 + r) * K + c64 + cc * 8;
        cpa16(dst, src);
    }
}

__global__ __launch_bounds__(256) void hgemm_bs(
        const __nv_bfloat16* __restrict__ Ah, const __nv_bfloat16* __restrict__ Al,
        const __nv_bfloat16* __restrict__ Bh, const __nv_bfloat16* __restrict__ Bl,
        float* __restrict__ C, int M, int N, int K, int ldc) {
    const uint32_t sb = smem_u32(gsm);

    const int tid = threadIdx.x, wid = tid >> 5, lane = tid & 31;
    const int wm = wid & 3, wn = wid >> 2;
    const int g = lane >> 2, t = lane & 3;
    const int m0 = blockIdx.y * 128, n0 = blockIdx.x * 64;

    const int arow = ((lane >> 3) & 1) * 8 + (lane & 7);
    const int acol = (lane >> 4) << 3;
    const int brow = ((lane >> 4) << 3) + (lane & 7);
    const int bcol = ((lane >> 3) & 1) * 8;

    float acc[2][4][4];
#pragma unroll
    for (int i = 0; i < 2; i++)
#pragma unroll
        for (int j = 0; j < 4; j++)
#pragma unroll
            for (int r = 0; r < 4; r++) acc[i][j][r] = 0.f;

    const int nch = K >> 6;
    gemm_prefetch(sb, 0, 0, tid, Ah, Al, Bh, Bl, m0, n0, K);
    CP_COMMIT();

    for (int c = 0; c < nch; c++) {
        const int st = c & 1;
        CP_WAIT0();
        __syncthreads();
        if (c + 1 < nch) {
            gemm_prefetch(sb, st ^ 1, (c + 1) << 6, tid, Ah, Al, Bh, Bl, m0, n0, K);
            CP_COMMIT();
        }

        const uint32_t stg = sb + (uint32_t)(st * GB_STG) * 2;
        const uint32_t aH_b = stg + (uint32_t)(GB_AH + (wm * 32 + arow) * GS + acol) * 2;
        const uint32_t aL_b = stg + (uint32_t)(GB_AL + (wm * 32 + arow) * GS + acol) * 2;
        const uint32_t bH_b = stg + (uint32_t)(GB_BH + (wn * 32 + brow) * GS + bcol) * 2;
        const uint32_t bL_b = stg + (uint32_t)(GB_BL + (wn * 32 + brow) * GS + bcol) * 2;

#pragma unroll
        for (int kk = 0; kk < 64; kk += 16) {
            uint32_t ah[2][4], al[2][4];
#pragma unroll
            for (int i = 0; i < 2; i++) {
                ldsm4(ah[i][0], ah[i][1], ah[i][2], ah[i][3],
                      aH_b + (uint32_t)(i * 16 * GS + kk) * 2);
                ldsm4(al[i][0], al[i][1], al[i][2], al[i][3],
                      aL_b + (uint32_t)(i * 16 * GS + kk) * 2);
            }
#pragma unroll
            for (int jp = 0; jp < 2; jp++) {
                uint32_t h0, h1, h2, h3, l0, l1, l2, l3;
                ldsm4(h0, h1, h2, h3, bH_b + (uint32_t)(jp * 16 * GS + kk) * 2);
                ldsm4(l0, l1, l2, l3, bL_b + (uint32_t)(jp * 16 * GS + kk) * 2);
#pragma unroll
                for (int i = 0; i < 2; i++) {
                    mma16816(acc[i][2*jp],   ah[i][0], ah[i][1], ah[i][2], ah[i][3], h0, h1);
                    mma16816(acc[i][2*jp],   al[i][0], al[i][1], al[i][2], al[i][3], h0, h1);
                    mma16816(acc[i][2*jp],   ah[i][0], ah[i][1], ah[i][2], ah[i][3], l0, l1);
                    mma16816(acc[i][2*jp+1], ah[i][0], ah[i][1], ah[i][2], ah[i][3], h2, h3);
                    mma16816(acc[i][2*jp+1], al[i][0], al[i][1], al[i][2], al[i][3], h2, h3);
                    mma16816(acc[i][2*jp+1], ah[i][0], ah[i][1], ah[i][2], ah[i][3], l2, l3);
                }
            }
        }
    }

#pragma unroll
    for (int i = 0; i < 2; i++)
#pragma unroll
        for (int j = 0; j < 4; j++) {
            const int row = m0 + wm * 32 + i * 16 + g;
            const int col = n0 + wn * 32 + j * 8 + 2 * t;
            *(float2*)&C[(size_t)row * ldc + col]       = make_float2(acc[i][j][0], acc[i][j][1]);
            *(float2*)&C[(size_t)(row + 8) * ldc + col] = make_float2(acc[i][j][2], acc[i][j][3]);
        }
}

// ---------------- RoPE + concat + per-head RMS -> bf16 hi/lo [B,h,T,64] ----------------
__global__ __launch_bounds__(256) void assemble(const float* __restrict__ qhw,
                                                const float* __restrict__ khw) {
    const int n = blockIdx.x;
    const int b = n / TSEQ, t = n % TSEQ;
    const int tid = threadIdx.x, w = tid >> 5, l = tid & 31;

    const int j = l & 15;
    const float invf = powf(500000.0f, -(float)j / 16.0f);
    const float f = (float)t * invf;
    const float cs = cosf(f), sn = sinf(f);

    {
        const int h = w;
        float v0 = g_qo[(size_t)n * 512 + h * 32 + l];
        const float* qr = &g_qo[(size_t)n * 512 + 256 + h * 32];
        float a = qr[l];
        float v1 = (l < 16) ? (a * cs - qr[l + 16] * sn) : (a * cs + qr[l - 16] * sn);
        float ss = v0 * v0 + v1 * v1;
#pragma unroll
        for (int o = 16; o > 0; o >>= 1) ss += __shfl_xor_sync(0xffffffffu, ss, o);
        float scale = rsqrtf(ss / 64.0f + 1e-6f);
        const size_t base = (((size_t)b * NHEADS + h) * TSEQ + t) * HDIM;
        __nv_bfloat16 hh, ll;
        bfsplit(v0 * scale * qhw[l], hh, ll);
        g_qh[base + l] = hh; g_ql[base + l] = ll;
        bfsplit(v1 * scale * qhw[32 + l], hh, ll);
        g_qh[base + 32 + l] = hh; g_ql[base + 32 + l] = ll;
    }
    if (w < 2) {
        const int kvh = w;
        float v0 = g_ko[(size_t)n * 192 + kvh * 32 + l];
        const float* kr = &g_xo[(size_t)n * 960 + 384 + kvh * 32];
        float a = kr[l];
        float v1 = (l < 16) ? (a * cs - kr[l + 16] * sn) : (a * cs + kr[l - 16] * sn);
        float ss = v0 * v0 + v1 * v1;
#pragma unroll
        for (int o = 16; o > 0; o >>= 1) ss += __shfl_xor_sync(0xffffffffu, ss, o);
        float scale = rsqrtf(ss / 64.0f + 1e-6f);
        const size_t base = (((size_t)b * NKVH + kvh) * TSEQ + t) * HDIM;
        __nv_bfloat16 hh, ll;
        bfsplit(v0 * scale * khw[l], hh, ll);
        g_kh[base + l] = hh; g_kl[base + l] = ll;
        bfsplit(v1 * scale * khw[32 + l], hh, ll);
        g_kh[base + 32 + l] = hh; g_kl[base + 32 + l] = ll;
    }
}

// ---------------- V transpose + split (reads fused up-kv output) ----------------
__global__ __launch_bounds__(256) void vtrans() {
    __shared__ __nv_bfloat16 sh[64][65], sl[64][65];
    const int bk = blockIdx.x;
    const int b = bk >> 1, kvh = bk & 1;
    const int t0 = blockIdx.y * 64;
    const int tid = threadIdx.x;
    for (int i = tid; i < 4096; i += 256) {
        const int tt = i >> 6, d = i & 63;
        float v = g_ko[(size_t)(b * TSEQ + t0 + tt) * 192 + 64 + kvh * 64 + d];
        __nv_bfloat16 hh, ll;
        bfsplit(v, hh, ll);
        sh[tt][d] = hh; sl[tt][d] = ll;
    }
    __syncthreads();
    for (int i = tid; i < 4096; i += 256) {
        const int d = i >> 6, tt = i & 63;
        g_vth[((size_t)bk * 64 + d) * TSEQ + t0 + tt] = sh[tt][d];
        g_vtl[((size_t)bk * 64 + d) * TSEQ + t0 + tt] = sl[tt][d];
    }
}

// ---------------- HMMA causal flash attention, BM=128, BN=64, d=64 ----------------
#define FS 72
#define FQH 0
#define FQL 9216
#define FSTG 18432
#define FSTGSZ 18432
#define FL_SMEM ((FSTG + 2 * FSTGSZ) * 2)   /* 110592 bytes */
#define SCL2 0.18033688011112042f          /* 0.125 * log2(e) */

__device__ __forceinline__ void flash_prefetch(uint32_t sb, int stage, int kt, int tid,
        const __nv_bfloat16* Khb, const __nv_bfloat16* Klb,
        const __nv_bfloat16* Vthb, const __nv_bfloat16* Vtlb) {
    const int base = FSTG + stage * FSTGSZ;
#pragma unroll
    for (int i = tid; i < 2048; i += 256) {
        const int arr = i >> 9;
        const int r = (i >> 3) & 63;
        const int c = i & 7;
        const uint32_t dst = sb + (uint32_t)(base + arr * 4608 + r * FS + c * 8) * 2;
        const __nv_bfloat16* src;
        if (arr == 0)      src = Khb + ((size_t)(kt * 64 + r)) * 64 + c * 8;
        else if (arr == 1) src = Klb + ((size_t)(kt * 64 + r)) * 64 + c * 8;
        else if (arr == 2) src = Vthb + (size_t)r * TSEQ + kt * 64 + c * 8;
        else               src = Vtlb + (size_t)r * TSEQ + kt * 64 + c * 8;
        cpa16(dst, src);
    }
}

__global__ __launch_bounds__(256) void flash(const float* __restrict__ xo) {
    const uint32_t sb = smem_u32(gsm);

    const int qt = gridDim.x - 1 - blockIdx.x;
    const int bh = blockIdx.y;
    const int b = bh >> 3, h = bh & 7, kvh = h >> 2;
    const int q0 = qt * 128;

    const int tid = threadIdx.x, wid = tid >> 5, lane = tid & 31;
    const int g = lane >> 2, t = lane & 3;
    const int r0 = wid * 16;

    const int arow = ((lane >> 3) & 1) * 8 + (lane & 7);
    const int acol = (lane >> 4) << 3;
    const int brow = ((lane >> 4) << 3) + (lane & 7);
    const int bcol = ((lane >> 3) & 1) * 8;
    const uint32_t qh_a = sb + (uint32_t)(FQH + (r0 + arow) * FS + acol) * 2;
    const uint32_t ql_a = sb + (uint32_t)(FQL + (r0 + arow) * FS + acol) * 2;

    const __nv_bfloat16* Qhb = &g_qh[(((size_t)b * NHEADS + h) * TSEQ + q0) * HDIM];
    const __nv_bfloat16* Qlb = &g_ql[(((size_t)b * NHEADS + h) * TSEQ + q0) * HDIM];
    const __nv_bfloat16* Khb = &g_kh[(((size_t)b * NKVH + kvh) * TSEQ) * HDIM];
    const __nv_bfloat16* Klb = &g_kl[(((size_t)b * NKVH + kvh) * TSEQ) * HDIM];
    const __nv_bfloat16* Vthb = &g_vth[(((size_t)b * NKVH + kvh) * HDIM) * TSEQ];
    const __nv_bfloat16* Vtlb = &g_vtl[(((size_t)b * NKVH + kvh) * HDIM) * TSEQ];

#pragma unroll
    for (int i = tid; i < 2048; i += 256) {
        const int half = i >> 10;
        const int r = (i >> 3) & 127;
        const int c = i & 7;
        const uint32_t dst = sb + (uint32_t)((half ? FQL : FQH) + r * FS + c * 8) * 2;
        const __nv_bfloat16* src = (half ? Qlb : Qhb) + (size_t)r * 64 + c * 8;
        cpa16(dst, src);
    }
    flash_prefetch(sb, 0, 0, tid, Khb, Klb, Vthb, Vtlb);
    CP_COMMIT();

    float m0 = -INFINITY, m1 = -INFINITY, l0 = 0.f, l1 = 0.f;
    float o[8][4];
#pragma unroll
    for (int j = 0; j < 8; j++)
#pragma unroll
        for (int r = 0; r < 4; r++) o[j][r] = 0.f;

    const int ktmax = 2 * qt + 1;
    for (int kt = 0; kt <= ktmax; kt++) {
        const int st = kt & 1;
        CP_WAIT0();
        __syncthreads();
        if (kt < ktmax) {
            flash_prefetch(sb, st ^ 1, kt + 1, tid, Khb, Klb, Vthb, Vtlb);
            CP_COMMIT();
        }

        const uint32_t stg = sb + (uint32_t)(FSTG + st * FSTGSZ) * 2;
        const uint32_t kh_b = stg + (uint32_t)(brow * FS + bcol) * 2;
        const uint32_t kl_b = kh_b + 4608 * 2;
        const uint32_t vh_b = kh_b + 9216 * 2;
        const uint32_t vl_b = kh_b + 13824 * 2;

        // ---- S = Q K^T ----
        float s[8][4];
#pragma unroll
        for (int j = 0; j < 8; j++)
#pragma unroll
            for (int r = 0; r < 4; r++) s[j][r] = 0.f;

#pragma unroll
        for (int kk = 0; kk < 64; kk += 16) {
            uint32_t aH[4], aL[4];
            ldsm4(aH[0], aH[1], aH[2], aH[3], qh_a + (uint32_t)kk * 2);
            ldsm4(aL[0], aL[1], aL[2], aL[3], ql_a + (uint32_t)kk * 2);
#pragma unroll
            for (int jp = 0; jp < 4; jp++) {
                uint32_t h0, h1, h2, h3, lo0, lo1, lo2, lo3;
                ldsm4(h0, h1, h2, h3, kh_b + (uint32_t)(jp * 16 * FS + kk) * 2);
                ldsm4(lo0, lo1, lo2, lo3, kl_b + (uint32_t)(jp * 16 * FS + kk) * 2);
                mma16816(s[2*jp],   aH[0], aH[1], aH[2], aH[3], h0, h1);
                mma16816(s[2*jp],   aL[0], aL[1], aL[2], aL[3], h0, h1);
                mma16816(s[2*jp],   aH[0], aH[1], aH[2], aH[3], lo0, lo1);
                mma16816(s[2*jp+1], aH[0], aH[1], aH[2], aH[3], h2, h3);
                mma16816(s[2*jp+1], aL[0], aL[1], aL[2], aL[3], h2, h3);
                mma16816(s[2*jp+1], aH[0], aH[1], aH[2], aH[3], lo2, lo3);
            }
        }

        // ---- scale (into log2 domain) + causal mask ----
        const bool diag = (kt >= 2 * qt);
#pragma unroll
        for (int j = 0; j < 8; j++) {
#pragma unroll
            for (int r = 0; r < 4; r++) {
                s[j][r] *= SCL2;
                if (diag) {
                    const int col = kt * 64 + j * 8 + 2 * t + (r & 1);
                    const int row = q0 + r0 + g + ((r >> 1) << 3);
                    if (col > row) s[j][r] = -INFINITY;
                }
            }
        }

        // ---- online softmax (base-2) ----
        float mx0 = -INFINITY, mx1 = -INFINITY;
#pragma unroll
        for (int j = 0; j < 8; j++) {
            mx0 = fmaxf(mx0, fmaxf(s[j][0], s[j][1]));
            mx1 = fmaxf(mx1, fmaxf(s[j][2], s[j][3]));
        }
        mx0 = fmaxf(mx0, __shfl_xor_sync(0xffffffffu, mx0, 1));
        mx0 = fmaxf(mx0, __shfl_xor_sync(0xffffffffu, mx0, 2));
        mx1 = fmaxf(mx1, __shfl_xor_sync(0xffffffffu, mx1, 1));
        mx1 = fmaxf(mx1, __shfl_xor_sync(0xffffffffu, mx1, 2));
        const float mn0 = fmaxf(m0, mx0), mn1 = fmaxf(m1, mx1);
        const float al0 = fexp2(m0 - mn0), al1 = fexp2(m1 - mn1);
        m0 = mn0; m1 = mn1;
        float rs0 = 0.f, rs1 = 0.f;
#pragma unroll
        for (int j = 0; j < 8; j++) {
            s[j][0] = fexp2(s[j][0] - m0);
            s[j][1] = fexp2(s[j][1] - m0);
            s[j][2] = fexp2(s[j][2] - m1);
            s[j][3] = fexp2(s[j][3] - m1);
            rs0 += s[j][0] + s[j][1];
            rs1 += s[j][2] + s[j][3];
        }
        rs0 += __shfl_xor_sync(0xffffffffu, rs0, 1);
        rs0 += __shfl_xor_sync(0xffffffffu, rs0, 2);
        rs1 += __shfl_xor_sync(0xffffffffu, rs1, 1);
        rs1 += __shfl_xor_sync(0xffffffffu, rs1, 2);
        l0 = l0 * al0 + rs0;
        l1 = l1 * al1 + rs1;
#pragma unroll
        for (int j = 0; j < 8; j++) {
            o[j][0] *= al0; o[j][1] *= al0;
            o[j][2] *= al1; o[j][3] *= al1;
        }

        // ---- O += P V ----
#pragma unroll
        for (int u = 0; u < 4; u++) {
            uint32_t aPh[4], aPl[4];
            {
                __nv_bfloat16 h0, h1, h2, h3, lo0, lo1, lo2, lo3;
                bfsplit(s[2*u][0], h0, lo0);   bfsplit(s[2*u][1], h1, lo1);
                bfsplit(s[2*u][2], h2, lo2);   bfsplit(s[2*u][3], h3, lo3);
                aPh[0] = packbf(h0, h1);  aPl[0] = packbf(lo0, lo1);
                aPh[1] = packbf(h2, h3);  aPl[1] = packbf(lo2, lo3);
                bfsplit(s[2*u+1][0], h0, lo0); bfsplit(s[2*u+1][1], h1, lo1);
                bfsplit(s[2*u+1][2], h2, lo2); bfsplit(s[2*u+1][3], h3, lo3);
                aPh[2] = packbf(h0, h1);  aPl[2] = packbf(lo0, lo1);
                aPh[3] = packbf(h2, h3);  aPl[3] = packbf(lo2, lo3);
            }
#pragma unroll
            for (int jp = 0; jp < 4; jp++) {
                uint32_t h0, h1, h2, h3, lo0, lo1, lo2, lo3;
                ldsm4(h0, h1, h2, h3, vh_b + (uint32_t)(jp * 16 * FS + 16 * u) * 2);
                ldsm4(lo0, lo1, lo2, lo3, vl_b + (uint32_t)(jp * 16 * FS + 16 * u) * 2);
                mma16816(o[2*jp],   aPh[0], aPh[1], aPh[2], aPh[3], h0, h1);
                mma16816(o[2*jp],   aPl[0], aPl[1], aPl[2], aPl[3], h0, h1);
                mma16816(o[2*jp],   aPh[0], aPh[1], aPh[2], aPh[3], lo0, lo1);
                mma16816(o[2*jp+1], aPh[0], aPh[1], aPh[2], aPh[3], h2, h3);
                mma16816(o[2*jp+1], aPl[0], aPl[1], aPl[2], aPl[3], h2, h3);
                mma16816(o[2*jp+1], aPh[0], aPh[1], aPh[2], aPh[3], lo2, lo3);
            }
        }
    }

    // ---- epilogue: normalize, add v_res (fused cols 448+), write attn pre-split ----
    const float inv0 = 1.0f / l0, inv1 = 1.0f / l1;
#pragma unroll
    for (int j = 0; j < 8; j++) {
        const int col = h * 64 + j * 8 + 2 * t;
        {
            const int row = q0 + r0 + g;
            const size_t tok = (size_t)b * TSEQ + row;
            const float2 vr = *(const float2*)&xo[tok * 960 + 448 + col];
            __nv_bfloat16 h0, lo0, h1, lo1;
            bfsplit(o[j][0] * inv0 + vr.x, h0, lo0);
            bfsplit(o[j][1] * inv0 + vr.y, h1, lo1);
            *(uint32_t*)&g_ath[tok * 512 + col] = packbf(h0, h1);
            *(uint32_t*)&g_atl[tok * 512 + col] = packbf(lo0, lo1);
        }
        {
            const int row = q0 + r0 + g + 8;
            const size_t tok = (size_t)b * TSEQ + row;
            const float2 vr = *(const float2*)&xo[tok * 960 + 448 + col];
            __nv_bfloat16 h0, lo0, h1, lo1;
            bfsplit(o[j][2] * inv1 + vr.x, h0, lo0);
            bfsplit(o[j][3] * inv1 + vr.y, h1, lo1);
            *(uint32_t*)&g_ath[tok * 512 + col] = packbf(h0, h1);
            *(uint32_t*)&g_atl[tok * 512 + col] = packbf(lo0, lo1);
        }
    }
}

// ---------------- launch ----------------
extern "C" void kernel_launch(void* const* d_in, const int* in_sizes, int n_in,
                              void* d_out, int out_size) {
    const float* x     = (const float*)d_in[0];
    const float* W_DQ  = (const float*)d_in[1];
    const float* W_UQ  = (const float*)d_in[2];
    const float* W_QR  = (const float*)d_in[3];
    const float* W_DKV = (const float*)d_in[4];
    const float* W_UK  = (const float*)d_in[5];
    const float* W_UV  = (const float*)d_in[6];
    const float* W_KR  = (const float*)d_in[7];
    const float* W_VR  = (const float*)d_in[8];
    const float* W_O   = (const float*)d_in[9];
    const float* q_ln  = (const float*)d_in[10];
    const float* kv_ln = (const float*)d_in[11];
    const float* qhw   = (const float*)d_in[12];
    const float* khw   = (const float*)d_in[13];
    float* out = (float*)d_out;

    float *xo, *qo, *ko;
    cudaGetSymbolAddress((void**)&xo, g_xo);
    cudaGetSymbolAddress((void**)&qo, g_qo);
    cudaGetSymbolAddress((void**)&ko, g_ko);

    __nv_bfloat16 *xh, *xl, *cqh, *cql, *ckvh, *ckvl, *ath, *atl;
    __nv_bfloat16 *wxh, *wxl, *wqh, *wql, *wkvh, *wkvl, *woh, *wol;
    cudaGetSymbolAddress((void**)&xh, g_xh);     cudaGetSymbolAddress((void**)&xl, g_xl);
    cudaGetSymbolAddress((void**)&cqh, g_cqh);   cudaGetSymbolAddress((void**)&cql, g_cql);
    cudaGetSymbolAddress((void**)&ckvh, g_ckvh); cudaGetSymbolAddress((void**)&ckvl, g_ckvl);
    cudaGetSymbolAddress((void**)&ath, g_ath);   cudaGetSymbolAddress((void**)&atl, g_atl);
    cudaGetSymbolAddress((void**)&wxh, g_wxh);   cudaGetSymbolAddress((void**)&wxl, g_wxl);
    cudaGetSymbolAddress((void**)&wqh, g_wqh);   cudaGetSymbolAddress((void**)&wql, g_wql);
    cudaGetSymbolAddress((void**)&wkvh, g_wkvh); cudaGetSymbolAddress((void**)&wkvl, g_wkvl);
    cudaGetSymbolAddress((void**)&woh, g_woh);   cudaGetSymbolAddress((void**)&wol, g_wol);

    cudaFuncSetAttribute(flash, cudaFuncAttributeMaxDynamicSharedMemorySize, FL_SMEM);
    cudaFuncSetAttribute(hgemm_bs, cudaFuncAttributeMaxDynamicSharedMemorySize, GB_SMEM);

    // ---- pre-split inputs & fused weights ----
    asplit<<<(NTOK * 512 / 4 + 255) / 256, 256>>>(x, xh, xl, NTOK * 512 / 4);
    // fused x-weight [960,512]: rows DQ 0-255 | DKV 256-383 | KR 384-447 | VR 448-959
    wsplit_t<<<dim3(256 / 32, 512 / 32), 256>>>(W_DQ,  wxh,             wxl,             512, 256);
    wsplit_t<<<dim3(128 / 32, 512 / 32), 256>>>(W_DKV, wxh + 256 * 512, wxl + 256 * 512, 512, 128);
    wsplit_t<<<dim3( 64 / 32, 512 / 32), 256>>>(W_KR,  wxh + 384 * 512, wxl + 384 * 512, 512,  64);
    wsplit_t<<<dim3(512 / 32, 512 / 32), 256>>>(W_VR,  wxh + 448 * 512, wxl + 448 * 512, 512, 512);
    // fused up-q weight [512,256]: UQ 0-255 | QR 256-511
    wsplit_t<<<dim3(256 / 32, 256 / 32), 256>>>(W_UQ,  wqh,             wql,             256, 256);
    wsplit_t<<<dim3(256 / 32, 256 / 32), 256>>>(W_QR,  wqh + 256 * 256, wql + 256 * 256, 256, 256);
    // fused up-kv weight [192,128]: UK 0-63 | UV 64-191
    wsplit_t<<<dim3( 64 / 32, 128 / 32), 256>>>(W_UK,  wkvh,            wkvl,            128,  64);
    wsplit_t<<<dim3(128 / 32, 128 / 32), 256>>>(W_UV,  wkvh + 64 * 128, wkvl + 64 * 128, 128, 128);
    wsplit_t<<<dim3(512 / 32, 512 / 32), 256>>>(W_O,   woh,             wol,             512, 512);

#define GEMMB(Ah, Al, Bh, Bl, Cm, Mv, Nv, Kv, Ldc) \
    hgemm_bs<<<dim3((Nv) / 64, (Mv) / 128), 256, GB_SMEM>>>(Ah, Al, Bh, Bl, Cm, Mv, Nv, Kv, Ldc)

    // fused x projections: [cq | ckv | krope | vres]
    GEMMB(xh, xl, wxh, wxl, xo, NTOK, 960, 512, 960);

    // latent RMS norms (+ split) from fused buffer
    rms_split<<<NTOK, 256>>>(xo, q_ln,  cqh,  cql,  256, 960, 0);
    rms_split<<<NTOK, 128>>>(xo, kv_ln, ckvh, ckvl, 128, 960, 256);

    // fused up-projections
    GEMMB(cqh,  cql,  wqh,  wql,  qo, NTOK, 512, 256, 512);
    GEMMB(ckvh, ckvl, wkvh, wkvl, ko, NTOK, 192, 128, 192);

    // rope + concat + head-RMS + split; V transpose+split
    assemble<<<NTOK, 256>>>(qhw, khw);
    vtrans<<<dim3(BATCH * NKVH, TSEQ / 64), 256>>>();

    // causal flash attention + v_res
    flash<<<dim3(TSEQ / 128, BATCH * NHEADS), 256, FL_SMEM>>>(xo);

    // output projection
    GEMMB(ath, atl, woh, wol, out, NTOK, 512, 512, 512);
}

// round 13
// speedup vs baseline: 2.9715x; 1.0793x over previous
#include <cuda_runtime.h>
#include <cuda_bf16.h>
#include <math.h>
#include <stdint.h>

#define NHEADS 8
#define NKVH   2
#define HDIM   64
#define TSEQ   2048
#define BATCH  4
#define NTOK   (BATCH*TSEQ)   /* 8192 */

// ---------------- scratch (device globals; no allocation allowed) ----------------
__device__ float g_xo[NTOK*960];   // [cq 0:256 | ckv 256:384 | krope 384:448 | vres 448:960]
__device__ float g_qo[NTOK*512];   // [qnope 0:256 | qrope 256:512]
__device__ float g_ko[NTOK*192];   // [knope 0:64 | vv 64:192]
__device__ __nv_bfloat16 g_xh  [NTOK*512], g_xl  [NTOK*512];
__device__ __nv_bfloat16 g_cqh [NTOK*256], g_cql [NTOK*256];
__device__ __nv_bfloat16 g_ckvh[NTOK*128], g_ckvl[NTOK*128];
__device__ __nv_bfloat16 g_ath [NTOK*512], g_atl [NTOK*512];
__device__ __nv_bfloat16 g_wxh [960*512], g_wxl [960*512];
__device__ __nv_bfloat16 g_wqh [512*256], g_wql [512*256];
__device__ __nv_bfloat16 g_wkvh[192*128], g_wkvl[192*128];
__device__ __nv_bfloat16 g_woh [512*512], g_wol [512*512];
__device__ __nv_bfloat16 g_qh [BATCH*NHEADS*TSEQ*HDIM];
__device__ __nv_bfloat16 g_ql [BATCH*NHEADS*TSEQ*HDIM];
__device__ __nv_bfloat16 g_kh [BATCH*NKVH*TSEQ*HDIM];
__device__ __nv_bfloat16 g_kl [BATCH*NKVH*TSEQ*HDIM];
__device__ __nv_bfloat16 g_vth[BATCH*NKVH*HDIM*TSEQ];
__device__ __nv_bfloat16 g_vtl[BATCH*NKVH*HDIM*TSEQ];

__device__ __forceinline__ uint32_t packbf(__nv_bfloat16 a, __nv_bfloat16 b) {
    return ((uint32_t)__bfloat16_as_ushort(b) << 16) | (uint32_t)__bfloat16_as_ushort(a);
}
__device__ __forceinline__ void mma16816(float* c, uint32_t a0, uint32_t a1,
                                         uint32_t a2, uint32_t a3,
                                         uint32_t b0, uint32_t b1) {
    asm volatile(
        "mma.sync.aligned.m16n8k16.row.col.f32.bf16.bf16.f32 "
        "{%0,%1,%2,%3}, {%4,%5,%6,%7}, {%8,%9}, {%0,%1,%2,%3};"
        : "+f"(c[0]), "+f"(c[1]), "+f"(c[2]), "+f"(c[3])
        : "r"(a0), "r"(a1), "r"(a2), "r"(a3), "r"(b0), "r"(b1));
}
__device__ __forceinline__ void ldsm4(uint32_t& r0, uint32_t& r1, uint32_t& r2,
                                      uint32_t& r3, uint32_t addr) {
    asm volatile("ldmatrix.sync.aligned.m8n8.x4.shared.b16 {%0,%1,%2,%3}, [%4];"
                 : "=r"(r0), "=r"(r1), "=r"(r2), "=r"(r3) : "r"(addr));
}
__device__ __forceinline__ void bfsplit(float v, __nv_bfloat16& h, __nv_bfloat16& l) {
    h = __float2bfloat16(v);
    l = __float2bfloat16(v - __bfloat162float(h));
}
__device__ __forceinline__ float fexp2(float x) {
    float y;
    asm("ex2.approx.f32 %0, %1;" : "=f"(y) : "f"(x));
    return y;
}
__device__ __forceinline__ uint32_t smem_u32(const void* p) {
    uint32_t a;
    asm("{ .reg .u64 t; cvta.to.shared.u64 t, %1; cvt.u32.u64 %0, t; }" : "=r"(a) : "l"(p));
    return a;
}
__device__ __forceinline__ void cpa16(uint32_t dst, const void* src) {
    asm volatile("cp.async.ca.shared.global [%0], [%1], 16;" :: "r"(dst), "l"(src) : "memory");
}
#define CP_COMMIT() asm volatile("cp.async.commit_group;" ::: "memory")
#define CP_WAIT0()  asm volatile("cp.async.wait_group 0;" ::: "memory")

// ---------------- merged prep: activation split + all weight transpose-splits ----------------
struct PrepJob {
    const float* W;
    __nv_bfloat16* Wh;
    __nv_bfloat16* Wl;
    int K, N, nb, type;   // type 0: act split (nb blocks of 256 float4); type 1: [K,N]->[N,K] split
};
struct PrepJobs { PrepJob j[10]; };

__global__ __launch_bounds__(256) void prep(PrepJobs js) {
    __shared__ float tile[32][33];
    int bid = blockIdx.x;
    int ji = 0;
    while (bid >= js.j[ji].nb) { bid -= js.j[ji].nb; ji++; }
    const PrepJob jb = js.j[ji];
    const int tid = threadIdx.x;

    if (jb.type == 0) {
        const int i = bid * 256 + tid;
        const float4 v = ((const float4*)jb.W)[i];
        __nv_bfloat16 h0, h1, h2, h3, l0, l1, l2, l3;
        bfsplit(v.x, h0, l0); bfsplit(v.y, h1, l1);
        bfsplit(v.z, h2, l2); bfsplit(v.w, h3, l3);
        ((uint2*)jb.Wh)[i] = make_uint2(packbf(h0, h1), packbf(h2, h3));
        ((uint2*)jb.Wl)[i] = make_uint2(packbf(l0, l1), packbf(l2, l3));
    } else {
        const int tpx = jb.N >> 5;
        const int n0 = (bid % tpx) * 32, k0 = (bid / tpx) * 32;
        for (int i = tid; i < 1024; i += 256) {
            const int r = i >> 5, c = i & 31;
            tile[r][c] = jb.W[(size_t)(k0 + r) * jb.N + n0 + c];
        }
        __syncthreads();
        for (int i = tid; i < 1024; i += 256) {
            const int n = i >> 5, k = i & 31;
            __nv_bfloat16 h, l;
            bfsplit(tile[k][n], h, l);
            jb.Wh[(size_t)(n0 + n) * jb.K + k0 + k] = h;
            jb.Wl[(size_t)(n0 + n) * jb.K + k0 + k] = l;
        }
    }
}

// ---------------- fused latent RMS norms (cq 256 + ckv 128) -> bf16 hi/lo ----------------
__global__ __launch_bounds__(384) void rms2(const float* __restrict__ xo,
                                            const float* __restrict__ qw,
                                            const float* __restrict__ kvw,
                                            __nv_bfloat16* __restrict__ cqh,
                                            __nv_bfloat16* __restrict__ cql,
                                            __nv_bfloat16* __restrict__ ckvh,
                                            __nv_bfloat16* __restrict__ ckvl) {
    const int n = blockIdx.x;
    const int tid = threadIdx.x;
    __shared__ float sh[12];
    const bool isq = tid < 256;
    const int d = isq ? tid : tid - 256;
    const float v = xo[(size_t)n * 960 + (isq ? 0 : 256) + d];
    float ss = v * v;
#pragma unroll
    for (int o = 16; o > 0; o >>= 1) ss += __shfl_xor_sync(0xffffffffu, ss, o);
    const int wid = tid >> 5;
    if ((tid & 31) == 0) sh[wid] = ss;
    __syncthreads();
    float tot = 0.f;
    if (isq) { for (int i = 0; i < 8; i++)  tot += sh[i]; }
    else     { for (int i = 8; i < 12; i++) tot += sh[i]; }
    const float scale = rsqrtf(tot / (isq ? 256.0f : 128.0f) + 1e-6f);
    __nv_bfloat16 h, l;
    bfsplit(v * scale * (isq ? qw[d] : kvw[d]), h, l);
    if (isq) { cqh [(size_t)n * 256 + d] = h; cql [(size_t)n * 256 + d] = l; }
    else     { ckvh[(size_t)n * 128 + d] = h; ckvl[(size_t)n * 128 + d] = l; }
}

// ---------------- bf16x3 HMMA GEMM, pre-split, cp.async + ldmatrix, 1 sync/chunk ----
#define GS 72
#define GB_AH 0
#define GB_AL 9216
#define GB_BH 18432
#define GB_BL 23040
#define GB_STG 27648
#define GB_SMEM (2 * GB_STG * 2)        /* 110592 bytes */

extern __shared__ char gsm[];

__device__ __forceinline__ void gemm_prefetch(uint32_t sb, int stage, int c64, int tid,
        const __nv_bfloat16* Ah, const __nv_bfloat16* Al,
        const __nv_bfloat16* Bh, const __nv_bfloat16* Bl,
        int m0, int n0, int K) {
    const int base = stage * GB_STG;
#pragma unroll
    for (int i = tid; i < 2048; i += 256) {
        const int half = i >> 10;
        const int r = (i >> 3) & 127;
        const int cc = i & 7;
        const uint32_t dst = sb + (uint32_t)(base + (half ? GB_AL : GB_AH) + r * GS + cc * 8) * 2;
        const __nv_bfloat16* src = (half ? Al : Ah) + (size_t)(m0 + r) * K + c64 + cc * 8;
        cpa16(dst, src);
    }
#pragma unroll
    for (int i = tid; i < 1024; i += 256) {
        const int half = i >> 9;
        const int r = (i >> 3) & 63;
        const int cc = i & 7;
        const uint32_t dst = sb + (uint32_t)(base + (half ? GB_BL : GB_BH) + r * GS + cc * 8) * 2;
        const __nv_bfloat16* src = (half ? Bl : Bh) + (size_t)(n0 + r) * K + c64 + cc * 8;
        cpa16(dst, src);
    }
}

__global__ __launch_bounds__(256) void hgemm_bs(
        const __nv_bfloat16* __restrict__ Ah, const __nv_bfloat16* __restrict__ Al,
        const __nv_bfloat16* __restrict__ Bh, const __nv_bfloat16* __restrict__ Bl,
        float* __restrict__ C, int M, int N, int K, int ldc) {
    const uint32_t sb = smem_u32(gsm);

    const int tid = threadIdx.x, wid = tid >> 5, lane = tid & 31;
    const int wm = wid & 3, wn = wid >> 2;
    const int g = lane >> 2, t = lane & 3;
    const int m0 = blockIdx.y * 128, n0 = blockIdx.x * 64;

    const int arow = ((lane >> 3) & 1) * 8 + (lane & 7);
    const int acol = (lane >> 4) << 3;
    const int brow = ((lane >> 4) << 3) + (lane & 7);
    const int bcol = ((lane >> 3) & 1) * 8;

    float acc[2][4][4];
#pragma unroll
    for (int i = 0; i < 2; i++)
#pragma unroll
        for (int j = 0; j < 4; j++)
#pragma unroll
            for (int r = 0; r < 4; r++) acc[i][j][r] = 0.f;

    const int nch = K >> 6;
    gemm_prefetch(sb, 0, 0, tid, Ah, Al, Bh, Bl, m0, n0, K);
    CP_COMMIT();

    for (int c = 0; c < nch; c++) {
        const int st = c & 1;
        CP_WAIT0();
        __syncthreads();
        if (c + 1 < nch) {
            gemm_prefetch(sb, st ^ 1, (c + 1) << 6, tid, Ah, Al, Bh, Bl, m0, n0, K);
            CP_COMMIT();
        }

        const uint32_t stg = sb + (uint32_t)(st * GB_STG) * 2;
        const uint32_t aH_b = stg + (uint32_t)(GB_AH + (wm * 32 + arow) * GS + acol) * 2;
        const uint32_t aL_b = stg + (uint32_t)(GB_AL + (wm * 32 + arow) * GS + acol) * 2;
        const uint32_t bH_b = stg + (uint32_t)(GB_BH + (wn * 32 + brow) * GS + bcol) * 2;
        const uint32_t bL_b = stg + (uint32_t)(GB_BL + (wn * 32 + brow) * GS + bcol) * 2;

#pragma unroll
        for (int kk = 0; kk < 64; kk += 16) {
            uint32_t ah[2][4], al[2][4];
#pragma unroll
            for (int i = 0; i < 2; i++) {
                ldsm4(ah[i][0], ah[i][1], ah[i][2], ah[i][3],
                      aH_b + (uint32_t)(i * 16 * GS + kk) * 2);
                ldsm4(al[i][0], al[i][1], al[i][2], al[i][3],
                      aL_b + (uint32_t)(i * 16 * GS + kk) * 2);
            }
#pragma unroll
            for (int jp = 0; jp < 2; jp++) {
                uint32_t h0, h1, h2, h3, l0, l1, l2, l3;
                ldsm4(h0, h1, h2, h3, bH_b + (uint32_t)(jp * 16 * GS + kk) * 2);
                ldsm4(l0, l1, l2, l3, bL_b + (uint32_t)(jp * 16 * GS + kk) * 2);
#pragma unroll
                for (int i = 0; i < 2; i++) {
                    mma16816(acc[i][2*jp],   ah[i][0], ah[i][1], ah[i][2], ah[i][3], h0, h1);
                    mma16816(acc[i][2*jp],   al[i][0], al[i][1], al[i][2], al[i][3], h0, h1);
                    mma16816(acc[i][2*jp],   ah[i][0], ah[i][1], ah[i][2], ah[i][3], l0, l1);
                    mma16816(acc[i][2*jp+1], ah[i][0], ah[i][1], ah[i][2], ah[i][3], h2, h3);
                    mma16816(acc[i][2*jp+1], al[i][0], al[i][1], al[i][2], al[i][3], h2, h3);
                    mma16816(acc[i][2*jp+1], ah[i][0], ah[i][1], ah[i][2], ah[i][3], l2, l3);
                }
            }
        }
    }

#pragma unroll
    for (int i = 0; i < 2; i++)
#pragma unroll
        for (int j = 0; j < 4; j++) {
            const int row = m0 + wm * 32 + i * 16 + g;
            const int col = n0 + wn * 32 + j * 8 + 2 * t;
            *(float2*)&C[(size_t)row * ldc + col]       = make_float2(acc[i][j][0], acc[i][j][1]);
            *(float2*)&C[(size_t)(row + 8) * ldc + col] = make_float2(acc[i][j][2], acc[i][j][3]);
        }
}

// ---------------- RoPE + concat + per-head RMS -> bf16 hi/lo [B,h,T,64] ----------------
__global__ __launch_bounds__(256) void assemble(const float* __restrict__ qhw,
                                                const float* __restrict__ khw) {
    const int n = blockIdx.x;
    const int b = n / TSEQ, t = n % TSEQ;
    const int tid = threadIdx.x, w = tid >> 5, l = tid & 31;

    const int j = l & 15;
    const float invf = powf(500000.0f, -(float)j / 16.0f);
    const float f = (float)t * invf;
    const float cs = cosf(f), sn = sinf(f);

    {
        const int h = w;
        float v0 = g_qo[(size_t)n * 512 + h * 32 + l];
        const float* qr = &g_qo[(size_t)n * 512 + 256 + h * 32];
        float a = qr[l];
        float v1 = (l < 16) ? (a * cs - qr[l + 16] * sn) : (a * cs + qr[l - 16] * sn);
        float ss = v0 * v0 + v1 * v1;
#pragma unroll
        for (int o = 16; o > 0; o >>= 1) ss += __shfl_xor_sync(0xffffffffu, ss, o);
        float scale = rsqrtf(ss / 64.0f + 1e-6f);
        const size_t base = (((size_t)b * NHEADS + h) * TSEQ + t) * HDIM;
        __nv_bfloat16 hh, ll;
        bfsplit(v0 * scale * qhw[l], hh, ll);
        g_qh[base + l] = hh; g_ql[base + l] = ll;
        bfsplit(v1 * scale * qhw[32 + l], hh, ll);
        g_qh[base + 32 + l] = hh; g_ql[base + 32 + l] = ll;
    }
    if (w < 2) {
        const int kvh = w;
        float v0 = g_ko[(size_t)n * 192 + kvh * 32 + l];
        const float* kr = &g_xo[(size_t)n * 960 + 384 + kvh * 32];
        float a = kr[l];
        float v1 = (l < 16) ? (a * cs - kr[l + 16] * sn) : (a * cs + kr[l - 16] * sn);
        float ss = v0 * v0 + v1 * v1;
#pragma unroll
        for (int o = 16; o > 0; o >>= 1) ss += __shfl_xor_sync(0xffffffffu, ss, o);
        float scale = rsqrtf(ss / 64.0f + 1e-6f);
        const size_t base = (((size_t)b * NKVH + kvh) * TSEQ + t) * HDIM;
        __nv_bfloat16 hh, ll;
        bfsplit(v0 * scale * khw[l], hh, ll);
        g_kh[base + l] = hh; g_kl[base + l] = ll;
        bfsplit(v1 * scale * khw[32 + l], hh, ll);
        g_kh[base + 32 + l] = hh; g_kl[base + 32 + l] = ll;
    }
}

// ---------------- V transpose + split ----------------
__global__ __launch_bounds__(256) void vtrans() {
    __shared__ __nv_bfloat16 sh[64][65], sl[64][65];
    const int bk = blockIdx.x;
    const int b = bk >> 1, kvh = bk & 1;
    const int t0 = blockIdx.y * 64;
    const int tid = threadIdx.x;
    for (int i = tid; i < 4096; i += 256) {
        const int tt = i >> 6, d = i & 63;
        float v = g_ko[(size_t)(b * TSEQ + t0 + tt) * 192 + 64 + kvh * 64 + d];
        __nv_bfloat16 hh, ll;
        bfsplit(v, hh, ll);
        sh[tt][d] = hh; sl[tt][d] = ll;
    }
    __syncthreads();
    for (int i = tid; i < 4096; i += 256) {
        const int d = i >> 6, tt = i & 63;
        g_vth[((size_t)bk * 64 + d) * TSEQ + t0 + tt] = sh[tt][d];
        g_vtl[((size_t)bk * 64 + d) * TSEQ + t0 + tt] = sl[tt][d];
    }
}

// ---------------- HMMA causal flash attention, BM=128, BN=64, d=64 ----------------
#define FS 72
#define FQH 0
#define FQL 9216
#define FSTG 18432
#define FSTGSZ 18432
#define FL_SMEM ((FSTG + 2 * FSTGSZ) * 2)   /* 110592 bytes */
#define SCL2 0.18033688011112042f          /* 0.125 * log2(e) */

__device__ __forceinline__ void flash_prefetch(uint32_t sb, int stage, int kt, int tid,
        const __nv_bfloat16* Khb, const __nv_bfloat16* Klb,
        const __nv_bfloat16* Vthb, const __nv_bfloat16* Vtlb) {
    const int base = FSTG + stage * FSTGSZ;
#pragma unroll
    for (int i = tid; i < 2048; i += 256) {
        const int arr = i >> 9;
        const int r = (i >> 3) & 63;
        const int c = i & 7;
        const uint32_t dst = sb + (uint32_t)(base + arr * 4608 + r * FS + c * 8) * 2;
        const __nv_bfloat16* src;
        if (arr == 0)      src = Khb + ((size_t)(kt * 64 + r)) * 64 + c * 8;
        else if (arr == 1) src = Klb + ((size_t)(kt * 64 + r)) * 64 + c * 8;
        else if (arr == 2) src = Vthb + (size_t)r * TSEQ + kt * 64 + c * 8;
        else               src = Vtlb + (size_t)r * TSEQ + kt * 64 + c * 8;
        cpa16(dst, src);
    }
}

__global__ __launch_bounds__(256) void flash(const float* __restrict__ xo) {
    const uint32_t sb = smem_u32(gsm);

    const int qt = gridDim.x - 1 - blockIdx.x;
    const int bh = blockIdx.y;
    const int b = bh >> 3, h = bh & 7, kvh = h >> 2;
    const int q0 = qt * 128;

    const int tid = threadIdx.x, wid = tid >> 5, lane = tid & 31;
    const int g = lane >> 2, t = lane & 3;
    const int r0 = wid * 16;

    const int arow = ((lane >> 3) & 1) * 8 + (lane & 7);
    const int acol = (lane >> 4) << 3;
    const int brow = ((lane >> 4) << 3) + (lane & 7);
    const int bcol = ((lane >> 3) & 1) * 8;
    const uint32_t qh_a = sb + (uint32_t)(FQH + (r0 + arow) * FS + acol) * 2;
    const uint32_t ql_a = sb + (uint32_t)(FQL + (r0 + arow) * FS + acol) * 2;

    const __nv_bfloat16* Qhb = &g_qh[(((size_t)b * NHEADS + h) * TSEQ + q0) * HDIM];
    const __nv_bfloat16* Qlb = &g_ql[(((size_t)b * NHEADS + h) * TSEQ + q0) * HDIM];
    const __nv_bfloat16* Khb = &g_kh[(((size_t)b * NKVH + kvh) * TSEQ) * HDIM];
    const __nv_bfloat16* Klb = &g_kl[(((size_t)b * NKVH + kvh) * TSEQ) * HDIM];
    const __nv_bfloat16* Vthb = &g_vth[(((size_t)b * NKVH + kvh) * HDIM) * TSEQ];
    const __nv_bfloat16* Vtlb = &g_vtl[(((size_t)b * NKVH + kvh) * HDIM) * TSEQ];

#pragma unroll
    for (int i = tid; i < 2048; i += 256) {
        const int half = i >> 10;
        const int r = (i >> 3) & 127;
        const int c = i & 7;
        const uint32_t dst = sb + (uint32_t)((half ? FQL : FQH) + r * FS + c * 8) * 2;
        const __nv_bfloat16* src = (half ? Qlb : Qhb) + (size_t)r * 64 + c * 8;
        cpa16(dst, src);
    }
    flash_prefetch(sb, 0, 0, tid, Khb, Klb, Vthb, Vtlb);
    CP_COMMIT();

    float m0 = -INFINITY, m1 = -INFINITY, l0 = 0.f, l1 = 0.f;
    float o[8][4];
#pragma unroll
    for (int j = 0; j < 8; j++)
#pragma unroll
        for (int r = 0; r < 4; r++) o[j][r] = 0.f;

    const int ktmax = 2 * qt + 1;
    for (int kt = 0; kt <= ktmax; kt++) {
        const int st = kt & 1;
        CP_WAIT0();
        __syncthreads();
        if (kt < ktmax) {
            flash_prefetch(sb, st ^ 1, kt + 1, tid, Khb, Klb, Vthb, Vtlb);
            CP_COMMIT();
        }

        const uint32_t stg = sb + (uint32_t)(FSTG + st * FSTGSZ) * 2;
        const uint32_t kh_b = stg + (uint32_t)(brow * FS + bcol) * 2;
        const uint32_t kl_b = kh_b + 4608 * 2;
        const uint32_t vh_b = kh_b + 9216 * 2;
        const uint32_t vl_b = kh_b + 13824 * 2;

        float s[8][4];
#pragma unroll
        for (int j = 0; j < 8; j++)
#pragma unroll
            for (int r = 0; r < 4; r++) s[j][r] = 0.f;

#pragma unroll
        for (int kk = 0; kk < 64; kk += 16) {
            uint32_t aH[4], aL[4];
            ldsm4(aH[0], aH[1], aH[2], aH[3], qh_a + (uint32_t)kk * 2);
            ldsm4(aL[0], aL[1], aL[2], aL[3], ql_a + (uint32_t)kk * 2);
#pragma unroll
            for (int jp = 0; jp < 4; jp++) {
                uint32_t h0, h1, h2, h3, lo0, lo1, lo2, lo3;
                ldsm4(h0, h1, h2, h3, kh_b + (uint32_t)(jp * 16 * FS + kk) * 2);
                ldsm4(lo0, lo1, lo2, lo3, kl_b + (uint32_t)(jp * 16 * FS + kk) * 2);
                mma16816(s[2*jp],   aH[0], aH[1], aH[2], aH[3], h0, h1);
                mma16816(s[2*jp],   aL[0], aL[1], aL[2], aL[3], h0, h1);
                mma16816(s[2*jp],   aH[0], aH[1], aH[2], aH[3], lo0, lo1);
                mma16816(s[2*jp+1], aH[0], aH[1], aH[2], aH[3], h2, h3);
                mma16816(s[2*jp+1], aL[0], aL[1], aL[2], aL[3], h2, h3);
                mma16816(s[2*jp+1], aH[0], aH[1], aH[2], aH[3], lo2, lo3);
            }
        }

        const bool diag = (kt >= 2 * qt);
#pragma unroll
        for (int j = 0; j < 8; j++) {
#pragma unroll
            for (int r = 0; r < 4; r++) {
                s[j][r] *= SCL2;
                if (diag) {
                    const int col = kt * 64 + j * 8 + 2 * t + (r & 1);
                    const int row = q0 + r0 + g + ((r >> 1) << 3);
                    if (col > row) s[j][r] = -INFINITY;
                }
            }
        }

        float mx0 = -INFINITY, mx1 = -INFINITY;
#pragma unroll
        for (int j = 0; j < 8; j++) {
            mx0 = fmaxf(mx0, fmaxf(s[j][0], s[j][1]));
            mx1 = fmaxf(mx1, fmaxf(s[j][2], s[j][3]));
        }
        mx0 = fmaxf(mx0, __shfl_xor_sync(0xffffffffu, mx0, 1));
        mx0 = fmaxf(mx0, __shfl_xor_sync(0xffffffffu, mx0, 2));
        mx1 = fmaxf(mx1, __shfl_xor_sync(0xffffffffu, mx1, 1));
        mx1 = fmaxf(mx1, __shfl_xor_sync(0xffffffffu, mx1, 2));
        const float mn0 = fmaxf(m0, mx0), mn1 = fmaxf(m1, mx1);
        const float al0 = fexp2(m0 - mn0), al1 = fexp2(m1 - mn1);
        m0 = mn0; m1 = mn1;
        float rs0 = 0.f, rs1 = 0.f;
#pragma unroll
        for (int j = 0; j < 8; j++) {
            s[j][0] = fexp2(s[j][0] - m0);
            s[j][1] = fexp2(s[j][1] - m0);
            s[j][2] = fexp2(s[j][2] - m1);
            s[j][3] = fexp2(s[j][3] - m1);
            rs0 += s[j][0] + s[j][1];
            rs1 += s[j][2] + s[j][3];
        }
        rs0 += __shfl_xor_sync(0xffffffffu, rs0, 1);
        rs0 += __shfl_xor_sync(0xffffffffu, rs0, 2);
        rs1 += __shfl_xor_sync(0xffffffffu, rs1, 1);
        rs1 += __shfl_xor_sync(0xffffffffu, rs1, 2);
        l0 = l0 * al0 + rs0;
        l1 = l1 * al1 + rs1;
#pragma unroll
        for (int j = 0; j < 8; j++) {
            o[j][0] *= al0; o[j][1] *= al0;
            o[j][2] *= al1; o[j][3] *= al1;
        }

#pragma unroll
        for (int u = 0; u < 4; u++) {
            uint32_t aPh[4], aPl[4];
            {
                __nv_bfloat16 h0, h1, h2, h3, lo0, lo1, lo2, lo3;
                bfsplit(s[2*u][0], h0, lo0);   bfsplit(s[2*u][1], h1, lo1);
                bfsplit(s[2*u][2], h2, lo2);   bfsplit(s[2*u][3], h3, lo3);
                aPh[0] = packbf(h0, h1);  aPl[0] = packbf(lo0, lo1);
                aPh[1] = packbf(h2, h3);  aPl[1] = packbf(lo2, lo3);
                bfsplit(s[2*u+1][0], h0, lo0); bfsplit(s[2*u+1][1], h1, lo1);
                bfsplit(s[2*u+1][2], h2, lo2); bfsplit(s[2*u+1][3], h3, lo3);
                aPh[2] = packbf(h0, h1);  aPl[2] = packbf(lo0, lo1);
                aPh[3] = packbf(h2, h3);  aPl[3] = packbf(lo2, lo3);
            }
#pragma unroll
            for (int jp = 0; jp < 4; jp++) {
                uint32_t h0, h1, h2, h3, lo0, lo1, lo2, lo3;
                ldsm4(h0, h1, h2, h3, vh_b + (uint32_t)(jp * 16 * FS + 16 * u) * 2);
                ldsm4(lo0, lo1, lo2, lo3, vl_b + (uint32_t)(jp * 16 * FS + 16 * u) * 2);
                mma16816(o[2*jp],   aPh[0], aPh[1], aPh[2], aPh[3], h0, h1);
                mma16816(o[2*jp],   aPl[0], aPl[1], aPl[2], aPl[3], h0, h1);
                mma16816(o[2*jp],   aPh[0], aPh[1], aPh[2], aPh[3], lo0, lo1);
                mma16816(o[2*jp+1], aPh[0], aPh[1], aPh[2], aPh[3], h2, h3);
                mma16816(o[2*jp+1], aPl[0], aPl[1], aPl[2], aPl[3], h2, h3);
                mma16816(o[2*jp+1], aPh[0], aPh[1], aPh[2], aPh[3], lo2, lo3);
            }
        }
    }

    const float inv0 = 1.0f / l0, inv1 = 1.0f / l1;
#pragma unroll
    for (int j = 0; j < 8; j++) {
        const int col = h * 64 + j * 8 + 2 * t;
        {
            const int row = q0 + r0 + g;
            const size_t tok = (size_t)b * TSEQ + row;
            const float2 vr = *(const float2*)&xo[tok * 960 + 448 + col];
            __nv_bfloat16 h0, lo0, h1, lo1;
            bfsplit(o[j][0] * inv0 + vr.x, h0, lo0);
            bfsplit(o[j][1] * inv0 + vr.y, h1, lo1);
            *(uint32_t*)&g_ath[tok * 512 + col] = packbf(h0, h1);
            *(uint32_t*)&g_atl[tok * 512 + col] = packbf(lo0, lo1);
        }
        {
            const int row = q0 + r0 + g + 8;
            const size_t tok = (size_t)b * TSEQ + row;
            const float2 vr = *(const float2*)&xo[tok * 960 + 448 + col];
            __nv_bfloat16 h0, lo0, h1, lo1;
            bfsplit(o[j][2] * inv1 + vr.x, h0, lo0);
            bfsplit(o[j][3] * inv1 + vr.y, h1, lo1);
            *(uint32_t*)&g_ath[tok * 512 + col] = packbf(h0, h1);
            *(uint32_t*)&g_atl[tok * 512 + col] = packbf(lo0, lo1);
        }
    }
}

// ---------------- launch ----------------
extern "C" void kernel_launch(void* const* d_in, const int* in_sizes, int n_in,
                              void* d_out, int out_size) {
    const float* x     = (const float*)d_in[0];
    const float* W_DQ  = (const float*)d_in[1];
    const float* W_UQ  = (const float*)d_in[2];
    const float* W_QR  = (const float*)d_in[3];
    const float* W_DKV = (const float*)d_in[4];
    const float* W_UK  = (const float*)d_in[5];
    const float* W_UV  = (const float*)d_in[6];
    const float* W_KR  = (const float*)d_in[7];
    const float* W_VR  = (const float*)d_in[8];
    const float* W_O   = (const float*)d_in[9];
    const float* q_ln  = (const float*)d_in[10];
    const float* kv_ln = (const float*)d_in[11];
    const float* qhw   = (const float*)d_in[12];
    const float* khw   = (const float*)d_in[13];
    float* out = (float*)d_out;

    float *xo, *qo, *ko;
    cudaGetSymbolAddress((void**)&xo, g_xo);
    cudaGetSymbolAddress((void**)&qo, g_qo);
    cudaGetSymbolAddress((void**)&ko, g_ko);

    __nv_bfloat16 *xh, *xl, *cqh, *cql, *ckvh, *ckvl, *ath, *atl;
    __nv_bfloat16 *wxh, *wxl, *wqh, *wql, *wkvh, *wkvl, *woh, *wol;
    cudaGetSymbolAddress((void**)&xh, g_xh);     cudaGetSymbolAddress((void**)&xl, g_xl);
    cudaGetSymbolAddress((void**)&cqh, g_cqh);   cudaGetSymbolAddress((void**)&cql, g_cql);
    cudaGetSymbolAddress((void**)&ckvh, g_ckvh); cudaGetSymbolAddress((void**)&ckvl, g_ckvl);
    cudaGetSymbolAddress((void**)&ath, g_ath);   cudaGetSymbolAddress((void**)&atl, g_atl);
    cudaGetSymbolAddress((void**)&wxh, g_wxh);   cudaGetSymbolAddress((void**)&wxl, g_wxl);
    cudaGetSymbolAddress((void**)&wqh, g_wqh);   cudaGetSymbolAddress((void**)&wql, g_wql);
    cudaGetSymbolAddress((void**)&wkvh, g_wkvh); cudaGetSymbolAddress((void**)&wkvl, g_wkvl);
    cudaGetSymbolAddress((void**)&woh, g_woh);   cudaGetSymbolAddress((void**)&wol, g_wol);

    cudaFuncSetAttribute(flash, cudaFuncAttributeMaxDynamicSharedMemorySize, FL_SMEM);
    cudaFuncSetAttribute(hgemm_bs, cudaFuncAttributeMaxDynamicSharedMemorySize, GB_SMEM);

    // ---- merged prep: activation split + 9 weight transpose-splits ----
    PrepJobs js;
    // act split: NTOK*512/4 float4s / 256 per block = 4096 blocks
    js.j[0] = { x, xh, xl, 0, 0, 4096, 0 };
    js.j[1] = { W_DQ,  wxh,             wxl,             512, 256, (256/32)*(512/32), 1 };
    js.j[2] = { W_DKV, wxh + 256 * 512, wxl + 256 * 512, 512, 128, (128/32)*(512/32), 1 };
    js.j[3] = { W_KR,  wxh + 384 * 512, wxl + 384 * 512, 512,  64, ( 64/32)*(512/32), 1 };
    js.j[4] = { W_VR,  wxh + 448 * 512, wxl + 448 * 512, 512, 512, (512/32)*(512/32), 1 };
    js.j[5] = { W_UQ,  wqh,             wql,             256, 256, (256/32)*(256/32), 1 };
    js.j[6] = { W_QR,  wqh + 256 * 256, wql + 256 * 256, 256, 256, (256/32)*(256/32), 1 };
    js.j[7] = { W_UK,  wkvh,            wkvl,            128,  64, ( 64/32)*(128/32), 1 };
    js.j[8] = { W_UV,  wkvh + 64 * 128, wkvl + 64 * 128, 128, 128, (128/32)*(128/32), 1 };
    js.j[9] = { W_O,   woh,             wol,             512, 512, (512/32)*(512/32), 1 };
    int total = 0;
    for (int i = 0; i < 10; i++) total += js.j[i].nb;
    prep<<<total, 256>>>(js);

#define GEMMB(Ah, Al, Bh, Bl, Cm, Mv, Nv, Kv, Ldc) \
    hgemm_bs<<<dim3((Nv) / 64, (Mv) / 128), 256, GB_SMEM>>>(Ah, Al, Bh, Bl, Cm, Mv, Nv, Kv, Ldc)

    // fused x projections: [cq | ckv | krope | vres]
    GEMMB(xh, xl, wxh, wxl, xo, NTOK, 960, 512, 960);

    // fused latent RMS norms (+ split)
    rms2<<<NTOK, 384>>>(xo, q_ln, kv_ln, cqh, cql, ckvh, ckvl);

    // fused up-projections
    GEMMB(cqh,  cql,  wqh,  wql,  qo, NTOK, 512, 256, 512);
    GEMMB(ckvh, ckvl, wkvh, wkvl, ko, NTOK, 192, 128, 192);

    // rope + concat + head-RMS + split; V transpose+split
    assemble<<<NTOK, 256>>>(qhw, khw);
    vtrans<<<dim3(BATCH * NKVH, TSEQ / 64), 256>>>();

    // causal flash attention + v_res
    flash<<<dim3(TSEQ / 128, BATCH * NHEADS), 256, FL_SMEM>>>(xo);

    // output projection
    GEMMB(ath, atl, woh, wol, out, NTOK, 512, 512, 512);
}

// round 15
// speedup vs baseline: 2.9733x; 1.0006x over previous
#include <cuda_runtime.h>
#include <cuda_bf16.h>
#include <math.h>
#include <stdint.h>

#define NHEADS 8
#define NKVH   2
#define HDIM   64
#define TSEQ   2048
#define BATCH  4
#define NTOK   (BATCH*TSEQ)   /* 8192 */
#define SCL2 0.18033688011112042f      /* 0.125 * log2(e) */

// ---------------- scratch (device globals; no allocation allowed) ----------------
__device__ float g_xo[NTOK*960];   // [cq 0:256 | ckv 256:384 | krope 384:448 | vres 448:960]
__device__ float g_qo[NTOK*512];   // [qnope 0:256 | qrope 256:512]
__device__ float g_ko[NTOK*192];   // [knope 0:64 | vv 64:192]
__device__ __nv_bfloat16 g_xh  [NTOK*512], g_xl  [NTOK*512];
__device__ __nv_bfloat16 g_cqh [NTOK*256], g_cql [NTOK*256];
__device__ __nv_bfloat16 g_ckvh[NTOK*128], g_ckvl[NTOK*128];
__device__ __nv_bfloat16 g_ath [NTOK*512], g_atl [NTOK*512];
__device__ __nv_bfloat16 g_wxh [960*512], g_wxl [960*512];
__device__ __nv_bfloat16 g_wqh [512*256], g_wql [512*256];
__device__ __nv_bfloat16 g_wkvh[192*128], g_wkvl[192*128];
__device__ __nv_bfloat16 g_woh [512*512], g_wol [512*512];
__device__ __nv_bfloat16 g_qh [BATCH*NHEADS*TSEQ*HDIM];
__device__ __nv_bfloat16 g_ql [BATCH*NHEADS*TSEQ*HDIM];
__device__ __nv_bfloat16 g_kh [BATCH*NKVH*TSEQ*HDIM];
__device__ __nv_bfloat16 g_kl [BATCH*NKVH*TSEQ*HDIM];
__device__ __nv_bfloat16 g_vth[BATCH*NKVH*HDIM*TSEQ];
__device__ __nv_bfloat16 g_vtl[BATCH*NKVH*HDIM*TSEQ];

__device__ __forceinline__ uint32_t packbf(__nv_bfloat16 a, __nv_bfloat16 b) {
    return ((uint32_t)__bfloat16_as_ushort(b) << 16) | (uint32_t)__bfloat16_as_ushort(a);
}
__device__ __forceinline__ void mma16816(float* c, uint32_t a0, uint32_t a1,
                                         uint32_t a2, uint32_t a3,
                                         uint32_t b0, uint32_t b1) {
    asm volatile(
        "mma.sync.aligned.m16n8k16.row.col.f32.bf16.bf16.f32 "
        "{%0,%1,%2,%3}, {%4,%5,%6,%7}, {%8,%9}, {%0,%1,%2,%3};"
        : "+f"(c[0]), "+f"(c[1]), "+f"(c[2]), "+f"(c[3])
        : "r"(a0), "r"(a1), "r"(a2), "r"(a3), "r"(b0), "r"(b1));
}
__device__ __forceinline__ void ldsm4(uint32_t& r0, uint32_t& r1, uint32_t& r2,
                                      uint32_t& r3, uint32_t addr) {
    asm volatile("ldmatrix.sync.aligned.m8n8.x4.shared.b16 {%0,%1,%2,%3}, [%4];"
                 : "=r"(r0), "=r"(r1), "=r"(r2), "=r"(r3) : "r"(addr));
}
__device__ __forceinline__ void bfsplit(float v, __nv_bfloat16& h, __nv_bfloat16& l) {
    h = __float2bfloat16(v);
    l = __float2bfloat16(v - __bfloat162float(h));
}
__device__ __forceinline__ float fexp2(float x) {
    float y;
    asm("ex2.approx.f32 %0, %1;" : "=f"(y) : "f"(x));
    return y;
}
__device__ __forceinline__ uint32_t smem_u32(const void* p) {
    uint32_t a;
    asm("{ .reg .u64 t; cvta.to.shared.u64 t, %1; cvt.u32.u64 %0, t; }" : "=r"(a) : "l"(p));
    return a;
}
__device__ __forceinline__ void cpa16(uint32_t dst, const void* src) {
    asm volatile("cp.async.ca.shared.global [%0], [%1], 16;" :: "r"(dst), "l"(src) : "memory");
}
#define CP_COMMIT() asm volatile("cp.async.commit_group;" ::: "memory")
#define CP_WAIT0()  asm volatile("cp.async.wait_group 0;" ::: "memory")

// ---------------- merged prep: activation split + all weight transpose-splits ----------------
struct PrepJob {
    const float* W;
    __nv_bfloat16* Wh;
    __nv_bfloat16* Wl;
    int K, N, nb, type;
};
struct PrepJobs { PrepJob j[10]; };

__global__ __launch_bounds__(256) void prep(PrepJobs js) {
    __shared__ float tile[32][33];
    int bid = blockIdx.x;
    int ji = 0;
    while (bid >= js.j[ji].nb) { bid -= js.j[ji].nb; ji++; }
    const PrepJob jb = js.j[ji];
    const int tid = threadIdx.x;

    if (jb.type == 0) {
        const int i = bid * 256 + tid;
        const float4 v = ((const float4*)jb.W)[i];
        __nv_bfloat16 h0, h1, h2, h3, l0, l1, l2, l3;
        bfsplit(v.x, h0, l0); bfsplit(v.y, h1, l1);
        bfsplit(v.z, h2, l2); bfsplit(v.w, h3, l3);
        ((uint2*)jb.Wh)[i] = make_uint2(packbf(h0, h1), packbf(h2, h3));
        ((uint2*)jb.Wl)[i] = make_uint2(packbf(l0, l1), packbf(l2, l3));
    } else {
        const int tpx = jb.N >> 5;
        const int n0 = (bid % tpx) * 32, k0 = (bid / tpx) * 32;
        for (int i = tid; i < 1024; i += 256) {
            const int r = i >> 5, c = i & 31;
            tile[r][c] = jb.W[(size_t)(k0 + r) * jb.N + n0 + c];
        }
        __syncthreads();
        for (int i = tid; i < 1024; i += 256) {
            const int n = i >> 5, k = i & 31;
            __nv_bfloat16 h, l;
            bfsplit(tile[k][n], h, l);
            jb.Wh[(size_t)(n0 + n) * jb.K + k0 + k] = h;
            jb.Wl[(size_t)(n0 + n) * jb.K + k0 + k] = l;
        }
    }
}

// ---------------- fused latent RMS norms (cq 256 + ckv 128) -> bf16 hi/lo ----------------
__global__ __launch_bounds__(384) void rms2(const float* __restrict__ xo,
                                            const float* __restrict__ qw,
                                            const float* __restrict__ kvw,
                                            __nv_bfloat16* __restrict__ cqh,
                                            __nv_bfloat16* __restrict__ cql,
                                            __nv_bfloat16* __restrict__ ckvh,
                                            __nv_bfloat16* __restrict__ ckvl) {
    const int n = blockIdx.x;
    const int tid = threadIdx.x;
    __shared__ float sh[12];
    const bool isq = tid < 256;
    const int d = isq ? tid : tid - 256;
    const float v = xo[(size_t)n * 960 + (isq ? 0 : 256) + d];
    float ss = v * v;
#pragma unroll
    for (int o = 16; o > 0; o >>= 1) ss += __shfl_xor_sync(0xffffffffu, ss, o);
    const int wid = tid >> 5;
    if ((tid & 31) == 0) sh[wid] = ss;
    __syncthreads();
    float tot = 0.f;
    if (isq) { for (int i = 0; i < 8; i++)  tot += sh[i]; }
    else     { for (int i = 8; i < 12; i++) tot += sh[i]; }
    const float scale = rsqrtf(tot / (isq ? 256.0f : 128.0f) + 1e-6f);
    __nv_bfloat16 h, l;
    bfsplit(v * scale * (isq ? qw[d] : kvw[d]), h, l);
    if (isq) { cqh [(size_t)n * 256 + d] = h; cql [(size_t)n * 256 + d] = l; }
    else     { ckvh[(size_t)n * 128 + d] = h; ckvl[(size_t)n * 128 + d] = l; }
}

// ---------------- bf16x3 HMMA GEMM ----------------
#define GS 72
#define GB_AH 0
#define GB_AL 9216
#define GB_BH 18432
#define GB_BL 23040
#define GB_STG 27648
#define GB_SMEM (2 * GB_STG * 2)        /* 110592 bytes */

extern __shared__ char gsm[];

__device__ __forceinline__ void gemm_prefetch(uint32_t sb, int stage, int c64, int tid,
        const __nv_bfloat16* Ah, const __nv_bfloat16* Al,
        const __nv_bfloat16* Bh, const __nv_bfloat16* Bl,
        int m0, int n0, int K) {
    const int base = stage * GB_STG;
#pragma unroll
    for (int i = tid; i < 2048; i += 256) {
        const int half = i >> 10;
        const int r = (i >> 3) & 127;
        const int cc = i & 7;
        const uint32_t dst = sb + (uint32_t)(base + (half ? GB_AL : GB_AH) + r * GS + cc * 8) * 2;
        const __nv_bfloat16* src = (half ? Al : Ah) + (size_t)(m0 + r) * K + c64 + cc * 8;
        cpa16(dst, src);
    }
#pragma unroll
    for (int i = tid; i < 1024; i += 256) {
        const int half = i >> 9;
        const int r = (i >> 3) & 63;
        const int cc = i & 7;
        const uint32_t dst = sb + (uint32_t)(base + (half ? GB_BL : GB_BH) + r * GS + cc * 8) * 2;
        const __nv_bfloat16* src = (half ? Bl : Bh) + (size_t)(n0 + r) * K + c64 + cc * 8;
        cpa16(dst, src);
    }
}

__global__ __launch_bounds__(256) void hgemm_bs(
        const __nv_bfloat16* __restrict__ Ah, const __nv_bfloat16* __restrict__ Al,
        const __nv_bfloat16* __restrict__ Bh, const __nv_bfloat16* __restrict__ Bl,
        float* __restrict__ C, int M, int N, int K, int ldc) {
    const uint32_t sb = smem_u32(gsm);

    const int tid = threadIdx.x, wid = tid >> 5, lane = tid & 31;
    const int wm = wid & 3, wn = wid >> 2;
    const int g = lane >> 2, t = lane & 3;
    const int m0 = blockIdx.y * 128, n0 = blockIdx.x * 64;

    const int arow = ((lane >> 3) & 1) * 8 + (lane & 7);
    const int acol = (lane >> 4) << 3;
    const int brow = ((lane >> 4) << 3) + (lane & 7);
    const int bcol = ((lane >> 3) & 1) * 8;

    float acc[2][4][4];
#pragma unroll
    for (int i = 0; i < 2; i++)
#pragma unroll
        for (int j = 0; j < 4; j++)
#pragma unroll
            for (int r = 0; r < 4; r++) acc[i][j][r] = 0.f;

    const int nch = K >> 6;
    gemm_prefetch(sb, 0, 0, tid, Ah, Al, Bh, Bl, m0, n0, K);
    CP_COMMIT();

    for (int c = 0; c < nch; c++) {
        const int st = c & 1;
        CP_WAIT0();
        __syncthreads();
        if (c + 1 < nch) {
            gemm_prefetch(sb, st ^ 1, (c + 1) << 6, tid, Ah, Al, Bh, Bl, m0, n0, K);
            CP_COMMIT();
        }

        const uint32_t stg = sb + (uint32_t)(st * GB_STG) * 2;
        const uint32_t aH_b = stg + (uint32_t)(GB_AH + (wm * 32 + arow) * GS + acol) * 2;
        const uint32_t aL_b = stg + (uint32_t)(GB_AL + (wm * 32 + arow) * GS + acol) * 2;
        const uint32_t bH_b = stg + (uint32_t)(GB_BH + (wn * 32 + brow) * GS + bcol) * 2;
        const uint32_t bL_b = stg + (uint32_t)(GB_BL + (wn * 32 + brow) * GS + bcol) * 2;

#pragma unroll
        for (int kk = 0; kk < 64; kk += 16) {
            uint32_t ah[2][4], al[2][4];
#pragma unroll
            for (int i = 0; i < 2; i++) {
                ldsm4(ah[i][0], ah[i][1], ah[i][2], ah[i][3],
                      aH_b + (uint32_t)(i * 16 * GS + kk) * 2);
                ldsm4(al[i][0], al[i][1], al[i][2], al[i][3],
                      aL_b + (uint32_t)(i * 16 * GS + kk) * 2);
            }
#pragma unroll
            for (int jp = 0; jp < 2; jp++) {
                uint32_t h0, h1, h2, h3, l0, l1, l2, l3;
                ldsm4(h0, h1, h2, h3, bH_b + (uint32_t)(jp * 16 * GS + kk) * 2);
                ldsm4(l0, l1, l2, l3, bL_b + (uint32_t)(jp * 16 * GS + kk) * 2);
                // interleaved accumulators: 4 independent streams
                mma16816(acc[0][2*jp],   ah[0][0], ah[0][1], ah[0][2], ah[0][3], h0, h1);
                mma16816(acc[0][2*jp+1], ah[0][0], ah[0][1], ah[0][2], ah[0][3], h2, h3);
                mma16816(acc[1][2*jp],   ah[1][0], ah[1][1], ah[1][2], ah[1][3], h0, h1);
                mma16816(acc[1][2*jp+1], ah[1][0], ah[1][1], ah[1][2], ah[1][3], h2, h3);
                mma16816(acc[0][2*jp],   al[0][0], al[0][1], al[0][2], al[0][3], h0, h1);
                mma16816(acc[0][2*jp+1], al[0][0], al[0][1], al[0][2], al[0][3], h2, h3);
                mma16816(acc[1][2*jp],   al[1][0], al[1][1], al[1][2], al[1][3], h0, h1);
                mma16816(acc[1][2*jp+1], al[1][0], al[1][1], al[1][2], al[1][3], h2, h3);
                mma16816(acc[0][2*jp],   ah[0][0], ah[0][1], ah[0][2], ah[0][3], l0, l1);
                mma16816(acc[0][2*jp+1], ah[0][0], ah[0][1], ah[0][2], ah[0][3], l2, l3);
                mma16816(acc[1][2*jp],   ah[1][0], ah[1][1], ah[1][2], ah[1][3], l0, l1);
                mma16816(acc[1][2*jp+1], ah[1][0], ah[1][1], ah[1][2], ah[1][3], l2, l3);
            }
        }
    }

#pragma unroll
    for (int i = 0; i < 2; i++)
#pragma unroll
        for (int j = 0; j < 4; j++) {
            const int row = m0 + wm * 32 + i * 16 + g;
            const int col = n0 + wn * 32 + j * 8 + 2 * t;
            *(float2*)&C[(size_t)row * ldc + col]       = make_float2(acc[i][j][0], acc[i][j][1]);
            *(float2*)&C[(size_t)(row + 8) * ldc + col] = make_float2(acc[i][j][2], acc[i][j][3]);
        }
}

// ---- merged assemble (RoPE+head-RMS+split; Q pre-scaled by SCL2) + V transpose ----
__global__ __launch_bounds__(256) void assemble_vt(const float* __restrict__ qhw,
                                                   const float* __restrict__ khw) {
    __shared__ __nv_bfloat16 shv[64][65], slv[64][65];
    if (blockIdx.x >= NTOK) {
        // ---- vtrans part ----
        const int vb = blockIdx.x - NTOK;
        const int bk = vb & 7;               // b*NKVH + kvh
        const int t0 = (vb >> 3) * 64;
        const int b = bk >> 1, kvh = bk & 1;
        const int tid = threadIdx.x;
        for (int i = tid; i < 4096; i += 256) {
            const int tt = i >> 6, d = i & 63;
            float v = g_ko[(size_t)(b * TSEQ + t0 + tt) * 192 + 64 + kvh * 64 + d];
            __nv_bfloat16 hh, ll;
            bfsplit(v, hh, ll);
            shv[tt][d] = hh; slv[tt][d] = ll;
        }
        __syncthreads();
        for (int i = tid; i < 4096; i += 256) {
            const int d = i >> 6, tt = i & 63;
            g_vth[((size_t)bk * 64 + d) * TSEQ + t0 + tt] = shv[tt][d];
            g_vtl[((size_t)bk * 64 + d) * TSEQ + t0 + tt] = slv[tt][d];
        }
        return;
    }
    const int n = blockIdx.x;
    const int b = n / TSEQ, t = n % TSEQ;
    const int tid = threadIdx.x, w = tid >> 5, l = tid & 31;

    const int j = l & 15;
    const float invf = powf(500000.0f, -(float)j / 16.0f);
    const float f = (float)t * invf;
    const float cs = cosf(f), sn = sinf(f);

    {
        const int h = w;
        float v0 = g_qo[(size_t)n * 512 + h * 32 + l];
        const float* qr = &g_qo[(size_t)n * 512 + 256 + h * 32];
        float a = qr[l];
        float v1 = (l < 16) ? (a * cs - qr[l + 16] * sn) : (a * cs + qr[l - 16] * sn);
        float ss = v0 * v0 + v1 * v1;
#pragma unroll
        for (int o = 16; o > 0; o >>= 1) ss += __shfl_xor_sync(0xffffffffu, ss, o);
        float scale = rsqrtf(ss / 64.0f + 1e-6f) * SCL2;   // fold softmax scale into Q
        const size_t base = (((size_t)b * NHEADS + h) * TSEQ + t) * HDIM;
        __nv_bfloat16 hh, ll;
        bfsplit(v0 * scale * qhw[l], hh, ll);
        g_qh[base + l] = hh; g_ql[base + l] = ll;
        bfsplit(v1 * scale * qhw[32 + l], hh, ll);
        g_qh[base + 32 + l] = hh; g_ql[base + 32 + l] = ll;
    }
    if (w < 2) {
        const int kvh = w;
        float v0 = g_ko[(size_t)n * 192 + kvh * 32 + l];
        const float* kr = &g_xo[(size_t)n * 960 + 384 + kvh * 32];
        float a = kr[l];
        float v1 = (l < 16) ? (a * cs - kr[l + 16] * sn) : (a * cs + kr[l - 16] * sn);
        float ss = v0 * v0 + v1 * v1;
#pragma unroll
        for (int o = 16; o > 0; o >>= 1) ss += __shfl_xor_sync(0xffffffffu, ss, o);
        float scale = rsqrtf(ss / 64.0f + 1e-6f);
        const size_t base = (((size_t)b * NKVH + kvh) * TSEQ + t) * HDIM;
        __nv_bfloat16 hh, ll;
        bfsplit(v0 * scale * khw[l], hh, ll);
        g_kh[base + l] = hh; g_kl[base + l] = ll;
        bfsplit(v1 * scale * khw[32 + l], hh, ll);
        g_kh[base + 32 + l] = hh; g_kl[base + 32 + l] = ll;
    }
}

// ---------------- HMMA causal flash attention, BM=128, BN=64, d=64 ----------------
#define FS 72
#define FQH 0
#define FQL 9216
#define FSTG 18432
#define FSTGSZ 18432
#define FL_SMEM ((FSTG + 2 * FSTGSZ) * 2)   /* 110592 bytes */

__device__ __forceinline__ void flash_prefetch(uint32_t sb, int stage, int kt, int tid,
        const __nv_bfloat16* Khb, const __nv_bfloat16* Klb,
        const __nv_bfloat16* Vthb, const __nv_bfloat16* Vtlb) {
    const int base = FSTG + stage * FSTGSZ;
#pragma unroll
    for (int i = tid; i < 2048; i += 256) {
        const int arr = i >> 9;
        const int r = (i >> 3) & 63;
        const int c = i & 7;
        const uint32_t dst = sb + (uint32_t)(base + arr * 4608 + r * FS + c * 8) * 2;
        const __nv_bfloat16* src;
        if (arr == 0)      src = Khb + ((size_t)(kt * 64 + r)) * 64 + c * 8;
        else if (arr == 1) src = Klb + ((size_t)(kt * 64 + r)) * 64 + c * 8;
        else if (arr == 2) src = Vthb + (size_t)r * TSEQ + kt * 64 + c * 8;
        else               src = Vtlb + (size_t)r * TSEQ + kt * 64 + c * 8;
        cpa16(dst, src);
    }
}

__global__ __launch_bounds__(256) void flash(const float* __restrict__ xo) {
    const uint32_t sb = smem_u32(gsm);

    const int qt = gridDim.x - 1 - blockIdx.x;
    const int bh = blockIdx.y;
    const int b = bh >> 3, h = bh & 7, kvh = h >> 2;
    const int q0 = qt * 128;

    const int tid = threadIdx.x, wid = tid >> 5, lane = tid & 31;
    const int g = lane >> 2, t = lane & 3;
    const int r0 = wid * 16;

    const int arow = ((lane >> 3) & 1) * 8 + (lane & 7);
    const int acol = (lane >> 4) << 3;
    const int brow = ((lane >> 4) << 3) + (lane & 7);
    const int bcol = ((lane >> 3) & 1) * 8;
    const uint32_t qh_a = sb + (uint32_t)(FQH + (r0 + arow) * FS + acol) * 2;
    const uint32_t ql_a = sb + (uint32_t)(FQL + (r0 + arow) * FS + acol) * 2;

    const __nv_bfloat16* Qhb = &g_qh[(((size_t)b * NHEADS + h) * TSEQ + q0) * HDIM];
    const __nv_bfloat16* Qlb = &g_ql[(((size_t)b * NHEADS + h) * TSEQ + q0) * HDIM];
    const __nv_bfloat16* Khb = &g_kh[(((size_t)b * NKVH + kvh) * TSEQ) * HDIM];
    const __nv_bfloat16* Klb = &g_kl[(((size_t)b * NKVH + kvh) * TSEQ) * HDIM];
    const __nv_bfloat16* Vthb = &g_vth[(((size_t)b * NKVH + kvh) * HDIM) * TSEQ];
    const __nv_bfloat16* Vtlb = &g_vtl[(((size_t)b * NKVH + kvh) * HDIM) * TSEQ];

#pragma unroll
    for (int i = tid; i < 2048; i += 256) {
        const int half = i >> 10;
        const int r = (i >> 3) & 127;
        const int c = i & 7;
        const uint32_t dst = sb + (uint32_t)((half ? FQL : FQH) + r * FS + c * 8) * 2;
        const __nv_bfloat16* src = (half ? Qlb : Qhb) + (size_t)r * 64 + c * 8;
        cpa16(dst, src);
    }
    flash_prefetch(sb, 0, 0, tid, Khb, Klb, Vthb, Vtlb);
    CP_COMMIT();

    float m0 = -INFINITY, m1 = -INFINITY, l0 = 0.f, l1 = 0.f;
    float o[8][4];
#pragma unroll
    for (int j = 0; j < 8; j++)
#pragma unroll
        for (int r = 0; r < 4; r++) o[j][r] = 0.f;

    const int ktmax = 2 * qt + 1;
    for (int kt = 0; kt <= ktmax; kt++) {
        const int st = kt & 1;
        CP_WAIT0();
        __syncthreads();
        if (kt < ktmax) {
            flash_prefetch(sb, st ^ 1, kt + 1, tid, Khb, Klb, Vthb, Vtlb);
            CP_COMMIT();
        }

        const uint32_t stg = sb + (uint32_t)(FSTG + st * FSTGSZ) * 2;
        const uint32_t kh_b = stg + (uint32_t)(brow * FS + bcol) * 2;
        const uint32_t kl_b = kh_b + 4608 * 2;
        const uint32_t vh_b = kh_b + 9216 * 2;
        const uint32_t vl_b = kh_b + 13824 * 2;

        float s[8][4];
#pragma unroll
        for (int j = 0; j < 8; j++)
#pragma unroll
            for (int r = 0; r < 4; r++) s[j][r] = 0.f;

#pragma unroll
        for (int kk = 0; kk < 64; kk += 16) {
            uint32_t aH[4], aL[4];
            ldsm4(aH[0], aH[1], aH[2], aH[3], qh_a + (uint32_t)kk * 2);
            ldsm4(aL[0], aL[1], aL[2], aL[3], ql_a + (uint32_t)kk * 2);
#pragma unroll
            for (int jp = 0; jp < 4; jp++) {
                uint32_t h0, h1, h2, h3, lo0, lo1, lo2, lo3;
                ldsm4(h0, h1, h2, h3, kh_b + (uint32_t)(jp * 16 * FS + kk) * 2);
                ldsm4(lo0, lo1, lo2, lo3, kl_b + (uint32_t)(jp * 16 * FS + kk) * 2);
                // interleaved accumulators
                mma16816(s[2*jp],   aH[0], aH[1], aH[2], aH[3], h0, h1);
                mma16816(s[2*jp+1], aH[0], aH[1], aH[2], aH[3], h2, h3);
                mma16816(s[2*jp],   aL[0], aL[1], aL[2], aL[3], h0, h1);
                mma16816(s[2*jp+1], aL[0], aL[1], aL[2], aL[3], h2, h3);
                mma16816(s[2*jp],   aH[0], aH[1], aH[2], aH[3], lo0, lo1);
                mma16816(s[2*jp+1], aH[0], aH[1], aH[2], aH[3], lo2, lo3);
            }
        }

        // ---- causal mask (S already in log2 domain via Q pre-scale) ----
        const bool diag = (kt >= 2 * qt);
        if (diag) {
#pragma unroll
            for (int j = 0; j < 8; j++)
#pragma unroll
                for (int r = 0; r < 4; r++) {
                    const int col = kt * 64 + j * 8 + 2 * t + (r & 1);
                    const int row = q0 + r0 + g + ((r >> 1) << 3);
                    if (col > row) s[j][r] = -INFINITY;
                }
        }

        // ---- online softmax (base-2) ----
        float mx0 = -INFINITY, mx1 = -INFINITY;
#pragma unroll
        for (int j = 0; j < 8; j++) {
            mx0 = fmaxf(mx0, fmaxf(s[j][0], s[j][1]));
            mx1 = fmaxf(mx1, fmaxf(s[j][2], s[j][3]));
        }
        mx0 = fmaxf(mx0, __shfl_xor_sync(0xffffffffu, mx0, 1));
        mx0 = fmaxf(mx0, __shfl_xor_sync(0xffffffffu, mx0, 2));
        mx1 = fmaxf(mx1, __shfl_xor_sync(0xffffffffu, mx1, 1));
        mx1 = fmaxf(mx1, __shfl_xor_sync(0xffffffffu, mx1, 2));
        const float mn0 = fmaxf(m0, mx0), mn1 = fmaxf(m1, mx1);
        const float al0 = fexp2(m0 - mn0), al1 = fexp2(m1 - mn1);
        m0 = mn0; m1 = mn1;
        float rs0 = 0.f, rs1 = 0.f;
#pragma unroll
        for (int j = 0; j < 8; j++) {
            s[j][0] = fexp2(s[j][0] - m0);
            s[j][1] = fexp2(s[j][1] - m0);
            s[j][2] = fexp2(s[j][2] - m1);
            s[j][3] = fexp2(s[j][3] - m1);
            rs0 += s[j][0] + s[j][1];
            rs1 += s[j][2] + s[j][3];
        }
        rs0 += __shfl_xor_sync(0xffffffffu, rs0, 1);
        rs0 += __shfl_xor_sync(0xffffffffu, rs0, 2);
        rs1 += __shfl_xor_sync(0xffffffffu, rs1, 1);
        rs1 += __shfl_xor_sync(0xffffffffu, rs1, 2);
        l0 = l0 * al0 + rs0;
        l1 = l1 * al1 + rs1;
#pragma unroll
        for (int j = 0; j < 8; j++) {
            o[j][0] *= al0; o[j][1] *= al0;
            o[j][2] *= al1; o[j][3] *= al1;
        }

        // ---- O += P V ----
#pragma unroll
        for (int u = 0; u < 4; u++) {
            uint32_t aPh[4], aPl[4];
            {
                __nv_bfloat16 h0, h1, h2, h3, lo0, lo1, lo2, lo3;
                bfsplit(s[2*u][0], h0, lo0);   bfsplit(s[2*u][1], h1, lo1);
                bfsplit(s[2*u][2], h2, lo2);   bfsplit(s[2*u][3], h3, lo3);
                aPh[0] = packbf(h0, h1);  aPl[0] = packbf(lo0, lo1);
                aPh[1] = packbf(h2, h3);  aPl[1] = packbf(lo2, lo3);
                bfsplit(s[2*u+1][0], h0, lo0); bfsplit(s[2*u+1][1], h1, lo1);
                bfsplit(s[2*u+1][2], h2, lo2); bfsplit(s[2*u+1][3], h3, lo3);
                aPh[2] = packbf(h0, h1);  aPl[2] = packbf(lo0, lo1);
                aPh[3] = packbf(h2, h3);  aPl[3] = packbf(lo2, lo3);
            }
#pragma unroll
            for (int jp = 0; jp < 4; jp++) {
                uint32_t h0, h1, h2, h3, lo0, lo1, lo2, lo3;
                ldsm4(h0, h1, h2, h3, vh_b + (uint32_t)(jp * 16 * FS + 16 * u) * 2);
                ldsm4(lo0, lo1, lo2, lo3, vl_b + (uint32_t)(jp * 16 * FS + 16 * u) * 2);
                // interleaved accumulators
                mma16816(o[2*jp],   aPh[0], aPh[1], aPh[2], aPh[3], h0, h1);
                mma16816(o[2*jp+1], aPh[0], aPh[1], aPh[2], aPh[3], h2, h3);
                mma16816(o[2*jp],   aPl[0], aPl[1], aPl[2], aPl[3], h0, h1);
                mma16816(o[2*jp+1], aPl[0], aPl[1], aPl[2], aPl[3], h2, h3);
                mma16816(o[2*jp],   aPh[0], aPh[1], aPh[2], aPh[3], lo0, lo1);
                mma16816(o[2*jp+1], aPh[0], aPh[1], aPh[2], aPh[3], lo2, lo3);
            }
        }
    }

    const float inv0 = 1.0f / l0, inv1 = 1.0f / l1;
#pragma unroll
    for (int j = 0; j < 8; j++) {
        const int col = h * 64 + j * 8 + 2 * t;
        {
            const int row = q0 + r0 + g;
            const size_t tok = (size_t)b * TSEQ + row;
            const float2 vr = *(const float2*)&xo[tok * 960 + 448 + col];
            __nv_bfloat16 h0, lo0, h1, lo1;
            bfsplit(o[j][0] * inv0 + vr.x, h0, lo0);
            bfsplit(o[j][1] * inv0 + vr.y, h1, lo1);
            *(uint32_t*)&g_ath[tok * 512 + col] = packbf(h0, h1);
            *(uint32_t*)&g_atl[tok * 512 + col] = packbf(lo0, lo1);
        }
        {
            const int row = q0 + r0 + g + 8;
            const size_t tok = (size_t)b * TSEQ + row;
            const float2 vr = *(const float2*)&xo[tok * 960 + 448 + col];
            __nv_bfloat16 h0, lo0, h1, lo1;
            bfsplit(o[j][2] * inv1 + vr.x, h0, lo0);
            bfsplit(o[j][3] * inv1 + vr.y, h1, lo1);
            *(uint32_t*)&g_ath[tok * 512 + col] = packbf(h0, h1);
            *(uint32_t*)&g_atl[tok * 512 + col] = packbf(lo0, lo1);
        }
    }
}

// ---------------- launch ----------------
extern "C" void kernel_launch(void* const* d_in, const int* in_sizes, int n_in,
                              void* d_out, int out_size) {
    const float* x     = (const float*)d_in[0];
    const float* W_DQ  = (const float*)d_in[1];
    const float* W_UQ  = (const float*)d_in[2];
    const float* W_QR  = (const float*)d_in[3];
    const float* W_DKV = (const float*)d_in[4];
    const float* W_UK  = (const float*)d_in[5];
    const float* W_UV  = (const float*)d_in[6];
    const float* W_KR  = (const float*)d_in[7];
    const float* W_VR  = (const float*)d_in[8];
    const float* W_O   = (const float*)d_in[9];
    const float* q_ln  = (const float*)d_in[10];
    const float* kv_ln = (const float*)d_in[11];
    const float* qhw   = (const float*)d_in[12];
    const float* khw   = (const float*)d_in[13];
    float* out = (float*)d_out;

    float *xo, *qo, *ko;
    cudaGetSymbolAddress((void**)&xo, g_xo);
    cudaGetSymbolAddress((void**)&qo, g_qo);
    cudaGetSymbolAddress((void**)&ko, g_ko);

    __nv_bfloat16 *xh, *xl, *cqh, *cql, *ckvh, *ckvl, *ath, *atl;
    __nv_bfloat16 *wxh, *wxl, *wqh, *wql, *wkvh, *wkvl, *woh, *wol;
    cudaGetSymbolAddress((void**)&xh, g_xh);     cudaGetSymbolAddress((void**)&xl, g_xl);
    cudaGetSymbolAddress((void**)&cqh, g_cqh);   cudaGetSymbolAddress((void**)&cql, g_cql);
    cudaGetSymbolAddress((void**)&ckvh, g_ckvh); cudaGetSymbolAddress((void**)&ckvl, g_ckvl);
    cudaGetSymbolAddress((void**)&ath, g_ath);   cudaGetSymbolAddress((void**)&atl, g_atl);
    cudaGetSymbolAddress((void**)&wxh, g_wxh);   cudaGetSymbolAddress((void**)&wxl, g_wxl);
    cudaGetSymbolAddress((void**)&wqh, g_wqh);   cudaGetSymbolAddress((void**)&wql, g_wql);
    cudaGetSymbolAddress((void**)&wkvh, g_wkvh); cudaGetSymbolAddress((void**)&wkvl, g_wkvl);
    cudaGetSymbolAddress((void**)&woh, g_woh);   cudaGetSymbolAddress((void**)&wol, g_wol);

    cudaFuncSetAttribute(flash, cudaFuncAttributeMaxDynamicSharedMemorySize, FL_SMEM);
    cudaFuncSetAttribute(hgemm_bs, cudaFuncAttributeMaxDynamicSharedMemorySize, GB_SMEM);

    // ---- merged prep ----
    PrepJobs js;
    js.j[0] = { x, xh, xl, 0, 0, 4096, 0 };
    js.j[1] = { W_DQ,  wxh,             wxl,             512, 256, (256/32)*(512/32), 1 };
    js.j[2] = { W_DKV, wxh + 256 * 512, wxl + 256 * 512, 512, 128, (128/32)*(512/32), 1 };
    js.j[3] = { W_KR,  wxh + 384 * 512, wxl + 384 * 512, 512,  64, ( 64/32)*(512/32), 1 };
    js.j[4] = { W_VR,  wxh + 448 * 512, wxl + 448 * 512, 512, 512, (512/32)*(512/32), 1 };
    js.j[5] = { W_UQ,  wqh,             wql,             256, 256, (256/32)*(256/32), 1 };
    js.j[6] = { W_QR,  wqh + 256 * 256, wql + 256 * 256, 256, 256, (256/32)*(256/32), 1 };
    js.j[7] = { W_UK,  wkvh,            wkvl,            128,  64, ( 64/32)*(128/32), 1 };
    js.j[8] = { W_UV,  wkvh + 64 * 128, wkvl + 64 * 128, 128, 128, (128/32)*(128/32), 1 };
    js.j[9] = { W_O,   woh,             wol,             512, 512, (512/32)*(512/32), 1 };
    int total = 0;
    for (int i = 0; i < 10; i++) total += js.j[i].nb;
    prep<<<total, 256>>>(js);

#define GEMMB(Ah, Al, Bh, Bl, Cm, Mv, Nv, Kv, Ldc) \
    hgemm_bs<<<dim3((Nv) / 64, (Mv) / 128), 256, GB_SMEM>>>(Ah, Al, Bh, Bl, Cm, Mv, Nv, Kv, Ldc)

    // fused x projections: [cq | ckv | krope | vres]
    GEMMB(xh, xl, wxh, wxl, xo, NTOK, 960, 512, 960);

    // fused latent RMS norms (+ split)
    rms2<<<NTOK, 384>>>(xo, q_ln, kv_ln, cqh, cql, ckvh, ckvl);

    // fused up-projections
    GEMMB(cqh,  cql,  wqh,  wql,  qo, NTOK, 512, 256, 512);
    GEMMB(ckvh, ckvl, wkvh, wkvl, ko, NTOK, 192, 128, 192);

    // rope + head-RMS + split (Q pre-scaled) + V transpose, one launch
    assemble_vt<<<NTOK + BATCH * NKVH * (TSEQ / 64), 256>>>(qhw, khw);

    // causal flash attention + v_res
    flash<<<dim3(TSEQ / 128, BATCH * NHEADS), 256, FL_SMEM>>>(xo);

    // output projection
    GEMMB(ath, atl, woh, wol, out, NTOK, 512, 512, 512);
}

// round 17
// speedup vs baseline: 3.1146x; 1.0475x over previous
#include <cuda_runtime.h>
#include <cuda_bf16.h>
#include <math.h>
#include <stdint.h>

#define NHEADS 8
#define NKVH   2
#define HDIM   64
#define TSEQ   2048
#define BATCH  4
#define NTOK   (BATCH*TSEQ)   /* 8192 */
#define SCL2 0.18033688011112042f      /* 0.125 * log2(e) */

// ---------------- scratch (device globals; no allocation allowed) ----------------
__device__ float g_xo[NTOK*960];   // [cq 0:256 | ckv 256:384 | krope 384:448 | vres 448:960]
__device__ float g_qo[NTOK*512];   // [qnope 0:256 | qrope 256:512]
__device__ float g_ko[NTOK*192];   // [knope 0:64 | vv 64:192]
__device__ __nv_bfloat16 g_xh  [NTOK*512], g_xl  [NTOK*512];
__device__ __nv_bfloat16 g_cqh [NTOK*256], g_cql [NTOK*256];
__device__ __nv_bfloat16 g_ckvh[NTOK*128], g_ckvl[NTOK*128];
__device__ __nv_bfloat16 g_ath [NTOK*512], g_atl [NTOK*512];
__device__ __nv_bfloat16 g_wxh [960*512], g_wxl [960*512];
__device__ __nv_bfloat16 g_wqh [512*256], g_wql [512*256];
__device__ __nv_bfloat16 g_wkvh[192*128], g_wkvl[192*128];
__device__ __nv_bfloat16 g_woh [512*512], g_wol [512*512];
__device__ __nv_bfloat16 g_qh [BATCH*NHEADS*TSEQ*HDIM];
__device__ __nv_bfloat16 g_ql [BATCH*NHEADS*TSEQ*HDIM];
__device__ __nv_bfloat16 g_kh [BATCH*NKVH*TSEQ*HDIM];
__device__ __nv_bfloat16 g_kl [BATCH*NKVH*TSEQ*HDIM];
__device__ __nv_bfloat16 g_vth[BATCH*NKVH*HDIM*TSEQ];
__device__ __nv_bfloat16 g_vtl[BATCH*NKVH*HDIM*TSEQ];

__device__ __forceinline__ uint32_t packbf(__nv_bfloat16 a, __nv_bfloat16 b) {
    return ((uint32_t)__bfloat16_as_ushort(b) << 16) | (uint32_t)__bfloat16_as_ushort(a);
}
__device__ __forceinline__ void mma16816(float* c, uint32_t a0, uint32_t a1,
                                         uint32_t a2, uint32_t a3,
                                         uint32_t b0, uint32_t b1) {
    asm volatile(
        "mma.sync.aligned.m16n8k16.row.col.f32.bf16.bf16.f32 "
        "{%0,%1,%2,%3}, {%4,%5,%6,%7}, {%8,%9}, {%0,%1,%2,%3};"
        : "+f"(c[0]), "+f"(c[1]), "+f"(c[2]), "+f"(c[3])
        : "r"(a0), "r"(a1), "r"(a2), "r"(a3), "r"(b0), "r"(b1));
}
__device__ __forceinline__ void ldsm4(uint32_t& r0, uint32_t& r1, uint32_t& r2,
                                      uint32_t& r3, uint32_t addr) {
    asm volatile("ldmatrix.sync.aligned.m8n8.x4.shared.b16 {%0,%1,%2,%3}, [%4];"
                 : "=r"(r0), "=r"(r1), "=r"(r2), "=r"(r3) : "r"(addr));
}
__device__ __forceinline__ void bfsplit(float v, __nv_bfloat16& h, __nv_bfloat16& l) {
    h = __float2bfloat16(v);
    l = __float2bfloat16(v - __bfloat162float(h));
}
__device__ __forceinline__ float fexp2(float x) {
    float y;
    asm("ex2.approx.f32 %0, %1;" : "=f"(y) : "f"(x));
    return y;
}
__device__ __forceinline__ uint32_t smem_u32(const void* p) {
    uint32_t a;
    asm("{ .reg .u64 t; cvta.to.shared.u64 t, %1; cvt.u32.u64 %0, t; }" : "=r"(a) : "l"(p));
    return a;
}
__device__ __forceinline__ void cpa16(uint32_t dst, const void* src) {
    asm volatile("cp.async.ca.shared.global [%0], [%1], 16;" :: "r"(dst), "l"(src) : "memory");
}
#define CP_COMMIT() asm volatile("cp.async.commit_group;" ::: "memory")
#define CP_WAIT0()  asm volatile("cp.async.wait_group 0;" ::: "memory")

// ---------------- merged prep: activation split + all weight transpose-splits ----------------
struct PrepJob {
    const float* W;
    __nv_bfloat16* Wh;
    __nv_bfloat16* Wl;
    int K, N, nb, type;
};
struct PrepJobs { PrepJob j[10]; };

__global__ __launch_bounds__(256) void prep(PrepJobs js) {
    __shared__ float tile[32][33];
    int bid = blockIdx.x;
    int ji = 0;
    while (bid >= js.j[ji].nb) { bid -= js.j[ji].nb; ji++; }
    const PrepJob jb = js.j[ji];
    const int tid = threadIdx.x;

    if (jb.type == 0) {
        const int i = bid * 256 + tid;
        const float4 v = ((const float4*)jb.W)[i];
        __nv_bfloat16 h0, h1, h2, h3, l0, l1, l2, l3;
        bfsplit(v.x, h0, l0); bfsplit(v.y, h1, l1);
        bfsplit(v.z, h2, l2); bfsplit(v.w, h3, l3);
        ((uint2*)jb.Wh)[i] = make_uint2(packbf(h0, h1), packbf(h2, h3));
        ((uint2*)jb.Wl)[i] = make_uint2(packbf(l0, l1), packbf(l2, l3));
    } else {
        const int tpx = jb.N >> 5;
        const int n0 = (bid % tpx) * 32, k0 = (bid / tpx) * 32;
        for (int i = tid; i < 1024; i += 256) {
            const int r = i >> 5, c = i & 31;
            tile[r][c] = jb.W[(size_t)(k0 + r) * jb.N + n0 + c];
        }
        __syncthreads();
        for (int i = tid; i < 1024; i += 256) {
            const int n = i >> 5, k = i & 31;
            __nv_bfloat16 h, l;
            bfsplit(tile[k][n], h, l);
            jb.Wh[(size_t)(n0 + n) * jb.K + k0 + k] = h;
            jb.Wl[(size_t)(n0 + n) * jb.K + k0 + k] = l;
        }
    }
}

// ---------------- fused latent RMS norms (cq 256 + ckv 128) -> bf16 hi/lo ----------------
__global__ __launch_bounds__(384) void rms2(const float* __restrict__ xo,
                                            const float* __restrict__ qw,
                                            const float* __restrict__ kvw,
                                            __nv_bfloat16* __restrict__ cqh,
                                            __nv_bfloat16* __restrict__ cql,
                                            __nv_bfloat16* __restrict__ ckvh,
                                            __nv_bfloat16* __restrict__ ckvl) {
    const int n = blockIdx.x;
    const int tid = threadIdx.x;
    __shared__ float sh[12];
    const bool isq = tid < 256;
    const int d = isq ? tid : tid - 256;
    const float v = xo[(size_t)n * 960 + (isq ? 0 : 256) + d];
    float ss = v * v;
#pragma unroll
    for (int o = 16; o > 0; o >>= 1) ss += __shfl_xor_sync(0xffffffffu, ss, o);
    const int wid = tid >> 5;
    if ((tid & 31) == 0) sh[wid] = ss;
    __syncthreads();
    float tot = 0.f;
    if (isq) { for (int i = 0; i < 8; i++)  tot += sh[i]; }
    else     { for (int i = 8; i < 12; i++) tot += sh[i]; }
    const float scale = rsqrtf(tot / (isq ? 256.0f : 128.0f) + 1e-6f);
    __nv_bfloat16 h, l;
    bfsplit(v * scale * (isq ? qw[d] : kvw[d]), h, l);
    if (isq) { cqh [(size_t)n * 256 + d] = h; cql [(size_t)n * 256 + d] = l; }
    else     { ckvh[(size_t)n * 128 + d] = h; ckvl[(size_t)n * 128 + d] = l; }
}

// ---------------- bf16x3 HMMA GEMM ----------------
#define GS 72
#define GB_AH 0
#define GB_AL 9216
#define GB_BH 18432
#define GB_BL 23040
#define GB_STG 27648
#define GB_SMEM (2 * GB_STG * 2)        /* 110592 bytes */

extern __shared__ char gsm[];

__device__ __forceinline__ void gemm_prefetch(uint32_t sb, int stage, int c64, int tid,
        const __nv_bfloat16* Ah, const __nv_bfloat16* Al,
        const __nv_bfloat16* Bh, const __nv_bfloat16* Bl,
        int m0, int n0, int K) {
    const int base = stage * GB_STG;
#pragma unroll
    for (int i = tid; i < 2048; i += 256) {
        const int half = i >> 10;
        const int r = (i >> 3) & 127;
        const int cc = i & 7;
        const uint32_t dst = sb + (uint32_t)(base + (half ? GB_AL : GB_AH) + r * GS + cc * 8) * 2;
        const __nv_bfloat16* src = (half ? Al : Ah) + (size_t)(m0 + r) * K + c64 + cc * 8;
        cpa16(dst, src);
    }
#pragma unroll
    for (int i = tid; i < 1024; i += 256) {
        const int half = i >> 9;
        const int r = (i >> 3) & 63;
        const int cc = i & 7;
        const uint32_t dst = sb + (uint32_t)(base + (half ? GB_BL : GB_BH) + r * GS + cc * 8) * 2;
        const __nv_bfloat16* src = (half ? Bl : Bh) + (size_t)(n0 + r) * K + c64 + cc * 8;
        cpa16(dst, src);
    }
}

__global__ __launch_bounds__(256) void hgemm_bs(
        const __nv_bfloat16* __restrict__ Ah, const __nv_bfloat16* __restrict__ Al,
        const __nv_bfloat16* __restrict__ Bh, const __nv_bfloat16* __restrict__ Bl,
        float* __restrict__ C, int M, int N, int K, int ldc) {
    const uint32_t sb = smem_u32(gsm);

    const int tid = threadIdx.x, wid = tid >> 5, lane = tid & 31;
    const int wm = wid & 3, wn = wid >> 2;
    const int g = lane >> 2, t = lane & 3;
    const int m0 = blockIdx.y * 128, n0 = blockIdx.x * 64;

    const int arow = ((lane >> 3) & 1) * 8 + (lane & 7);
    const int acol = (lane >> 4) << 3;
    const int brow = ((lane >> 4) << 3) + (lane & 7);
    const int bcol = ((lane >> 3) & 1) * 8;

    float acc[2][4][4];
#pragma unroll
    for (int i = 0; i < 2; i++)
#pragma unroll
        for (int j = 0; j < 4; j++)
#pragma unroll
            for (int r = 0; r < 4; r++) acc[i][j][r] = 0.f;

    const int nch = K >> 6;
    gemm_prefetch(sb, 0, 0, tid, Ah, Al, Bh, Bl, m0, n0, K);
    CP_COMMIT();

    for (int c = 0; c < nch; c++) {
        const int st = c & 1;
        CP_WAIT0();
        __syncthreads();
        if (c + 1 < nch) {
            gemm_prefetch(sb, st ^ 1, (c + 1) << 6, tid, Ah, Al, Bh, Bl, m0, n0, K);
            CP_COMMIT();
        }

        const uint32_t stg = sb + (uint32_t)(st * GB_STG) * 2;
        const uint32_t aH_b = stg + (uint32_t)(GB_AH + (wm * 32 + arow) * GS + acol) * 2;
        const uint32_t aL_b = stg + (uint32_t)(GB_AL + (wm * 32 + arow) * GS + acol) * 2;
        const uint32_t bH_b = stg + (uint32_t)(GB_BH + (wn * 32 + brow) * GS + bcol) * 2;
        const uint32_t bL_b = stg + (uint32_t)(GB_BL + (wn * 32 + brow) * GS + bcol) * 2;

#pragma unroll
        for (int kk = 0; kk < 64; kk += 16) {
            uint32_t ah[2][4], al[2][4];
#pragma unroll
            for (int i = 0; i < 2; i++) {
                ldsm4(ah[i][0], ah[i][1], ah[i][2], ah[i][3],
                      aH_b + (uint32_t)(i * 16 * GS + kk) * 2);
                ldsm4(al[i][0], al[i][1], al[i][2], al[i][3],
                      aL_b + (uint32_t)(i * 16 * GS + kk) * 2);
            }
#pragma unroll
            for (int jp = 0; jp < 2; jp++) {
                uint32_t h0, h1, h2, h3, l0, l1, l2, l3;
                ldsm4(h0, h1, h2, h3, bH_b + (uint32_t)(jp * 16 * GS + kk) * 2);
                ldsm4(l0, l1, l2, l3, bL_b + (uint32_t)(jp * 16 * GS + kk) * 2);
                // R13 grouping (measured fastest)
#pragma unroll
                for (int i = 0; i < 2; i++) {
                    mma16816(acc[i][2*jp],   ah[i][0], ah[i][1], ah[i][2], ah[i][3], h0, h1);
                    mma16816(acc[i][2*jp],   al[i][0], al[i][1], al[i][2], al[i][3], h0, h1);
                    mma16816(acc[i][2*jp],   ah[i][0], ah[i][1], ah[i][2], ah[i][3], l0, l1);
                    mma16816(acc[i][2*jp+1], ah[i][0], ah[i][1], ah[i][2], ah[i][3], h2, h3);
                    mma16816(acc[i][2*jp+1], al[i][0], al[i][1], al[i][2], al[i][3], h2, h3);
                    mma16816(acc[i][2*jp+1], ah[i][0], ah[i][1], ah[i][2], ah[i][3], l2, l3);
                }
            }
        }
    }

#pragma unroll
    for (int i = 0; i < 2; i++)
#pragma unroll
        for (int j = 0; j < 4; j++) {
            const int row = m0 + wm * 32 + i * 16 + g;
            const int col = n0 + wn * 32 + j * 8 + 2 * t;
            *(float2*)&C[(size_t)row * ldc + col]       = make_float2(acc[i][j][0], acc[i][j][1]);
            *(float2*)&C[(size_t)(row + 8) * ldc + col] = make_float2(acc[i][j][2], acc[i][j][3]);
        }
}

// ---- merged assemble (RoPE+head-RMS+split; Q pre-scaled by SCL2) + V transpose ----
__global__ __launch_bounds__(256) void assemble_vt(const float* __restrict__ qhw,
                                                   const float* __restrict__ khw) {
    __shared__ __nv_bfloat16 shv[64][65], slv[64][65];
    if (blockIdx.x >= NTOK) {
        const int vb = blockIdx.x - NTOK;
        const int bk = vb & 7;               // b*NKVH + kvh
        const int t0 = (vb >> 3) * 64;
        const int b = bk >> 1, kvh = bk & 1;
        const int tid = threadIdx.x;
        for (int i = tid; i < 4096; i += 256) {
            const int tt = i >> 6, d = i & 63;
            float v = g_ko[(size_t)(b * TSEQ + t0 + tt) * 192 + 64 + kvh * 64 + d];
            __nv_bfloat16 hh, ll;
            bfsplit(v, hh, ll);
            shv[tt][d] = hh; slv[tt][d] = ll;
        }
        __syncthreads();
        for (int i = tid; i < 4096; i += 256) {
            const int d = i >> 6, tt = i & 63;
            g_vth[((size_t)bk * 64 + d) * TSEQ + t0 + tt] = shv[tt][d];
            g_vtl[((size_t)bk * 64 + d) * TSEQ + t0 + tt] = slv[tt][d];
        }
        return;
    }
    const int n = blockIdx.x;
    const int b = n / TSEQ, t = n % TSEQ;
    const int tid = threadIdx.x, w = tid >> 5, l = tid & 31;

    const int j = l & 15;
    const float invf = powf(500000.0f, -(float)j / 16.0f);
    const float f = (float)t * invf;
    const float cs = cosf(f), sn = sinf(f);

    {
        const int h = w;
        float v0 = g_qo[(size_t)n * 512 + h * 32 + l];
        const float* qr = &g_qo[(size_t)n * 512 + 256 + h * 32];
        float a = qr[l];
        float v1 = (l < 16) ? (a * cs - qr[l + 16] * sn) : (a * cs + qr[l - 16] * sn);
        float ss = v0 * v0 + v1 * v1;
#pragma unroll
        for (int o = 16; o > 0; o >>= 1) ss += __shfl_xor_sync(0xffffffffu, ss, o);
        float scale = rsqrtf(ss / 64.0f + 1e-6f) * SCL2;   // fold softmax scale into Q
        const size_t base = (((size_t)b * NHEADS + h) * TSEQ + t) * HDIM;
        __nv_bfloat16 hh, ll;
        bfsplit(v0 * scale * qhw[l], hh, ll);
        g_qh[base + l] = hh; g_ql[base + l] = ll;
        bfsplit(v1 * scale * qhw[32 + l], hh, ll);
        g_qh[base + 32 + l] = hh; g_ql[base + 32 + l] = ll;
    }
    if (w < 2) {
        const int kvh = w;
        float v0 = g_ko[(size_t)n * 192 + kvh * 32 + l];
        const float* kr = &g_xo[(size_t)n * 960 + 384 + kvh * 32];
        float a = kr[l];
        float v1 = (l < 16) ? (a * cs - kr[l + 16] * sn) : (a * cs + kr[l - 16] * sn);
        float ss = v0 * v0 + v1 * v1;
#pragma unroll
        for (int o = 16; o > 0; o >>= 1) ss += __shfl_xor_sync(0xffffffffu, ss, o);
        float scale = rsqrtf(ss / 64.0f + 1e-6f);
        const size_t base = (((size_t)b * NKVH + kvh) * TSEQ + t) * HDIM;
        __nv_bfloat16 hh, ll;
        bfsplit(v0 * scale * khw[l], hh, ll);
        g_kh[base + l] = hh; g_kl[base + l] = ll;
        bfsplit(v1 * scale * khw[32 + l], hh, ll);
        g_kh[base + 32 + l] = hh; g_kl[base + 32 + l] = ll;
    }
}

// ---------------- HMMA causal flash attention, BM=128, BN=64, d=64 ----------------
#define FS 72
#define FQH 0
#define FQL 9216
#define FSTG 18432
#define FSTGSZ 18432
#define FL_SMEM ((FSTG + 2 * FSTGSZ) * 2)   /* 110592 bytes */

__device__ __forceinline__ void flash_prefetch(uint32_t sb, int stage, int kt, int tid,
        const __nv_bfloat16* Khb, const __nv_bfloat16* Klb,
        const __nv_bfloat16* Vthb, const __nv_bfloat16* Vtlb) {
    const int base = FSTG + stage * FSTGSZ;
#pragma unroll
    for (int i = tid; i < 2048; i += 256) {
        const int arr = i >> 9;
        const int r = (i >> 3) & 63;
        const int c = i & 7;
        const uint32_t dst = sb + (uint32_t)(base + arr * 4608 + r * FS + c * 8) * 2;
        const __nv_bfloat16* src;
        if (arr == 0)      src = Khb + ((size_t)(kt * 64 + r)) * 64 + c * 8;
        else if (arr == 1) src = Klb + ((size_t)(kt * 64 + r)) * 64 + c * 8;
        else if (arr == 2) src = Vthb + (size_t)r * TSEQ + kt * 64 + c * 8;
        else               src = Vtlb + (size_t)r * TSEQ + kt * 64 + c * 8;
        cpa16(dst, src);
    }
}

__global__ __launch_bounds__(256, 2) void flash(const float* __restrict__ xo) {
    const uint32_t sb = smem_u32(gsm);

    const int qt = gridDim.x - 1 - blockIdx.x;
    const int bh = blockIdx.y;
    const int b = bh >> 3, h = bh & 7, kvh = h >> 2;
    const int q0 = qt * 128;

    const int tid = threadIdx.x, wid = tid >> 5, lane = tid & 31;
    const int g = lane >> 2, t = lane & 3;
    const int r0 = wid * 16;

    const int arow = ((lane >> 3) & 1) * 8 + (lane & 7);
    const int acol = (lane >> 4) << 3;
    const int brow = ((lane >> 4) << 3) + (lane & 7);
    const int bcol = ((lane >> 3) & 1) * 8;
    const uint32_t qh_a = sb + (uint32_t)(FQH + (r0 + arow) * FS + acol) * 2;
    const uint32_t ql_a = sb + (uint32_t)(FQL + (r0 + arow) * FS + acol) * 2;

    const __nv_bfloat16* Qhb = &g_qh[(((size_t)b * NHEADS + h) * TSEQ + q0) * HDIM];
    const __nv_bfloat16* Qlb = &g_ql[(((size_t)b * NHEADS + h) * TSEQ + q0) * HDIM];
    const __nv_bfloat16* Khb = &g_kh[(((size_t)b * NKVH + kvh) * TSEQ) * HDIM];
    const __nv_bfloat16* Klb = &g_kl[(((size_t)b * NKVH + kvh) * TSEQ) * HDIM];
    const __nv_bfloat16* Vthb = &g_vth[(((size_t)b * NKVH + kvh) * HDIM) * TSEQ];
    const __nv_bfloat16* Vtlb = &g_vtl[(((size_t)b * NKVH + kvh) * HDIM) * TSEQ];

#pragma unroll
    for (int i = tid; i < 2048; i += 256) {
        const int half = i >> 10;
        const int r = (i >> 3) & 127;
        const int c = i & 7;
        const uint32_t dst = sb + (uint32_t)((half ? FQL : FQH) + r * FS + c * 8) * 2;
        const __nv_bfloat16* src = (half ? Qlb : Qhb) + (size_t)r * 64 + c * 8;
        cpa16(dst, src);
    }
    flash_prefetch(sb, 0, 0, tid, Khb, Klb, Vthb, Vtlb);
    CP_COMMIT();

    float m0 = -INFINITY, m1 = -INFINITY, l0 = 0.f, l1 = 0.f;
    float o[8][4];
#pragma unroll
    for (int j = 0; j < 8; j++)
#pragma unroll
        for (int r = 0; r < 4; r++) o[j][r] = 0.f;

    const int ktmax = 2 * qt + 1;
    for (int kt = 0; kt <= ktmax; kt++) {
        const int st = kt & 1;
        CP_WAIT0();
        __syncthreads();
        if (kt < ktmax) {
            flash_prefetch(sb, st ^ 1, kt + 1, tid, Khb, Klb, Vthb, Vtlb);
            CP_COMMIT();
        }

        const uint32_t stg = sb + (uint32_t)(FSTG + st * FSTGSZ) * 2;
        const uint32_t kh_b = stg + (uint32_t)(brow * FS + bcol) * 2;
        const uint32_t kl_b = kh_b + 4608 * 2;
        const uint32_t vh_b = kh_b + 9216 * 2;
        const uint32_t vl_b = kh_b + 13824 * 2;

        float s[8][4];
#pragma unroll
        for (int j = 0; j < 8; j++)
#pragma unroll
            for (int r = 0; r < 4; r++) s[j][r] = 0.f;

#pragma unroll
        for (int kk = 0; kk < 64; kk += 16) {
            uint32_t aH[4], aL[4];
            ldsm4(aH[0], aH[1], aH[2], aH[3], qh_a + (uint32_t)kk * 2);
            ldsm4(aL[0], aL[1], aL[2], aL[3], ql_a + (uint32_t)kk * 2);
#pragma unroll
            for (int jp = 0; jp < 4; jp++) {
                uint32_t h0, h1, h2, h3, lo0, lo1, lo2, lo3;
                ldsm4(h0, h1, h2, h3, kh_b + (uint32_t)(jp * 16 * FS + kk) * 2);
                ldsm4(lo0, lo1, lo2, lo3, kl_b + (uint32_t)(jp * 16 * FS + kk) * 2);
                mma16816(s[2*jp],   aH[0], aH[1], aH[2], aH[3], h0, h1);
                mma16816(s[2*jp+1], aH[0], aH[1], aH[2], aH[3], h2, h3);
                mma16816(s[2*jp],   aL[0], aL[1], aL[2], aL[3], h0, h1);
                mma16816(s[2*jp+1], aL[0], aL[1], aL[2], aL[3], h2, h3);
                mma16816(s[2*jp],   aH[0], aH[1], aH[2], aH[3], lo0, lo1);
                mma16816(s[2*jp+1], aH[0], aH[1], aH[2], aH[3], lo2, lo3);
            }
        }

        // ---- causal mask (S already in log2 domain via Q pre-scale) ----
        const bool diag = (kt >= 2 * qt);
        if (diag) {
#pragma unroll
            for (int j = 0; j < 8; j++)
#pragma unroll
                for (int r = 0; r < 4; r++) {
                    const int col = kt * 64 + j * 8 + 2 * t + (r & 1);
                    const int row = q0 + r0 + g + ((r >> 1) << 3);
                    if (col > row) s[j][r] = -INFINITY;
                }
        }

        // ---- online softmax (base-2) ----
        float mx0 = -INFINITY, mx1 = -INFINITY;
#pragma unroll
        for (int j = 0; j < 8; j++) {
            mx0 = fmaxf(mx0, fmaxf(s[j][0], s[j][1]));
            mx1 = fmaxf(mx1, fmaxf(s[j][2], s[j][3]));
        }
        mx0 = fmaxf(mx0, __shfl_xor_sync(0xffffffffu, mx0, 1));
        mx0 = fmaxf(mx0, __shfl_xor_sync(0xffffffffu, mx0, 2));
        mx1 = fmaxf(mx1, __shfl_xor_sync(0xffffffffu, mx1, 1));
        mx1 = fmaxf(mx1, __shfl_xor_sync(0xffffffffu, mx1, 2));
        const float mn0 = fmaxf(m0, mx0), mn1 = fmaxf(m1, mx1);
        const float al0 = fexp2(m0 - mn0), al1 = fexp2(m1 - mn1);
        m0 = mn0; m1 = mn1;
        float rs0 = 0.f, rs1 = 0.f;
#pragma unroll
        for (int j = 0; j < 8; j++) {
            s[j][0] = fexp2(s[j][0] - m0);
            s[j][1] = fexp2(s[j][1] - m0);
            s[j][2] = fexp2(s[j][2] - m1);
            s[j][3] = fexp2(s[j][3] - m1);
            rs0 += s[j][0] + s[j][1];
            rs1 += s[j][2] + s[j][3];
        }
        rs0 += __shfl_xor_sync(0xffffffffu, rs0, 1);
        rs0 += __shfl_xor_sync(0xffffffffu, rs0, 2);
        rs1 += __shfl_xor_sync(0xffffffffu, rs1, 1);
        rs1 += __shfl_xor_sync(0xffffffffu, rs1, 2);
        l0 = l0 * al0 + rs0;
        l1 = l1 * al1 + rs1;
#pragma unroll
        for (int j = 0; j < 8; j++) {
            o[j][0] *= al0; o[j][1] *= al0;
            o[j][2] *= al1; o[j][3] *= al1;
        }

        // ---- O += P V ----
#pragma unroll
        for (int u = 0; u < 4; u++) {
            uint32_t aPh[4], aPl[4];
            {
                __nv_bfloat16 h0, h1, h2, h3, lo0, lo1, lo2, lo3;
                bfsplit(s[2*u][0], h0, lo0);   bfsplit(s[2*u][1], h1, lo1);
                bfsplit(s[2*u][2], h2, lo2);   bfsplit(s[2*u][3], h3, lo3);
                aPh[0] = packbf(h0, h1);  aPl[0] = packbf(lo0, lo1);
                aPh[1] = packbf(h2, h3);  aPl[1] = packbf(lo2, lo3);
                bfsplit(s[2*u+1][0], h0, lo0); bfsplit(s[2*u+1][1], h1, lo1);
                bfsplit(s[2*u+1][2], h2, lo2); bfsplit(s[2*u+1][3], h3, lo3);
                aPh[2] = packbf(h0, h1);  aPl[2] = packbf(lo0, lo1);
                aPh[3] = packbf(h2, h3);  aPl[3] = packbf(lo2, lo3);
            }
#pragma unroll
            for (int jp = 0; jp < 4; jp++) {
                uint32_t h0, h1, h2, h3, lo0, lo1, lo2, lo3;
                ldsm4(h0, h1, h2, h3, vh_b + (uint32_t)(jp * 16 * FS + 16 * u) * 2);
                ldsm4(lo0, lo1, lo2, lo3, vl_b + (uint32_t)(jp * 16 * FS + 16 * u) * 2);
                mma16816(o[2*jp],   aPh[0], aPh[1], aPh[2], aPh[3], h0, h1);
                mma16816(o[2*jp+1], aPh[0], aPh[1], aPh[2], aPh[3], h2, h3);
                mma16816(o[2*jp],   aPl[0], aPl[1], aPl[2], aPl[3], h0, h1);
                mma16816(o[2*jp+1], aPl[0], aPl[1], aPl[2], aPl[3], h2, h3);
                mma16816(o[2*jp],   aPh[0], aPh[1], aPh[2], aPh[3], lo0, lo1);
                mma16816(o[2*jp+1], aPh[0], aPh[1], aPh[2], aPh[3], lo2, lo3);
            }
        }
    }

    const float inv0 = 1.0f / l0, inv1 = 1.0f / l1;
#pragma unroll
    for (int j = 0; j < 8; j++) {
        const int col = h * 64 + j * 8 + 2 * t;
        {
            const int row = q0 + r0 + g;
            const size_t tok = (size_t)b * TSEQ + row;
            const float2 vr = *(const float2*)&xo[tok * 960 + 448 + col];
            __nv_bfloat16 h0, lo0, h1, lo1;
            bfsplit(o[j][0] * inv0 + vr.x, h0, lo0);
            bfsplit(o[j][1] * inv0 + vr.y, h1, lo1);
            *(uint32_t*)&g_ath[tok * 512 + col] = packbf(h0, h1);
            *(uint32_t*)&g_atl[tok * 512 + col] = packbf(lo0, lo1);
        }
        {
            const int row = q0 + r0 + g + 8;
            const size_t tok = (size_t)b * TSEQ + row;
            const float2 vr = *(const float2*)&xo[tok * 960 + 448 + col];
            __nv_bfloat16 h0, lo0, h1, lo1;
            bfsplit(o[j][2] * inv1 + vr.x, h0, lo0);
            bfsplit(o[j][3] * inv1 + vr.y, h1, lo1);
            *(uint32_t*)&g_ath[tok * 512 + col] = packbf(h0, h1);
            *(uint32_t*)&g_atl[tok * 512 + col] = packbf(lo0, lo1);
        }
    }
}

// ---------------- launch ----------------
extern "C" void kernel_launch(void* const* d_in, const int* in_sizes, int n_in,
                              void* d_out, int out_size) {
    const float* x     = (const float*)d_in[0];
    const float* W_DQ  = (const float*)d_in[1];
    const float* W_UQ  = (const float*)d_in[2];
    const float* W_QR  = (const float*)d_in[3];
    const float* W_DKV = (const float*)d_in[4];
    const float* W_UK  = (const float*)d_in[5];
    const float* W_UV  = (const float*)d_in[6];
    const float* W_KR  = (const float*)d_in[7];
    const float* W_VR  = (const float*)d_in[8];
    const float* W_O   = (const float*)d_in[9];
    const float* q_ln  = (const float*)d_in[10];
    const float* kv_ln = (const float*)d_in[11];
    const float* qhw   = (const float*)d_in[12];
    const float* khw   = (const float*)d_in[13];
    float* out = (float*)d_out;

    float *xo, *qo, *ko;
    cudaGetSymbolAddress((void**)&xo, g_xo);
    cudaGetSymbolAddress((void**)&qo, g_qo);
    cudaGetSymbolAddress((void**)&ko, g_ko);

    __nv_bfloat16 *xh, *xl, *cqh, *cql, *ckvh, *ckvl, *ath, *atl;
    __nv_bfloat16 *wxh, *wxl, *wqh, *wql, *wkvh, *wkvl, *woh, *wol;
    cudaGetSymbolAddress((void**)&xh, g_xh);     cudaGetSymbolAddress((void**)&xl, g_xl);
    cudaGetSymbolAddress((void**)&cqh, g_cqh);   cudaGetSymbolAddress((void**)&cql, g_cql);
    cudaGetSymbolAddress((void**)&ckvh, g_ckvh); cudaGetSymbolAddress((void**)&ckvl, g_ckvl);
    cudaGetSymbolAddress((void**)&ath, g_ath);   cudaGetSymbolAddress((void**)&atl, g_atl);
    cudaGetSymbolAddress((void**)&wxh, g_wxh);   cudaGetSymbolAddress((void**)&wxl, g_wxl);
    cudaGetSymbolAddress((void**)&wqh, g_wqh);   cudaGetSymbolAddress((void**)&wql, g_wql);
    cudaGetSymbolAddress((void**)&wkvh, g_wkvh); cudaGetSymbolAddress((void**)&wkvl, g_wkvl);
    cudaGetSymbolAddress((void**)&woh, g_woh);   cudaGetSymbolAddress((void**)&wol, g_wol);

    cudaFuncSetAttribute(flash, cudaFuncAttributeMaxDynamicSharedMemorySize, FL_SMEM);
    cudaFuncSetAttribute(hgemm_bs, cudaFuncAttributeMaxDynamicSharedMemorySize, GB_SMEM);

    // ---- merged prep ----
    PrepJobs js;
    js.j[0] = { x, xh, xl, 0, 0, 4096, 0 };
    js.j[1] = { W_DQ,  wxh,             wxl,             512, 256, (256/32)*(512/32), 1 };
    js.j[2] = { W_DKV, wxh + 256 * 512, wxl + 256 * 512, 512, 128, (128/32)*(512/32), 1 };
    js.j[3] = { W_KR,  wxh + 384 * 512, wxl + 384 * 512, 512,  64, ( 64/32)*(512/32), 1 };
    js.j[4] = { W_VR,  wxh + 448 * 512, wxl + 448 * 512, 512, 512, (512/32)*(512/32), 1 };
    js.j[5] = { W_UQ,  wqh,             wql,             256, 256, (256/32)*(256/32), 1 };
    js.j[6] = { W_QR,  wqh + 256 * 256, wql + 256 * 256, 256, 256, (256/32)*(256/32), 1 };
    js.j[7] = { W_UK,  wkvh,            wkvl,            128,  64, ( 64/32)*(128/32), 1 };
    js.j[8] = { W_UV,  wkvh + 64 * 128, wkvl + 64 * 128, 128, 128, (128/32)*(128/32), 1 };
    js.j[9] = { W_O,   woh,             wol,             512, 512, (512/32)*(512/32), 1 };
    int total = 0;
    for (int i = 0; i < 10; i++) total += js.j[i].nb;
    prep<<<total, 256>>>(js);

#define GEMMB(Ah, Al, Bh, Bl, Cm, Mv, Nv, Kv, Ldc) \
    hgemm_bs<<<dim3((Nv) / 64, (Mv) / 128), 256, GB_SMEM>>>(Ah, Al, Bh, Bl, Cm, Mv, Nv, Kv, Ldc)

    // fused x projections: [cq | ckv | krope | vres]
    GEMMB(xh, xl, wxh, wxl, xo, NTOK, 960, 512, 960);

    // fused latent RMS norms (+ split)
    rms2<<<NTOK, 384>>>(xo, q_ln, kv_ln, cqh, cql, ckvh, ckvl);

    // fused up-projections
    GEMMB(cqh,  cql,  wqh,  wql,  qo, NTOK, 512, 256, 512);
    GEMMB(ckvh, ckvl, wkvh, wkvl, ko, NTOK, 192, 128, 192);

    // rope + head-RMS + split (Q pre-scaled) + V transpose, one launch
    assemble_vt<<<NTOK + BATCH * NKVH * (TSEQ / 64), 256>>>(qhw, khw);

    // causal flash attention + v_res (2 CTAs/SM for softmax/mma overlap)
    flash<<<dim3(TSEQ / 128, BATCH * NHEADS), 256, FL_SMEM>>>(xo);

    // output projection
    GEMMB(ath, atl, woh, wol, out, NTOK, 512, 512, 512);
}